// round 10
// baseline (speedup 1.0000x reference)
#include <cuda_runtime.h>
#include <cuda_bf16.h>
#include <cstdint>

// ---------------------------------------------------------------------------
// Problem constants
// ---------------------------------------------------------------------------
constexpr int Bb = 2, Tt = 256, Mm = 80, Dd = 512;
constexpr int NT = Bb * Tt * Mm;   // 40960 tokens
constexpr int G3 = 3 * Dd;         // 1536
constexpr int NSEQ_T = Bb * Mm;    // 160
constexpr int NSEQ_F = Bb * Tt;    // 512

constexpr int TGROUPS = 8;
constexpr int TSQ = NSEQ_T / TGROUPS;  // 20
constexpr int TCOLB = 16;
constexpr int PBLK = 96;               // persistent scan grid size

// ---------------------------------------------------------------------------
// Static device scratch
// ---------------------------------------------------------------------------
__device__ float g_gi_t[(size_t)NT * G3];
__device__ float g_gi_f[(size_t)NT * G3];
__device__ float g_gi_b[(size_t)NT * G3];
__device__ float g_gi_s[(size_t)NT * G3];
__device__ float g_h0[NSEQ_F * Dd];
__device__ float g_h1[NSEQ_F * Dd];
__device__ float g_h2[NSEQ_F * Dd];
__device__ float g_h3[NSEQ_F * Dd];
__device__ float g_gh[2 * (size_t)NSEQ_F * G3];   // per-step gh (2 dirs / 2 K-halves)
__device__ unsigned g_tbar[TGROUPS];
__device__ unsigned g_fbar;
__device__ unsigned g_sbar;

// bf16 split buffers
__device__ __nv_bfloat16 g_ahi[(size_t)NT * G3];   // xcat / x_time split
__device__ __nv_bfloat16 g_alo[(size_t)NT * G3];
__device__ __nv_bfloat16 g_bhi[(size_t)NT * Dd];   // (xt+x_freq) split, xs split
__device__ __nv_bfloat16 g_blo[(size_t)NT * Dd];
// bf16 hidden-state ping-pong: [dir(2)*pp(2)][NSEQ_F*Dd]
__device__ __nv_bfloat16 g_hbhi[4 * NSEQ_F * Dd];
__device__ __nv_bfloat16 g_hblo[4 * NSEQ_F * Dd];
// weights: 9 slots of 1536*512
constexpr size_t WSLOT = 786432;
__device__ __nv_bfloat16 g_whi[9 * WSLOT];
__device__ __nv_bfloat16 g_wlo[9 * WSLOT];

// ---------------------------------------------------------------------------
// PTX helpers (portable: cp.async / ldmatrix / mma.sync)
// ---------------------------------------------------------------------------
__device__ __forceinline__ uint32_t smem_to_u32(const void* p) {
    uint32_t a;
    asm("{ .reg .u64 t; cvta.to.shared.u64 t, %1; cvt.u32.u64 %0, t; }"
        : "=r"(a) : "l"(p));
    return a;
}
#define CP_ASYNC16(dst, src) \
    asm volatile("cp.async.cg.shared.global [%0], [%1], 16;" \
        :: "r"((uint32_t)(dst)), "l"(src) : "memory")
#define CP_COMMIT() asm volatile("cp.async.commit_group;" ::: "memory")
#define CP_WAIT(n)  asm volatile("cp.async.wait_group %0;" :: "n"(n) : "memory")

__device__ __forceinline__ void ldsm4(uint32_t* r, uint32_t addr) {
    asm volatile("ldmatrix.sync.aligned.m8n8.x4.shared.b16 {%0,%1,%2,%3}, [%4];"
        : "=r"(r[0]), "=r"(r[1]), "=r"(r[2]), "=r"(r[3]) : "r"(addr));
}
__device__ __forceinline__ void mma16816(float* c, const uint32_t* a, const uint32_t* b) {
    asm volatile(
        "mma.sync.aligned.m16n8k16.row.col.f32.bf16.bf16.f32 "
        "{%0,%1,%2,%3}, {%4,%5,%6,%7}, {%8,%9}, {%0,%1,%2,%3};"
        : "+f"(c[0]), "+f"(c[1]), "+f"(c[2]), "+f"(c[3])
        : "r"(a[0]), "r"(a[1]), "r"(a[2]), "r"(a[3]), "r"(b[0]), "r"(b[1]));
}
__device__ __forceinline__ unsigned ld_cg_u32(const unsigned* p) {
    unsigned v;
    asm volatile("ld.global.cg.u32 %0, [%1];" : "=r"(v) : "l"(p));
    return v;
}

// ---------------------------------------------------------------------------
// fp32 -> (hi,lo) bf16 split (optionally X+Y first)
// ---------------------------------------------------------------------------
__global__ void split_bf16_kernel(
    const float* __restrict__ X, const float* __restrict__ Y,
    __nv_bfloat16* __restrict__ hi, __nv_bfloat16* __restrict__ lo, int n4)
{
    int i = blockIdx.x * blockDim.x + threadIdx.x;
    if (i >= n4) return;
    float4 v = reinterpret_cast<const float4*>(X)[i];
    if (Y) {
        float4 y = reinterpret_cast<const float4*>(Y)[i];
        v.x += y.x; v.y += y.y; v.z += y.z; v.w += y.w;
    }
    __nv_bfloat16 h0 = __float2bfloat16_rn(v.x);
    __nv_bfloat16 h1 = __float2bfloat16_rn(v.y);
    __nv_bfloat16 h2 = __float2bfloat16_rn(v.z);
    __nv_bfloat16 h3 = __float2bfloat16_rn(v.w);
    __nv_bfloat16 l0 = __float2bfloat16_rn(v.x - __bfloat162float(h0));
    __nv_bfloat16 l1 = __float2bfloat16_rn(v.y - __bfloat162float(h1));
    __nv_bfloat16 l2 = __float2bfloat16_rn(v.z - __bfloat162float(h2));
    __nv_bfloat16 l3 = __float2bfloat16_rn(v.w - __bfloat162float(h3));
    reinterpret_cast<__nv_bfloat162*>(hi)[2*i]   = __nv_bfloat162(h0, h1);
    reinterpret_cast<__nv_bfloat162*>(hi)[2*i+1] = __nv_bfloat162(h2, h3);
    reinterpret_cast<__nv_bfloat162*>(lo)[2*i]   = __nv_bfloat162(l0, l1);
    reinterpret_cast<__nv_bfloat162*>(lo)[2*i+1] = __nv_bfloat162(l2, l3);
}

// ---------------------------------------------------------------------------
// mma.sync 128x128 tile core (3-product bf16 split), BK=32, 3-stage cp.async.
// ---------------------------------------------------------------------------
constexpr int GSTRIDE = 40;
constexpr int TILE_B  = 128 * GSTRIDE * 2;     // 10240 B
constexpr int STAGE_B = 4 * TILE_B;            // 40960 B
constexpr int NSTAGE  = 3;
constexpr int GEMM_SMEM = NSTAGE * STAGE_B;    // 122880 B

__device__ __forceinline__ void gemm128_core(
    const __nv_bfloat16* __restrict__ Ahi, const __nv_bfloat16* __restrict__ Alo,
    const __nv_bfloat16* __restrict__ Bhi, const __nv_bfloat16* __restrict__ Blo,
    int ld, int K, char* smem, float acc[2][8][4])
{
    const uint32_t sb = smem_to_u32(smem);
    const int tid  = threadIdx.x;
    const int lane = tid & 31;
    const int wid  = tid >> 5;
    const int wm   = wid & 3;
    const int wn   = wid >> 2;

    const __nv_bfloat16* srcs[4] = {Ahi, Alo, Bhi, Blo};

    auto stage_load = [&](int c, int buf) {
        const int k0 = c * 32;
        const uint32_t base = sb + buf * STAGE_B;
#pragma unroll
        for (int t4 = 0; t4 < 4; t4++) {
#pragma unroll
            for (int i = 0; i < 2; i++) {
                int idx = tid + i * 256;
                int r = idx >> 2;
                int seg = idx & 3;
                uint32_t dst = base + t4 * TILE_B + r * (GSTRIDE * 2) + seg * 16;
                const void* gp = srcs[t4] + (size_t)r * ld + k0 + seg * 8;
                CP_ASYNC16(dst, gp);
            }
        }
        CP_COMMIT();
    };

#pragma unroll
    for (int mf = 0; mf < 2; mf++)
#pragma unroll
        for (int nf = 0; nf < 8; nf++)
#pragma unroll
            for (int q = 0; q < 4; q++) acc[mf][nf][q] = 0.f;

    const int NC = K / 32;
    stage_load(0, 0);
    stage_load(1, 1);

    const uint32_t a_off =
        ((wm * 32 + (lane & 15)) * GSTRIDE + ((lane >> 4) * 8)) * 2;
    const uint32_t b_row = wn * 64 + (lane & 7) + ((lane >> 4) & 1) * 8;
    const uint32_t b_off = (b_row * GSTRIDE + (((lane >> 3) & 1) * 8)) * 2;

    int nb = 2 % NSTAGE;
    for (int c = 0; c < NC; c++) {
        if (c + 2 < NC) {
            stage_load(c + 2, nb);
            nb = (nb + 1) % NSTAGE;
            CP_WAIT(2);
        } else if (c + 1 < NC) {
            CP_WAIT(1);
        } else {
            CP_WAIT(0);
        }
        __syncthreads();

        const uint32_t st = sb + (c % NSTAGE) * STAGE_B;

#pragma unroll
        for (int kk = 0; kk < 2; kk++) {
            const uint32_t kb = kk * 32;
            uint32_t ahi[2][4], alo[2][4];
#pragma unroll
            for (int mf = 0; mf < 2; mf++) {
                ldsm4(ahi[mf], st + 0 * TILE_B + a_off + mf * 16 * (GSTRIDE * 2) + kb);
                ldsm4(alo[mf], st + 1 * TILE_B + a_off + mf * 16 * (GSTRIDE * 2) + kb);
            }
            uint32_t bhi[8][2], blo[8][2];
#pragma unroll
            for (int p = 0; p < 4; p++) {
                uint32_t r4[4];
                ldsm4(r4, st + 2 * TILE_B + b_off + p * 16 * (GSTRIDE * 2) + kb);
                bhi[2*p][0] = r4[0]; bhi[2*p][1] = r4[1];
                bhi[2*p+1][0] = r4[2]; bhi[2*p+1][1] = r4[3];
                ldsm4(r4, st + 3 * TILE_B + b_off + p * 16 * (GSTRIDE * 2) + kb);
                blo[2*p][0] = r4[0]; blo[2*p][1] = r4[1];
                blo[2*p+1][0] = r4[2]; blo[2*p+1][1] = r4[3];
            }
#pragma unroll
            for (int mf = 0; mf < 2; mf++)
#pragma unroll
                for (int nf = 0; nf < 8; nf++) {
                    mma16816(acc[mf][nf], ahi[mf], bhi[nf]);
                    mma16816(acc[mf][nf], alo[mf], bhi[nf]);
                    mma16816(acc[mf][nf], ahi[mf], blo[nf]);
                }
        }
        __syncthreads();
    }
}

__device__ __forceinline__ void epi_store(
    float acc[2][8][4], float* __restrict__ C, const float* __restrict__ bias,
    const float* __restrict__ res, int row0, int col0, int N)
{
    const int lane = threadIdx.x & 31;
    const int wid  = threadIdx.x >> 5;
    const int wm   = wid & 3;
    const int wn   = wid >> 2;
#pragma unroll
    for (int mf = 0; mf < 2; mf++) {
        const int rA = row0 + wm * 32 + mf * 16 + (lane >> 2);
        const int rB = rA + 8;
#pragma unroll
        for (int nf = 0; nf < 8; nf++) {
            const int cc = col0 + wn * 64 + nf * 8 + (lane & 3) * 2;
            float b0 = bias ? bias[cc] : 0.f;
            float b1 = bias ? bias[cc + 1] : 0.f;
            float2 v0, v1;
            v0.x = acc[mf][nf][0] + b0;
            v0.y = acc[mf][nf][1] + b1;
            v1.x = acc[mf][nf][2] + b0;
            v1.y = acc[mf][nf][3] + b1;
            if (res) {
                float2 r0 = *reinterpret_cast<const float2*>(res + (size_t)rA * N + cc);
                float2 r1 = *reinterpret_cast<const float2*>(res + (size_t)rB * N + cc);
                v0.x += r0.x; v0.y += r0.y; v1.x += r1.x; v1.y += r1.y;
            }
            *reinterpret_cast<float2*>(C + (size_t)rA * N + cc) = v0;
            *reinterpret_cast<float2*>(C + (size_t)rB * N + cc) = v1;
        }
    }
}

// ---------------------------------------------------------------------------
// Standalone dual-arg GEMM
// ---------------------------------------------------------------------------
struct GArgs {
    const __nv_bfloat16 *Ahi, *Alo, *Bhi, *Blo;
    const float *bias, *res;
    float *C;
};

__global__ __launch_bounds__(256, 1) void gemm_bf3(GArgs g0, GArgs g1,
                                                    int K, int ld, int N)
{
    const GArgs g = blockIdx.z ? g1 : g0;
    extern __shared__ char smem[];
    const int row0 = blockIdx.y * 128;
    const int col0 = blockIdx.x * 128;
    float acc[2][8][4];
    gemm128_core(g.Ahi + (size_t)row0 * ld, g.Alo + (size_t)row0 * ld,
                 g.Bhi + (size_t)col0 * ld, g.Blo + (size_t)col0 * ld,
                 ld, K, smem, acc);
    epi_store(acc, g.C, g.bias, g.res, row0, col0, N);
}

// ---------------------------------------------------------------------------
// Phase-4 fused GEMM: xt -> dout, split(xt + x_freq) -> shi/slo
// ---------------------------------------------------------------------------
__global__ __launch_bounds__(256, 1) void gemm_p4(
    const __nv_bfloat16* __restrict__ Ahi, const __nv_bfloat16* __restrict__ Alo,
    const __nv_bfloat16* __restrict__ Bhi, const __nv_bfloat16* __restrict__ Blo,
    const float* __restrict__ bias, const float* __restrict__ xtime,
    const float* __restrict__ xfreq, float* __restrict__ C,
    __nv_bfloat16* __restrict__ shi, __nv_bfloat16* __restrict__ slo)
{
    extern __shared__ char smem[];
    const int row0 = blockIdx.y * 128;
    const int col0 = blockIdx.x * 128;
    float acc[2][8][4];
    gemm128_core(Ahi + (size_t)row0 * G3, Alo + (size_t)row0 * G3,
                 Bhi + (size_t)col0 * G3, Blo + (size_t)col0 * G3,
                 G3, G3, smem, acc);

    const int lane = threadIdx.x & 31;
    const int wid  = threadIdx.x >> 5;
    const int wm   = wid & 3;
    const int wn   = wid >> 2;
#pragma unroll
    for (int mf = 0; mf < 2; mf++) {
        const int rA = row0 + wm * 32 + mf * 16 + (lane >> 2);
#pragma unroll
        for (int half = 0; half < 2; half++) {
            const int r = rA + half * 8;
#pragma unroll
            for (int nf = 0; nf < 8; nf++) {
                const int cc = col0 + wn * 64 + nf * 8 + (lane & 3) * 2;
                const size_t o = (size_t)r * Dd + cc;
                float2 v;
                v.x = acc[mf][nf][half * 2 + 0] + bias[cc];
                v.y = acc[mf][nf][half * 2 + 1] + bias[cc + 1];
                float2 rt = *reinterpret_cast<const float2*>(xtime + o);
                v.x += rt.x; v.y += rt.y;
                *reinterpret_cast<float2*>(C + o) = v;
                float2 rf = *reinterpret_cast<const float2*>(xfreq + o);
                float t0 = v.x + rf.x;
                float t1 = v.y + rf.y;
                __nv_bfloat16 h0 = __float2bfloat16_rn(t0);
                __nv_bfloat16 h1 = __float2bfloat16_rn(t1);
                *reinterpret_cast<__nv_bfloat162*>(shi + o) = __nv_bfloat162(h0, h1);
                *reinterpret_cast<__nv_bfloat162*>(slo + o) = __nv_bfloat162(
                    __float2bfloat16_rn(t0 - __bfloat162float(h0)),
                    __float2bfloat16_rn(t1 - __bfloat162float(h1)));
            }
        }
    }
}

// ---------------------------------------------------------------------------
// Activation helpers
// ---------------------------------------------------------------------------
__device__ __forceinline__ float sigf(float x) {
    return 1.f / (1.f + __expf(-x));
}
__device__ __forceinline__ float tanhfast(float x) {
    float e2x = __expf(2.f * x);
    return 1.f - 2.f / (e2x + 1.f);
}

// ---------------------------------------------------------------------------
// Grid barrier: one atomic arrival per block, LOAD-based polling (no RMW spin)
// ---------------------------------------------------------------------------
__device__ __forceinline__ void grid_bar(unsigned* ctr, unsigned target)
{
    __threadfence();
    __syncthreads();
    if (threadIdx.x == 0) {
        atomicAdd(ctr, 1u);
        while (ld_cg_u32(ctr) < target) __nanosleep(64);
    }
    __syncthreads();
}

// ---------------------------------------------------------------------------
// Persistent bidirectional freq GRU scan. Grid (12, 4, 2=dir), 256 thr.
// ---------------------------------------------------------------------------
__global__ __launch_bounds__(256, 1) void scan_freq_persist(
    const __nv_bfloat16* __restrict__ wfhH, const __nv_bfloat16* __restrict__ wfhL,
    const __nv_bfloat16* __restrict__ wbhH, const __nv_bfloat16* __restrict__ wbhL,
    const float* __restrict__ bfhh, const float* __restrict__ bbhh,
    const float* __restrict__ gi_f, const float* __restrict__ gi_b,
    float* __restrict__ h0, float* __restrict__ h1,
    float* __restrict__ h2, float* __restrict__ h3,
    float* __restrict__ gh,
    __nv_bfloat16* __restrict__ hbhi, __nv_bfloat16* __restrict__ hblo,
    __nv_bfloat16* __restrict__ ahi, __nv_bfloat16* __restrict__ alo)
{
    extern __shared__ char smem[];
    const int cx  = blockIdx.x;
    const int ry  = blockIdx.y;
    const int dir = blockIdx.z;
    const int tid = threadIdx.x;
    const int bid = cx + 12 * (ry + 4 * dir);
    const size_t HB = (size_t)NSEQ_F * Dd;

    const __nv_bfloat16* WH = dir ? wbhH : wfhH;
    const __nv_bfloat16* WL = dir ? wbhL : wfhL;
    const float* bias = dir ? bbhh : bfhh;
    float* ghd = gh + (size_t)dir * NSEQ_F * G3;

    for (int s = 0; s < Mm; s++) {
        const int pp = s & 1;
        {
            const __nv_bfloat16* Ah = hbhi + (dir*2 + pp) * HB + (size_t)ry * 128 * Dd;
            const __nv_bfloat16* Al = hblo + (dir*2 + pp) * HB + (size_t)ry * 128 * Dd;
            const __nv_bfloat16* Bh = WH + (size_t)cx * 128 * Dd;
            const __nv_bfloat16* Bl = WL + (size_t)cx * 128 * Dd;
            float acc[2][8][4];
            gemm128_core(Ah, Al, Bh, Bl, Dd, Dd, smem, acc);
            epi_store(acc, ghd, bias, nullptr, ry * 128, cx * 128, G3);
        }
        grid_bar(&g_fbar, (unsigned)(2*s + 1) * PBLK);

        for (int e = bid * 256 + tid; e < 2 * NSEQ_F * Dd; e += PBLK * 256) {
            const int d2 = e >> 18;
            const int idx = e & (NSEQ_F * Dd - 1);
            const int sq = idx >> 9, j = idx & 511;
            const float* ghr = gh + (size_t)d2 * NSEQ_F * G3 + (size_t)sq * G3;
            const int mtok = d2 ? (Mm - 1 - s) : s;
            const int token = sq * Mm + mtok;
            const float* gir = (d2 ? gi_b : gi_f) + (size_t)token * G3;
            float r = sigf(gir[j]        + ghr[j]);
            float z = sigf(gir[Dd + j]   + ghr[Dd + j]);
            float n = tanhfast(gir[2*Dd + j] + r * ghr[2*Dd + j]);
            float* hPrev = d2 ? (pp ? h3 : h2) : (pp ? h1 : h0);
            float* hNext = d2 ? (pp ? h2 : h3) : (pp ? h0 : h1);
            float hp = hPrev[idx];
            float hv = (1.f - z) * n + z * hp;
            hNext[idx] = hv;
            __nv_bfloat16 hib = __float2bfloat16_rn(hv);
            __nv_bfloat16 lob = __float2bfloat16_rn(hv - __bfloat162float(hib));
            hbhi[(d2*2 + (pp ^ 1)) * HB + idx] = hib;
            hblo[(d2*2 + (pp ^ 1)) * HB + idx] = lob;
            size_t o = (size_t)token * G3 + Dd + (size_t)d2 * Dd + j;
            ahi[o] = hib;
            alo[o] = lob;
        }
        grid_bar(&g_fbar, (unsigned)(2*s + 2) * PBLK);
    }
}

// ---------------------------------------------------------------------------
// Persistent stack GRU scan. Grid (12, 4, 2=K-half split-K), 256 thr.
// ---------------------------------------------------------------------------
__global__ __launch_bounds__(256, 1) void scan_stack_persist(
    const __nv_bfloat16* __restrict__ wshH, const __nv_bfloat16* __restrict__ wshL,
    const float* __restrict__ bshh, const float* __restrict__ gi_s,
    float* __restrict__ h0, float* __restrict__ h1,
    float* __restrict__ gh,
    __nv_bfloat16* __restrict__ hbhi, __nv_bfloat16* __restrict__ hblo,
    __nv_bfloat16* __restrict__ ohi, __nv_bfloat16* __restrict__ olo)
{
    extern __shared__ char smem[];
    const int cx = blockIdx.x;
    const int ry = blockIdx.y;
    const int kb = blockIdx.z;
    const int tid = threadIdx.x;
    const int bid = cx + 12 * (ry + 4 * kb);
    const size_t HB = (size_t)NSEQ_F * Dd;

    for (int s = 0; s < Mm; s++) {
        const int pp = s & 1;
        {
            const __nv_bfloat16* Ah = hbhi + pp * HB + (size_t)ry * 128 * Dd + kb * 256;
            const __nv_bfloat16* Al = hblo + pp * HB + (size_t)ry * 128 * Dd + kb * 256;
            const __nv_bfloat16* Bh = wshH + (size_t)cx * 128 * Dd + kb * 256;
            const __nv_bfloat16* Bl = wshL + (size_t)cx * 128 * Dd + kb * 256;
            float acc[2][8][4];
            gemm128_core(Ah, Al, Bh, Bl, Dd, 256, smem, acc);
            epi_store(acc, gh + (size_t)kb * NSEQ_F * G3,
                      kb == 0 ? bshh : nullptr, nullptr, ry * 128, cx * 128, G3);
        }
        grid_bar(&g_sbar, (unsigned)(2*s + 1) * PBLK);

        for (int e = bid * 256 + tid; e < NSEQ_F * Dd; e += PBLK * 256) {
            const int sq = e >> 9, j = e & 511;
            const float* g0 = gh + (size_t)sq * G3;
            const float* g1 = gh + (size_t)NSEQ_F * G3 + (size_t)sq * G3;
            const int token = sq * Mm + s;
            const float* gir = gi_s + (size_t)token * G3;
            float ghr = g0[j]        + g1[j];
            float ghz = g0[Dd + j]   + g1[Dd + j];
            float ghn = g0[2*Dd + j] + g1[2*Dd + j];
            float r = sigf(gir[j]        + ghr);
            float z = sigf(gir[Dd + j]   + ghz);
            float n = tanhfast(gir[2*Dd + j] + r * ghn);
            float* hPrev = pp ? h1 : h0;
            float* hNext = pp ? h0 : h1;
            float hp = hPrev[e];
            float hv = (1.f - z) * n + z * hp;
            hNext[e] = hv;
            __nv_bfloat16 hib = __float2bfloat16_rn(hv);
            __nv_bfloat16 lob = __float2bfloat16_rn(hv - __bfloat162float(hib));
            hbhi[(pp ^ 1) * HB + e] = hib;
            hblo[(pp ^ 1) * HB + e] = lob;
            size_t o = (size_t)token * Dd + j;
            ohi[o] = hib;
            olo[o] = lob;
        }
        grid_bar(&g_sbar, (unsigned)(2*s + 2) * PBLK);
    }
}

// ---------------------------------------------------------------------------
// Persistent time-GRU scan (fp32 SIMT), 512 threads, 16 warps x 32-k slices.
// Grid (TGROUPS=8, TCOLB=16).
// ---------------------------------------------------------------------------
constexpr int TPART = 17;   // padded partial stride (bank-conflict-free)
constexpr int TIME_SMEM = (TSQ * 512 + TSQ * 3 * 32 * TPART) * 4; // 171520 B

__global__ __launch_bounds__(512, 1) void gru_time_persist(
    const float* __restrict__ gi, const float* __restrict__ Whh,
    const float* __restrict__ bhh,
    __nv_bfloat16* __restrict__ ohi, __nv_bfloat16* __restrict__ olo,
    float* __restrict__ hb0, float* __restrict__ hb1)
{
    const int grp  = blockIdx.x;
    const int cb   = blockIdx.y;
    const int j0   = cb * 32;
    const int tid  = threadIdx.x;
    const int lane = tid & 31;
    const int w    = tid >> 5;     // 0..15
    const int k0   = w * 32;

    extern __shared__ float sm[];
    float* hs   = sm;                       // [TSQ][512]
    float* part = sm + TSQ * 512;           // [TSQ*3*32][TPART]

    float wr[32], wz[32], wn[32];
    {
        const float* Wr = Whh + (size_t)(0 * Dd + j0 + lane) * Dd + k0;
        const float* Wz = Whh + (size_t)(1 * Dd + j0 + lane) * Dd + k0;
        const float* Wn = Whh + (size_t)(2 * Dd + j0 + lane) * Dd + k0;
#pragma unroll
        for (int i = 0; i < 32; i += 4) {
            float4 a = *reinterpret_cast<const float4*>(Wr + i);
            float4 b = *reinterpret_cast<const float4*>(Wz + i);
            float4 c = *reinterpret_cast<const float4*>(Wn + i);
            wr[i] = a.x; wr[i+1] = a.y; wr[i+2] = a.z; wr[i+3] = a.w;
            wz[i] = b.x; wz[i+1] = b.y; wz[i+2] = b.z; wz[i+3] = b.w;
            wn[i] = c.x; wn[i+1] = c.y; wn[i+2] = c.z; wn[i+3] = c.w;
        }
    }

    for (int t = 0; t < Tt; t++) {
        const float* hc = (t & 1) ? hb1 : hb0;
        float*       hn = (t & 1) ? hb0 : hb1;

        for (int i = tid; i < TSQ * 128; i += 512) {
            int s  = i >> 7;
            int k4 = i & 127;
            float4 v = __ldcg(reinterpret_cast<const float4*>(
                hc + (size_t)(grp * TSQ + s) * Dd) + k4);
            *reinterpret_cast<float4*>(hs + s * Dd + k4 * 4) = v;
        }
        __syncthreads();

        // two sequences per iteration for ILP
        for (int s = 0; s < TSQ; s += 2) {
            float ar0 = 0.f, az0 = 0.f, an0 = 0.f;
            float ar1 = 0.f, az1 = 0.f, an1 = 0.f;
            const float* h0r = hs + s * Dd + k0;
            const float* h1r = hs + (s + 1) * Dd + k0;
#pragma unroll
            for (int i = 0; i < 32; i += 4) {
                float4 a4 = *reinterpret_cast<const float4*>(h0r + i);
                float4 b4 = *reinterpret_cast<const float4*>(h1r + i);
                ar0 = fmaf(a4.x, wr[i],   ar0); az0 = fmaf(a4.x, wz[i],   az0); an0 = fmaf(a4.x, wn[i],   an0);
                ar1 = fmaf(b4.x, wr[i],   ar1); az1 = fmaf(b4.x, wz[i],   az1); an1 = fmaf(b4.x, wn[i],   an1);
                ar0 = fmaf(a4.y, wr[i+1], ar0); az0 = fmaf(a4.y, wz[i+1], az0); an0 = fmaf(a4.y, wn[i+1], an0);
                ar1 = fmaf(b4.y, wr[i+1], ar1); az1 = fmaf(b4.y, wz[i+1], az1); an1 = fmaf(b4.y, wn[i+1], an1);
                ar0 = fmaf(a4.z, wr[i+2], ar0); az0 = fmaf(a4.z, wz[i+2], az0); an0 = fmaf(a4.z, wn[i+2], an0);
                ar1 = fmaf(b4.z, wr[i+2], ar1); az1 = fmaf(b4.z, wz[i+2], az1); an1 = fmaf(b4.z, wn[i+2], an1);
                ar0 = fmaf(a4.w, wr[i+3], ar0); az0 = fmaf(a4.w, wz[i+3], az0); an0 = fmaf(a4.w, wn[i+3], an0);
                ar1 = fmaf(b4.w, wr[i+3], ar1); az1 = fmaf(b4.w, wz[i+3], az1); an1 = fmaf(b4.w, wn[i+3], an1);
            }
            part[((s * 3 + 0) * 32 + lane) * TPART + w] = ar0;
            part[((s * 3 + 1) * 32 + lane) * TPART + w] = az0;
            part[((s * 3 + 2) * 32 + lane) * TPART + w] = an0;
            part[(((s+1) * 3 + 0) * 32 + lane) * TPART + w] = ar1;
            part[(((s+1) * 3 + 1) * 32 + lane) * TPART + w] = az1;
            part[(((s+1) * 3 + 2) * 32 + lane) * TPART + w] = an1;
        }
        __syncthreads();

        for (int idx = tid; idx < TSQ * 32; idx += 512) {
            int s = idx >> 5, j = idx & 31;
            float r = 0.f, z = 0.f, n = 0.f;
            const float* pr = part + ((s * 3 + 0) * 32 + j) * TPART;
            const float* pz = part + ((s * 3 + 1) * 32 + j) * TPART;
            const float* pn = part + ((s * 3 + 2) * 32 + j) * TPART;
#pragma unroll
            for (int ww = 0; ww < 16; ww++) { r += pr[ww]; z += pz[ww]; n += pn[ww]; }

            int sg = grp * TSQ + s;
            int b  = sg / Mm;
            int m  = sg - b * Mm;
            size_t token = ((size_t)(b * Tt + t)) * Mm + m;
            const float* gir = gi + token * G3;
            int jc = j0 + j;
            float rr = sigf(gir[jc]        + r + bhh[jc]);
            float zz = sigf(gir[Dd + jc]   + z + bhh[Dd + jc]);
            float nn = tanhfast(gir[2*Dd + jc] + rr * (n + bhh[2*Dd + jc]));
            float hp = hs[s * Dd + jc];
            float hv = (1.f - zz) * nn + zz * hp;
            __stcg(hn + (size_t)sg * Dd + jc, hv);
            __nv_bfloat16 hib = __float2bfloat16_rn(hv);
            ohi[token * G3 + jc] = hib;
            olo[token * G3 + jc] = __float2bfloat16_rn(hv - __bfloat162float(hib));
        }

        __threadfence();
        __syncthreads();
        if (tid == 0) {
            atomicAdd(&g_tbar[grp], 1u);
            unsigned target = (unsigned)(t + 1) * TCOLB;
            while (ld_cg_u32(&g_tbar[grp]) < target) __nanosleep(64);
        }
        __syncthreads();
    }
}

// ---------------------------------------------------------------------------
// Launch
// ---------------------------------------------------------------------------
static void split_launch(const float* X, const float* Y,
                         __nv_bfloat16* hi, __nv_bfloat16* lo, size_t n)
{
    int n4 = (int)(n / 4);
    split_bf16_kernel<<<(n4 + 255) / 256, 256>>>(X, Y, hi, lo, n4);
}

extern "C" void kernel_launch(void* const* d_in, const int* in_sizes, int n_in,
                              void* d_out_v, int out_size)
{
    const float* x_time = (const float*)d_in[0];
    const float* x_freq = (const float*)d_in[1];
    const float* wt_ih  = (const float*)d_in[2];
    const float* wt_hh  = (const float*)d_in[3];
    const float* bt_ih  = (const float*)d_in[4];
    const float* bt_hh  = (const float*)d_in[5];
    const float* wf_ih  = (const float*)d_in[6];
    const float* wf_hh  = (const float*)d_in[7];
    const float* bf_ih  = (const float*)d_in[8];
    const float* bf_hh  = (const float*)d_in[9];
    const float* wb_ih  = (const float*)d_in[10];
    const float* wb_hh  = (const float*)d_in[11];
    const float* bb_ih  = (const float*)d_in[12];
    const float* bb_hh  = (const float*)d_in[13];
    const float* ws_ih  = (const float*)d_in[14];
    const float* ws_hh  = (const float*)d_in[15];
    const float* bs_ih  = (const float*)d_in[16];
    const float* bs_hh  = (const float*)d_in[17];
    const float* W_time = (const float*)d_in[18];
    const float* b_time = (const float*)d_in[19];
    const float* W_freq = (const float*)d_in[20];
    const float* b_freq = (const float*)d_in[21];
    float* dout = (float*)d_out_v;

    float *gi_t, *gi_f, *gi_b, *gi_s, *h0, *h1, *h2, *h3, *gh;
    unsigned *tbar, *fbar, *sbar;
    __nv_bfloat16 *ahi, *alo, *bhi, *blo, *whi, *wlo, *hbhi, *hblo;
    cudaGetSymbolAddress((void**)&gi_t, g_gi_t);
    cudaGetSymbolAddress((void**)&gi_f, g_gi_f);
    cudaGetSymbolAddress((void**)&gi_b, g_gi_b);
    cudaGetSymbolAddress((void**)&gi_s, g_gi_s);
    cudaGetSymbolAddress((void**)&h0,   g_h0);
    cudaGetSymbolAddress((void**)&h1,   g_h1);
    cudaGetSymbolAddress((void**)&h2,   g_h2);
    cudaGetSymbolAddress((void**)&h3,   g_h3);
    cudaGetSymbolAddress((void**)&gh,   g_gh);
    cudaGetSymbolAddress((void**)&tbar, g_tbar);
    cudaGetSymbolAddress((void**)&fbar, g_fbar);
    cudaGetSymbolAddress((void**)&sbar, g_sbar);
    cudaGetSymbolAddress((void**)&ahi,  g_ahi);
    cudaGetSymbolAddress((void**)&alo,  g_alo);
    cudaGetSymbolAddress((void**)&bhi,  g_bhi);
    cudaGetSymbolAddress((void**)&blo,  g_blo);
    cudaGetSymbolAddress((void**)&whi,  g_whi);
    cudaGetSymbolAddress((void**)&wlo,  g_wlo);
    cudaGetSymbolAddress((void**)&hbhi, g_hbhi);
    cudaGetSymbolAddress((void**)&hblo, g_hblo);

    const dim3 blk(256);
    cudaFuncSetAttribute(gru_time_persist,
                         cudaFuncAttributeMaxDynamicSharedMemorySize, TIME_SMEM);
    cudaFuncSetAttribute(gemm_bf3,
                         cudaFuncAttributeMaxDynamicSharedMemorySize, GEMM_SMEM);
    cudaFuncSetAttribute(gemm_p4,
                         cudaFuncAttributeMaxDynamicSharedMemorySize, GEMM_SMEM);
    cudaFuncSetAttribute(scan_freq_persist,
                         cudaFuncAttributeMaxDynamicSharedMemorySize, GEMM_SMEM);
    cudaFuncSetAttribute(scan_stack_persist,
                         cudaFuncAttributeMaxDynamicSharedMemorySize, GEMM_SMEM);

    __nv_bfloat16 *wtH = whi + 0*WSLOT, *wtL = wlo + 0*WSLOT;   // wt_ih
    __nv_bfloat16 *wfH = whi + 1*WSLOT, *wfL = wlo + 1*WSLOT;   // wf_ih
    __nv_bfloat16 *wbH = whi + 2*WSLOT, *wbL = wlo + 2*WSLOT;   // wb_ih
    __nv_bfloat16 *wsH = whi + 3*WSLOT, *wsL = wlo + 3*WSLOT;   // ws_ih
    __nv_bfloat16 *wTH = whi + 4*WSLOT, *wTL = wlo + 4*WSLOT;   // W_time
    __nv_bfloat16 *wFH = whi + 5*WSLOT, *wFL = wlo + 5*WSLOT;   // W_freq
    __nv_bfloat16 *wfhH = whi + 6*WSLOT, *wfhL = wlo + 6*WSLOT; // wf_hh
    __nv_bfloat16 *wbhH = whi + 7*WSLOT, *wbhL = wlo + 7*WSLOT; // wb_hh
    __nv_bfloat16 *wshH = whi + 8*WSLOT, *wshL = wlo + 8*WSLOT; // ws_hh

    const size_t HB = (size_t)NSEQ_F * Dd;

    // ---- Phase 0: splits ----
    split_launch(wt_ih,  nullptr, wtH, wtL, (size_t)G3 * Dd);
    split_launch(wf_ih,  nullptr, wfH, wfL, (size_t)G3 * Dd);
    split_launch(wb_ih,  nullptr, wbH, wbL, (size_t)G3 * Dd);
    split_launch(ws_ih,  nullptr, wsH, wsL, (size_t)G3 * Dd);
    split_launch(W_time, nullptr, wTH, wTL, (size_t)Dd * G3);
    split_launch(W_freq, nullptr, wFH, wFL, (size_t)Dd * Dd);
    split_launch(wf_hh,  nullptr, wfhH, wfhL, (size_t)G3 * Dd);
    split_launch(wb_hh,  nullptr, wbhH, wbhL, (size_t)G3 * Dd);
    split_launch(ws_hh,  nullptr, wshH, wshL, (size_t)G3 * Dd);
    split_launch(x_time, nullptr, ahi, alo, (size_t)NT * Dd);

    // ---- Phase 1: input projections ----
    {
        dim3 grid(G3 / 128, NT / 128, 1);
        GArgs a{ahi, alo, wtH, wtL, bt_ih, nullptr, gi_t};
        gemm_bf3<<<grid, blk, GEMM_SMEM>>>(a, a, Dd, Dd, G3);
        GArgs b{ahi, alo, wfH, wfL, bf_ih, nullptr, gi_f};
        gemm_bf3<<<grid, blk, GEMM_SMEM>>>(b, b, Dd, Dd, G3);
        GArgs c{ahi, alo, wbH, wbL, bb_ih, nullptr, gi_b};
        gemm_bf3<<<grid, blk, GEMM_SMEM>>>(c, c, Dd, Dd, G3);
    }

    // ---- Phase 2: persistent time GRU scan (writes xcat cols [0,512) bf16) --
    cudaMemsetAsync(h0, 0, (size_t)NSEQ_T * Dd * sizeof(float));
    cudaMemsetAsync(h1, 0, (size_t)NSEQ_T * Dd * sizeof(float));
    cudaMemsetAsync(tbar, 0, TGROUPS * sizeof(unsigned));
    gru_time_persist<<<dim3(TGROUPS, TCOLB), dim3(512), TIME_SMEM>>>(
        gi_t, wt_hh, bt_hh, ahi, alo, h0, h1);

    // ---- Phase 3: persistent bidirectional freq GRU scan ----
    cudaMemsetAsync(h0, 0, HB * sizeof(float));
    cudaMemsetAsync(h2, 0, HB * sizeof(float));
    cudaMemsetAsync(hbhi + 0 * HB, 0, HB * sizeof(__nv_bfloat16));
    cudaMemsetAsync(hblo + 0 * HB, 0, HB * sizeof(__nv_bfloat16));
    cudaMemsetAsync(hbhi + 2 * HB, 0, HB * sizeof(__nv_bfloat16));
    cudaMemsetAsync(hblo + 2 * HB, 0, HB * sizeof(__nv_bfloat16));
    cudaMemsetAsync(fbar, 0, sizeof(unsigned));
    scan_freq_persist<<<dim3(12, 4, 2), blk, GEMM_SMEM>>>(
        wfhH, wfhL, wbhH, wbhL, bf_hh, bb_hh, gi_f, gi_b,
        h0, h1, h2, h3, gh, hbhi, hblo, ahi, alo);

    // ---- Phase 4: fused xt GEMM + split(xt + x_freq) -> bhi/blo ----
    gemm_p4<<<dim3(Dd / 128, NT / 128), blk, GEMM_SMEM>>>(
        ahi, alo, wTH, wTL, b_time, x_time, x_freq, dout, bhi, blo);

    // ---- Phase 5: gi_s = (xt + x_freq) @ ws_ih^T + bs_ih ----
    {
        GArgs a{bhi, blo, wsH, wsL, bs_ih, nullptr, gi_s};
        gemm_bf3<<<dim3(G3 / 128, NT / 128, 1), blk, GEMM_SMEM>>>(a, a, Dd, Dd, G3);
    }

    // ---- Phase 6: persistent stack GRU scan (split-K=2) ----
    cudaMemsetAsync(h0, 0, HB * sizeof(float));
    cudaMemsetAsync(hbhi + 0 * HB, 0, HB * sizeof(__nv_bfloat16));
    cudaMemsetAsync(hblo + 0 * HB, 0, HB * sizeof(__nv_bfloat16));
    cudaMemsetAsync(sbar, 0, sizeof(unsigned));
    scan_stack_persist<<<dim3(12, 4, 2), blk, GEMM_SMEM>>>(
        wshH, wshL, bs_hh, gi_s, h0, h1, gh, hbhi, hblo, bhi, blo);

    // ---- Phase 7: xf = xs @ W_freq^T + b_freq + x_freq ----
    {
        GArgs a{bhi, blo, wFH, wFL, b_freq, x_freq, dout + (size_t)NT * Dd};
        gemm_bf3<<<dim3(Dd / 128, NT / 128, 1), blk, GEMM_SMEM>>>(a, a, Dd, Dd, Dd);
    }
}

// round 11
// speedup vs baseline: 1.3432x; 1.3432x over previous
#include <cuda_runtime.h>
#include <cuda_bf16.h>
#include <cstdint>

// ---------------------------------------------------------------------------
// Problem constants
// ---------------------------------------------------------------------------
constexpr int Bb = 2, Tt = 256, Mm = 80, Dd = 512;
constexpr int NT = Bb * Tt * Mm;   // 40960 tokens
constexpr int G3 = 3 * Dd;         // 1536
constexpr int NSEQ_T = Bb * Mm;    // 160
constexpr int NSEQ_F = Bb * Tt;    // 512

constexpr int TGROUPS = 8;
constexpr int TSQ = NSEQ_T / TGROUPS;  // 20
constexpr int TCOLB = 16;

// ---------------------------------------------------------------------------
// Static device scratch
// ---------------------------------------------------------------------------
__device__ float g_gi_t[(size_t)NT * G3];
__device__ float g_gi_f[(size_t)NT * G3];
__device__ float g_gi_b[(size_t)NT * G3];
__device__ float g_gi_s[(size_t)NT * G3];
__device__ float g_h0[NSEQ_F * Dd];
__device__ float g_h1[NSEQ_F * Dd];
__device__ float g_h2[NSEQ_F * Dd];
__device__ float g_h3[NSEQ_F * Dd];
__device__ float g_gh[2 * (size_t)NSEQ_F * G3];   // per-step gh (2 dirs / 2 K-halves)
__device__ unsigned g_tbar[TGROUPS];

// bf16 split buffers
__device__ __nv_bfloat16 g_ahi[(size_t)NT * G3];   // xcat / x_time split
__device__ __nv_bfloat16 g_alo[(size_t)NT * G3];
__device__ __nv_bfloat16 g_bhi[(size_t)NT * Dd];   // (xt+x_freq) split, xs split
__device__ __nv_bfloat16 g_blo[(size_t)NT * Dd];
// bf16 hidden-state ping-pong: [dir(2)*pp(2)][NSEQ_F*Dd]
__device__ __nv_bfloat16 g_hbhi[4 * NSEQ_F * Dd];
__device__ __nv_bfloat16 g_hblo[4 * NSEQ_F * Dd];
// weights: 9 slots of 1536*512
constexpr size_t WSLOT = 786432;
__device__ __nv_bfloat16 g_whi[9 * WSLOT];
__device__ __nv_bfloat16 g_wlo[9 * WSLOT];

// ---------------------------------------------------------------------------
// PTX helpers (portable: cp.async / ldmatrix / mma.sync)
// ---------------------------------------------------------------------------
__device__ __forceinline__ uint32_t smem_to_u32(const void* p) {
    uint32_t a;
    asm("{ .reg .u64 t; cvta.to.shared.u64 t, %1; cvt.u32.u64 %0, t; }"
        : "=r"(a) : "l"(p));
    return a;
}
#define CP_ASYNC16(dst, src) \
    asm volatile("cp.async.cg.shared.global [%0], [%1], 16;" \
        :: "r"((uint32_t)(dst)), "l"(src) : "memory")
#define CP_COMMIT() asm volatile("cp.async.commit_group;" ::: "memory")
#define CP_WAIT(n)  asm volatile("cp.async.wait_group %0;" :: "n"(n) : "memory")

__device__ __forceinline__ void ldsm4(uint32_t* r, uint32_t addr) {
    asm volatile("ldmatrix.sync.aligned.m8n8.x4.shared.b16 {%0,%1,%2,%3}, [%4];"
        : "=r"(r[0]), "=r"(r[1]), "=r"(r[2]), "=r"(r[3]) : "r"(addr));
}
__device__ __forceinline__ void mma16816(float* c, const uint32_t* a, const uint32_t* b) {
    asm volatile(
        "mma.sync.aligned.m16n8k16.row.col.f32.bf16.bf16.f32 "
        "{%0,%1,%2,%3}, {%4,%5,%6,%7}, {%8,%9}, {%0,%1,%2,%3};"
        : "+f"(c[0]), "+f"(c[1]), "+f"(c[2]), "+f"(c[3])
        : "r"(a[0]), "r"(a[1]), "r"(a[2]), "r"(a[3]), "r"(b[0]), "r"(b[1]));
}
__device__ __forceinline__ unsigned ld_cg_u32(const unsigned* p) {
    unsigned v;
    asm volatile("ld.global.cg.u32 %0, [%1];" : "=r"(v) : "l"(p));
    return v;
}

// ---------------------------------------------------------------------------
// fp32 -> (hi,lo) bf16 split (optionally X+Y first)
// ---------------------------------------------------------------------------
__global__ void split_bf16_kernel(
    const float* __restrict__ X, const float* __restrict__ Y,
    __nv_bfloat16* __restrict__ hi, __nv_bfloat16* __restrict__ lo, int n4)
{
    int i = blockIdx.x * blockDim.x + threadIdx.x;
    if (i >= n4) return;
    float4 v = reinterpret_cast<const float4*>(X)[i];
    if (Y) {
        float4 y = reinterpret_cast<const float4*>(Y)[i];
        v.x += y.x; v.y += y.y; v.z += y.z; v.w += y.w;
    }
    __nv_bfloat16 h0 = __float2bfloat16_rn(v.x);
    __nv_bfloat16 h1 = __float2bfloat16_rn(v.y);
    __nv_bfloat16 h2 = __float2bfloat16_rn(v.z);
    __nv_bfloat16 h3 = __float2bfloat16_rn(v.w);
    __nv_bfloat16 l0 = __float2bfloat16_rn(v.x - __bfloat162float(h0));
    __nv_bfloat16 l1 = __float2bfloat16_rn(v.y - __bfloat162float(h1));
    __nv_bfloat16 l2 = __float2bfloat16_rn(v.z - __bfloat162float(h2));
    __nv_bfloat16 l3 = __float2bfloat16_rn(v.w - __bfloat162float(h3));
    reinterpret_cast<__nv_bfloat162*>(hi)[2*i]   = __nv_bfloat162(h0, h1);
    reinterpret_cast<__nv_bfloat162*>(hi)[2*i+1] = __nv_bfloat162(h2, h3);
    reinterpret_cast<__nv_bfloat162*>(lo)[2*i]   = __nv_bfloat162(l0, l1);
    reinterpret_cast<__nv_bfloat162*>(lo)[2*i+1] = __nv_bfloat162(l2, l3);
}

// ---------------------------------------------------------------------------
// mma.sync 128x128 tile core (3-product bf16 split), BK=32, 3-stage cp.async.
// ---------------------------------------------------------------------------
constexpr int GSTRIDE = 40;
constexpr int TILE_B  = 128 * GSTRIDE * 2;     // 10240 B
constexpr int STAGE_B = 4 * TILE_B;            // 40960 B
constexpr int NSTAGE  = 3;
constexpr int GEMM_SMEM = NSTAGE * STAGE_B;    // 122880 B

__device__ __forceinline__ void gemm128_core(
    const __nv_bfloat16* __restrict__ Ahi, const __nv_bfloat16* __restrict__ Alo,
    const __nv_bfloat16* __restrict__ Bhi, const __nv_bfloat16* __restrict__ Blo,
    int ld, int K, char* smem, float acc[2][8][4])
{
    const uint32_t sb = smem_to_u32(smem);
    const int tid  = threadIdx.x;
    const int lane = tid & 31;
    const int wid  = tid >> 5;
    const int wm   = wid & 3;
    const int wn   = wid >> 2;

    const __nv_bfloat16* srcs[4] = {Ahi, Alo, Bhi, Blo};

    auto stage_load = [&](int c, int buf) {
        const int k0 = c * 32;
        const uint32_t base = sb + buf * STAGE_B;
#pragma unroll
        for (int t4 = 0; t4 < 4; t4++) {
#pragma unroll
            for (int i = 0; i < 2; i++) {
                int idx = tid + i * 256;
                int r = idx >> 2;
                int seg = idx & 3;
                uint32_t dst = base + t4 * TILE_B + r * (GSTRIDE * 2) + seg * 16;
                const void* gp = srcs[t4] + (size_t)r * ld + k0 + seg * 8;
                CP_ASYNC16(dst, gp);
            }
        }
        CP_COMMIT();
    };

#pragma unroll
    for (int mf = 0; mf < 2; mf++)
#pragma unroll
        for (int nf = 0; nf < 8; nf++)
#pragma unroll
            for (int q = 0; q < 4; q++) acc[mf][nf][q] = 0.f;

    const int NC = K / 32;
    stage_load(0, 0);
    stage_load(1, 1);

    const uint32_t a_off =
        ((wm * 32 + (lane & 15)) * GSTRIDE + ((lane >> 4) * 8)) * 2;
    const uint32_t b_row = wn * 64 + (lane & 7) + ((lane >> 4) & 1) * 8;
    const uint32_t b_off = (b_row * GSTRIDE + (((lane >> 3) & 1) * 8)) * 2;

    int nb = 2 % NSTAGE;
    for (int c = 0; c < NC; c++) {
        if (c + 2 < NC) {
            stage_load(c + 2, nb);
            nb = (nb + 1) % NSTAGE;
            CP_WAIT(2);
        } else if (c + 1 < NC) {
            CP_WAIT(1);
        } else {
            CP_WAIT(0);
        }
        __syncthreads();

        const uint32_t st = sb + (c % NSTAGE) * STAGE_B;

#pragma unroll
        for (int kk = 0; kk < 2; kk++) {
            const uint32_t kb = kk * 32;
            uint32_t ahi[2][4], alo[2][4];
#pragma unroll
            for (int mf = 0; mf < 2; mf++) {
                ldsm4(ahi[mf], st + 0 * TILE_B + a_off + mf * 16 * (GSTRIDE * 2) + kb);
                ldsm4(alo[mf], st + 1 * TILE_B + a_off + mf * 16 * (GSTRIDE * 2) + kb);
            }
            uint32_t bhi[8][2], blo[8][2];
#pragma unroll
            for (int p = 0; p < 4; p++) {
                uint32_t r4[4];
                ldsm4(r4, st + 2 * TILE_B + b_off + p * 16 * (GSTRIDE * 2) + kb);
                bhi[2*p][0] = r4[0]; bhi[2*p][1] = r4[1];
                bhi[2*p+1][0] = r4[2]; bhi[2*p+1][1] = r4[3];
                ldsm4(r4, st + 3 * TILE_B + b_off + p * 16 * (GSTRIDE * 2) + kb);
                blo[2*p][0] = r4[0]; blo[2*p][1] = r4[1];
                blo[2*p+1][0] = r4[2]; blo[2*p+1][1] = r4[3];
            }
#pragma unroll
            for (int mf = 0; mf < 2; mf++)
#pragma unroll
                for (int nf = 0; nf < 8; nf++) {
                    mma16816(acc[mf][nf], ahi[mf], bhi[nf]);
                    mma16816(acc[mf][nf], alo[mf], bhi[nf]);
                    mma16816(acc[mf][nf], ahi[mf], blo[nf]);
                }
        }
        __syncthreads();
    }
}

__device__ __forceinline__ void epi_store(
    float acc[2][8][4], float* __restrict__ C, const float* __restrict__ bias,
    const float* __restrict__ res, int row0, int col0, int N)
{
    const int lane = threadIdx.x & 31;
    const int wid  = threadIdx.x >> 5;
    const int wm   = wid & 3;
    const int wn   = wid >> 2;
#pragma unroll
    for (int mf = 0; mf < 2; mf++) {
        const int rA = row0 + wm * 32 + mf * 16 + (lane >> 2);
        const int rB = rA + 8;
#pragma unroll
        for (int nf = 0; nf < 8; nf++) {
            const int cc = col0 + wn * 64 + nf * 8 + (lane & 3) * 2;
            float b0 = bias ? bias[cc] : 0.f;
            float b1 = bias ? bias[cc + 1] : 0.f;
            float2 v0, v1;
            v0.x = acc[mf][nf][0] + b0;
            v0.y = acc[mf][nf][1] + b1;
            v1.x = acc[mf][nf][2] + b0;
            v1.y = acc[mf][nf][3] + b1;
            if (res) {
                float2 r0 = *reinterpret_cast<const float2*>(res + (size_t)rA * N + cc);
                float2 r1 = *reinterpret_cast<const float2*>(res + (size_t)rB * N + cc);
                v0.x += r0.x; v0.y += r0.y; v1.x += r1.x; v1.y += r1.y;
            }
            *reinterpret_cast<float2*>(C + (size_t)rA * N + cc) = v0;
            *reinterpret_cast<float2*>(C + (size_t)rB * N + cc) = v1;
        }
    }
}

// ---------------------------------------------------------------------------
// Standalone dual-arg GEMM
// ---------------------------------------------------------------------------
struct GArgs {
    const __nv_bfloat16 *Ahi, *Alo, *Bhi, *Blo;
    const float *bias, *res;
    float *C;
};

__global__ __launch_bounds__(256, 1) void gemm_bf3(GArgs g0, GArgs g1,
                                                    int K, int ld, int N)
{
    const GArgs g = blockIdx.z ? g1 : g0;
    extern __shared__ char smem[];
    const int row0 = blockIdx.y * 128;
    const int col0 = blockIdx.x * 128;
    float acc[2][8][4];
    gemm128_core(g.Ahi + (size_t)row0 * ld, g.Alo + (size_t)row0 * ld,
                 g.Bhi + (size_t)col0 * ld, g.Blo + (size_t)col0 * ld,
                 ld, K, smem, acc);
    epi_store(acc, g.C, g.bias, g.res, row0, col0, N);
}

// ---------------------------------------------------------------------------
// Phase-4 fused GEMM: xt -> dout, split(xt + x_freq) -> shi/slo
// ---------------------------------------------------------------------------
__global__ __launch_bounds__(256, 1) void gemm_p4(
    const __nv_bfloat16* __restrict__ Ahi, const __nv_bfloat16* __restrict__ Alo,
    const __nv_bfloat16* __restrict__ Bhi, const __nv_bfloat16* __restrict__ Blo,
    const float* __restrict__ bias, const float* __restrict__ xtime,
    const float* __restrict__ xfreq, float* __restrict__ C,
    __nv_bfloat16* __restrict__ shi, __nv_bfloat16* __restrict__ slo)
{
    extern __shared__ char smem[];
    const int row0 = blockIdx.y * 128;
    const int col0 = blockIdx.x * 128;
    float acc[2][8][4];
    gemm128_core(Ahi + (size_t)row0 * G3, Alo + (size_t)row0 * G3,
                 Bhi + (size_t)col0 * G3, Blo + (size_t)col0 * G3,
                 G3, G3, smem, acc);

    const int lane = threadIdx.x & 31;
    const int wid  = threadIdx.x >> 5;
    const int wm   = wid & 3;
    const int wn   = wid >> 2;
#pragma unroll
    for (int mf = 0; mf < 2; mf++) {
        const int rA = row0 + wm * 32 + mf * 16 + (lane >> 2);
#pragma unroll
        for (int half = 0; half < 2; half++) {
            const int r = rA + half * 8;
#pragma unroll
            for (int nf = 0; nf < 8; nf++) {
                const int cc = col0 + wn * 64 + nf * 8 + (lane & 3) * 2;
                const size_t o = (size_t)r * Dd + cc;
                float2 v;
                v.x = acc[mf][nf][half * 2 + 0] + bias[cc];
                v.y = acc[mf][nf][half * 2 + 1] + bias[cc + 1];
                float2 rt = *reinterpret_cast<const float2*>(xtime + o);
                v.x += rt.x; v.y += rt.y;
                *reinterpret_cast<float2*>(C + o) = v;
                float2 rf = *reinterpret_cast<const float2*>(xfreq + o);
                float t0 = v.x + rf.x;
                float t1 = v.y + rf.y;
                __nv_bfloat16 h0 = __float2bfloat16_rn(t0);
                __nv_bfloat16 h1 = __float2bfloat16_rn(t1);
                *reinterpret_cast<__nv_bfloat162*>(shi + o) = __nv_bfloat162(h0, h1);
                *reinterpret_cast<__nv_bfloat162*>(slo + o) = __nv_bfloat162(
                    __float2bfloat16_rn(t0 - __bfloat162float(h0)),
                    __float2bfloat16_rn(t1 - __bfloat162float(h1)));
            }
        }
    }
}

// ---------------------------------------------------------------------------
// Activation helpers
// ---------------------------------------------------------------------------
__device__ __forceinline__ float sigf(float x) {
    return 1.f / (1.f + __expf(-x));
}
__device__ __forceinline__ float tanhfast(float x) {
    float e2x = __expf(2.f * x);
    return 1.f - 2.f / (e2x + 1.f);
}

// ---------------------------------------------------------------------------
// Gate kernel for tensor-core recurrent steps. gh includes b_hh (GEMM bias).
// gh2 (optional) = second split-K partial to add.
// ---------------------------------------------------------------------------
struct SArgs {
    const float *gh, *gh2;
    const float* gi;
    const float* hprev;
    float* hnext;
    __nv_bfloat16 *hhi, *hlo;
    __nv_bfloat16 *ohi, *olo;
    int outStride, outOff, mtok;
};

__global__ __launch_bounds__(256) void gate_step(SArgs a0, SArgs a1)
{
    const SArgs a = blockIdx.z ? a1 : a0;
    const int idx = blockIdx.x * 256 + threadIdx.x;
    const int s = idx >> 9;
    const int j = idx & 511;

    const float* g0 = a.gh + (size_t)s * G3;
    float ghr = g0[j], ghz = g0[Dd + j], ghn = g0[2*Dd + j];
    if (a.gh2) {
        const float* g1 = a.gh2 + (size_t)s * G3;
        ghr += g1[j]; ghz += g1[Dd + j]; ghn += g1[2*Dd + j];
    }
    const int token = s * Mm + a.mtok;
    const float* gir = a.gi + (size_t)token * G3;

    float r = sigf(gir[j]        + ghr);
    float z = sigf(gir[Dd + j]   + ghz);
    float n = tanhfast(gir[2*Dd + j] + r * ghn);
    float hp = a.hprev[idx];
    float hv = (1.f - z) * n + z * hp;

    a.hnext[idx] = hv;
    __nv_bfloat16 hi = __float2bfloat16_rn(hv);
    __nv_bfloat16 lo = __float2bfloat16_rn(hv - __bfloat162float(hi));
    a.hhi[idx] = hi;
    a.hlo[idx] = lo;
    size_t o = (size_t)token * a.outStride + a.outOff + j;
    a.ohi[o] = hi;
    a.olo[o] = lo;
}

// ---------------------------------------------------------------------------
// Persistent time-GRU scan (fp32 SIMT), 512 threads = 16 warps x 32-k slices.
// Grid (TGROUPS=8, TCOLB=16). W cache = 96 regs/thread; single-seq inner loop
// to stay under the 128-reg/thread budget at 512 threads (no spill).
// ---------------------------------------------------------------------------
constexpr int TPART = 17;   // padded partial stride (bank-conflict-free)
constexpr int TIME_SMEM = (TSQ * 512 + TSQ * 3 * 32 * TPART) * 4; // 171520 B

__global__ __launch_bounds__(512, 1) void gru_time_persist(
    const float* __restrict__ gi, const float* __restrict__ Whh,
    const float* __restrict__ bhh,
    __nv_bfloat16* __restrict__ ohi, __nv_bfloat16* __restrict__ olo,
    float* __restrict__ hb0, float* __restrict__ hb1)
{
    const int grp  = blockIdx.x;
    const int cb   = blockIdx.y;
    const int j0   = cb * 32;
    const int tid  = threadIdx.x;
    const int lane = tid & 31;
    const int w    = tid >> 5;     // 0..15
    const int k0   = w * 32;

    extern __shared__ float sm[];
    float* hs   = sm;                       // [TSQ][512]
    float* part = sm + TSQ * 512;           // [TSQ*3*32][TPART]

    float wr[32], wz[32], wn[32];
    {
        const float* Wr = Whh + (size_t)(0 * Dd + j0 + lane) * Dd + k0;
        const float* Wz = Whh + (size_t)(1 * Dd + j0 + lane) * Dd + k0;
        const float* Wn = Whh + (size_t)(2 * Dd + j0 + lane) * Dd + k0;
#pragma unroll
        for (int i = 0; i < 32; i += 4) {
            float4 a = *reinterpret_cast<const float4*>(Wr + i);
            float4 b = *reinterpret_cast<const float4*>(Wz + i);
            float4 c = *reinterpret_cast<const float4*>(Wn + i);
            wr[i] = a.x; wr[i+1] = a.y; wr[i+2] = a.z; wr[i+3] = a.w;
            wz[i] = b.x; wz[i+1] = b.y; wz[i+2] = b.z; wz[i+3] = b.w;
            wn[i] = c.x; wn[i+1] = c.y; wn[i+2] = c.z; wn[i+3] = c.w;
        }
    }

    for (int t = 0; t < Tt; t++) {
        const float* hc = (t & 1) ? hb1 : hb0;
        float*       hn = (t & 1) ? hb0 : hb1;

        for (int i = tid; i < TSQ * 128; i += 512) {
            int s  = i >> 7;
            int k4 = i & 127;
            float4 v = __ldcg(reinterpret_cast<const float4*>(
                hc + (size_t)(grp * TSQ + s) * Dd) + k4);
            *reinterpret_cast<float4*>(hs + s * Dd + k4 * 4) = v;
        }
        __syncthreads();

        for (int s = 0; s < TSQ; s++) {
            float ar = 0.f, az = 0.f, an = 0.f;
            const float* hrow = hs + s * Dd + k0;
#pragma unroll
            for (int i = 0; i < 32; i += 4) {
                float4 h4 = *reinterpret_cast<const float4*>(hrow + i);
                ar = fmaf(h4.x, wr[i],   ar); az = fmaf(h4.x, wz[i],   az); an = fmaf(h4.x, wn[i],   an);
                ar = fmaf(h4.y, wr[i+1], ar); az = fmaf(h4.y, wz[i+1], az); an = fmaf(h4.y, wn[i+1], an);
                ar = fmaf(h4.z, wr[i+2], ar); az = fmaf(h4.z, wz[i+2], az); an = fmaf(h4.z, wn[i+2], an);
                ar = fmaf(h4.w, wr[i+3], ar); az = fmaf(h4.w, wz[i+3], az); an = fmaf(h4.w, wn[i+3], an);
            }
            part[((s * 3 + 0) * 32 + lane) * TPART + w] = ar;
            part[((s * 3 + 1) * 32 + lane) * TPART + w] = az;
            part[((s * 3 + 2) * 32 + lane) * TPART + w] = an;
        }
        __syncthreads();

        for (int idx = tid; idx < TSQ * 32; idx += 512) {
            int s = idx >> 5, j = idx & 31;
            float r = 0.f, z = 0.f, n = 0.f;
            const float* pr = part + ((s * 3 + 0) * 32 + j) * TPART;
            const float* pz = part + ((s * 3 + 1) * 32 + j) * TPART;
            const float* pn = part + ((s * 3 + 2) * 32 + j) * TPART;
#pragma unroll
            for (int ww = 0; ww < 16; ww++) { r += pr[ww]; z += pz[ww]; n += pn[ww]; }

            int sg = grp * TSQ + s;
            int b  = sg / Mm;
            int m  = sg - b * Mm;
            size_t token = ((size_t)(b * Tt + t)) * Mm + m;
            const float* gir = gi + token * G3;
            int jc = j0 + j;
            float rr = sigf(gir[jc]        + r + bhh[jc]);
            float zz = sigf(gir[Dd + jc]   + z + bhh[Dd + jc]);
            float nn = tanhfast(gir[2*Dd + jc] + rr * (n + bhh[2*Dd + jc]));
            float hp = hs[s * Dd + jc];
            float hv = (1.f - zz) * nn + zz * hp;
            __stcg(hn + (size_t)sg * Dd + jc, hv);
            __nv_bfloat16 hib = __float2bfloat16_rn(hv);
            ohi[token * G3 + jc] = hib;
            olo[token * G3 + jc] = __float2bfloat16_rn(hv - __bfloat162float(hib));
        }

        __threadfence();
        __syncthreads();
        if (tid == 0) {
            atomicAdd(&g_tbar[grp], 1u);
            unsigned target = (unsigned)(t + 1) * TCOLB;
            while (ld_cg_u32(&g_tbar[grp]) < target) __nanosleep(64);
        }
        __syncthreads();
    }
}

// ---------------------------------------------------------------------------
// Launch
// ---------------------------------------------------------------------------
static void split_launch(const float* X, const float* Y,
                         __nv_bfloat16* hi, __nv_bfloat16* lo, size_t n)
{
    int n4 = (int)(n / 4);
    split_bf16_kernel<<<(n4 + 255) / 256, 256>>>(X, Y, hi, lo, n4);
}

extern "C" void kernel_launch(void* const* d_in, const int* in_sizes, int n_in,
                              void* d_out_v, int out_size)
{
    const float* x_time = (const float*)d_in[0];
    const float* x_freq = (const float*)d_in[1];
    const float* wt_ih  = (const float*)d_in[2];
    const float* wt_hh  = (const float*)d_in[3];
    const float* bt_ih  = (const float*)d_in[4];
    const float* bt_hh  = (const float*)d_in[5];
    const float* wf_ih  = (const float*)d_in[6];
    const float* wf_hh  = (const float*)d_in[7];
    const float* bf_ih  = (const float*)d_in[8];
    const float* bf_hh  = (const float*)d_in[9];
    const float* wb_ih  = (const float*)d_in[10];
    const float* wb_hh  = (const float*)d_in[11];
    const float* bb_ih  = (const float*)d_in[12];
    const float* bb_hh  = (const float*)d_in[13];
    const float* ws_ih  = (const float*)d_in[14];
    const float* ws_hh  = (const float*)d_in[15];
    const float* bs_ih  = (const float*)d_in[16];
    const float* bs_hh  = (const float*)d_in[17];
    const float* W_time = (const float*)d_in[18];
    const float* b_time = (const float*)d_in[19];
    const float* W_freq = (const float*)d_in[20];
    const float* b_freq = (const float*)d_in[21];
    float* dout = (float*)d_out_v;

    float *gi_t, *gi_f, *gi_b, *gi_s, *h0, *h1, *h2, *h3, *gh;
    unsigned* tbar;
    __nv_bfloat16 *ahi, *alo, *bhi, *blo, *whi, *wlo, *hbhi, *hblo;
    cudaGetSymbolAddress((void**)&gi_t, g_gi_t);
    cudaGetSymbolAddress((void**)&gi_f, g_gi_f);
    cudaGetSymbolAddress((void**)&gi_b, g_gi_b);
    cudaGetSymbolAddress((void**)&gi_s, g_gi_s);
    cudaGetSymbolAddress((void**)&h0,   g_h0);
    cudaGetSymbolAddress((void**)&h1,   g_h1);
    cudaGetSymbolAddress((void**)&h2,   g_h2);
    cudaGetSymbolAddress((void**)&h3,   g_h3);
    cudaGetSymbolAddress((void**)&gh,   g_gh);
    cudaGetSymbolAddress((void**)&tbar, g_tbar);
    cudaGetSymbolAddress((void**)&ahi,  g_ahi);
    cudaGetSymbolAddress((void**)&alo,  g_alo);
    cudaGetSymbolAddress((void**)&bhi,  g_bhi);
    cudaGetSymbolAddress((void**)&blo,  g_blo);
    cudaGetSymbolAddress((void**)&whi,  g_whi);
    cudaGetSymbolAddress((void**)&wlo,  g_wlo);
    cudaGetSymbolAddress((void**)&hbhi, g_hbhi);
    cudaGetSymbolAddress((void**)&hblo, g_hblo);

    const dim3 blk(256);
    cudaFuncSetAttribute(gru_time_persist,
                         cudaFuncAttributeMaxDynamicSharedMemorySize, TIME_SMEM);
    cudaFuncSetAttribute(gemm_bf3,
                         cudaFuncAttributeMaxDynamicSharedMemorySize, GEMM_SMEM);
    cudaFuncSetAttribute(gemm_p4,
                         cudaFuncAttributeMaxDynamicSharedMemorySize, GEMM_SMEM);

    __nv_bfloat16 *wtH = whi + 0*WSLOT, *wtL = wlo + 0*WSLOT;   // wt_ih
    __nv_bfloat16 *wfH = whi + 1*WSLOT, *wfL = wlo + 1*WSLOT;   // wf_ih
    __nv_bfloat16 *wbH = whi + 2*WSLOT, *wbL = wlo + 2*WSLOT;   // wb_ih
    __nv_bfloat16 *wsH = whi + 3*WSLOT, *wsL = wlo + 3*WSLOT;   // ws_ih
    __nv_bfloat16 *wTH = whi + 4*WSLOT, *wTL = wlo + 4*WSLOT;   // W_time
    __nv_bfloat16 *wFH = whi + 5*WSLOT, *wFL = wlo + 5*WSLOT;   // W_freq
    __nv_bfloat16 *wfhH = whi + 6*WSLOT, *wfhL = wlo + 6*WSLOT; // wf_hh
    __nv_bfloat16 *wbhH = whi + 7*WSLOT, *wbhL = wlo + 7*WSLOT; // wb_hh
    __nv_bfloat16 *wshH = whi + 8*WSLOT, *wshL = wlo + 8*WSLOT; // ws_hh

    const size_t HB = (size_t)NSEQ_F * Dd;

    // ---- Phase 0: splits ----
    split_launch(wt_ih,  nullptr, wtH, wtL, (size_t)G3 * Dd);
    split_launch(wf_ih,  nullptr, wfH, wfL, (size_t)G3 * Dd);
    split_launch(wb_ih,  nullptr, wbH, wbL, (size_t)G3 * Dd);
    split_launch(ws_ih,  nullptr, wsH, wsL, (size_t)G3 * Dd);
    split_launch(W_time, nullptr, wTH, wTL, (size_t)Dd * G3);
    split_launch(W_freq, nullptr, wFH, wFL, (size_t)Dd * Dd);
    split_launch(wf_hh,  nullptr, wfhH, wfhL, (size_t)G3 * Dd);
    split_launch(wb_hh,  nullptr, wbhH, wbhL, (size_t)G3 * Dd);
    split_launch(ws_hh,  nullptr, wshH, wshL, (size_t)G3 * Dd);
    split_launch(x_time, nullptr, ahi, alo, (size_t)NT * Dd);

    // ---- Phase 1: input projections ----
    {
        dim3 grid(G3 / 128, NT / 128, 1);
        GArgs a{ahi, alo, wtH, wtL, bt_ih, nullptr, gi_t};
        gemm_bf3<<<grid, blk, GEMM_SMEM>>>(a, a, Dd, Dd, G3);
        GArgs b{ahi, alo, wfH, wfL, bf_ih, nullptr, gi_f};
        gemm_bf3<<<grid, blk, GEMM_SMEM>>>(b, b, Dd, Dd, G3);
        GArgs c{ahi, alo, wbH, wbL, bb_ih, nullptr, gi_b};
        gemm_bf3<<<grid, blk, GEMM_SMEM>>>(c, c, Dd, Dd, G3);
    }

    // ---- Phase 2: persistent time GRU scan (writes xcat cols [0,512) bf16) --
    cudaMemsetAsync(h0, 0, (size_t)NSEQ_T * Dd * sizeof(float));
    cudaMemsetAsync(h1, 0, (size_t)NSEQ_T * Dd * sizeof(float));
    cudaMemsetAsync(tbar, 0, TGROUPS * sizeof(unsigned));
    gru_time_persist<<<dim3(TGROUPS, TCOLB), dim3(512), TIME_SMEM>>>(
        gi_t, wt_hh, bt_hh, ahi, alo, h0, h1);

    // ---- Phase 3: bidirectional freq GRU scan (per-step tensor cores) ----
    cudaMemsetAsync(h0, 0, HB * sizeof(float));
    cudaMemsetAsync(h2, 0, HB * sizeof(float));
    cudaMemsetAsync(hbhi + 0 * HB, 0, HB * sizeof(__nv_bfloat16));
    cudaMemsetAsync(hblo + 0 * HB, 0, HB * sizeof(__nv_bfloat16));
    cudaMemsetAsync(hbhi + 2 * HB, 0, HB * sizeof(__nv_bfloat16));
    cudaMemsetAsync(hblo + 2 * HB, 0, HB * sizeof(__nv_bfloat16));
    for (int s = 0; s < Mm; s++) {
        const int pp = s & 1;
        GArgs gf{hbhi + (0 + pp) * HB, hblo + (0 + pp) * HB,
                 wfhH, wfhL, bf_hh, nullptr, gh};
        GArgs gb{hbhi + (2 + pp) * HB, hblo + (2 + pp) * HB,
                 wbhH, wbhL, bb_hh, nullptr, gh + (size_t)NSEQ_F * G3};
        gemm_bf3<<<dim3(G3 / 128, NSEQ_F / 128, 2), blk, GEMM_SMEM>>>(
            gf, gb, Dd, Dd, G3);

        float* hpF = pp ? h1 : h0;  float* hnF = pp ? h0 : h1;
        float* hpB = pp ? h3 : h2;  float* hnB = pp ? h2 : h3;
        SArgs sf{gh, nullptr, gi_f, hpF, hnF,
                 hbhi + (0 + (pp ^ 1)) * HB, hblo + (0 + (pp ^ 1)) * HB,
                 ahi, alo, G3, Dd, s};
        SArgs sb{gh + (size_t)NSEQ_F * G3, nullptr, gi_b, hpB, hnB,
                 hbhi + (2 + (pp ^ 1)) * HB, hblo + (2 + (pp ^ 1)) * HB,
                 ahi, alo, G3, 2 * Dd, Mm - 1 - s};
        gate_step<<<dim3((int)(HB / 256), 1, 2), blk>>>(sf, sb);
    }

    // ---- Phase 4: fused xt GEMM + split(xt + x_freq) -> bhi/blo ----
    gemm_p4<<<dim3(Dd / 128, NT / 128), blk, GEMM_SMEM>>>(
        ahi, alo, wTH, wTL, b_time, x_time, x_freq, dout, bhi, blo);

    // ---- Phase 5: gi_s = (xt + x_freq) @ ws_ih^T + bs_ih ----
    {
        GArgs a{bhi, blo, wsH, wsL, bs_ih, nullptr, gi_s};
        gemm_bf3<<<dim3(G3 / 128, NT / 128, 1), blk, GEMM_SMEM>>>(a, a, Dd, Dd, G3);
    }

    // ---- Phase 6: stack GRU scan (per-step tensor cores, split-K=2) ----
    cudaMemsetAsync(h0, 0, HB * sizeof(float));
    cudaMemsetAsync(hbhi + 0 * HB, 0, HB * sizeof(__nv_bfloat16));
    cudaMemsetAsync(hblo + 0 * HB, 0, HB * sizeof(__nv_bfloat16));
    for (int s = 0; s < Mm; s++) {
        const int pp = s & 1;
        GArgs k0{hbhi + pp * HB, hblo + pp * HB,
                 wshH, wshL, bs_hh, nullptr, gh};
        GArgs k1{hbhi + pp * HB + 256, hblo + pp * HB + 256,
                 wshH + 256, wshL + 256, nullptr, nullptr,
                 gh + (size_t)NSEQ_F * G3};
        gemm_bf3<<<dim3(G3 / 128, NSEQ_F / 128, 2), blk, GEMM_SMEM>>>(
            k0, k1, 256, Dd, G3);

        float* hp = pp ? h1 : h0;  float* hn = pp ? h0 : h1;
        SArgs sa{gh, gh + (size_t)NSEQ_F * G3, gi_s, hp, hn,
                 hbhi + (pp ^ 1) * HB, hblo + (pp ^ 1) * HB,
                 bhi, blo, Dd, 0, s};
        gate_step<<<dim3((int)(HB / 256), 1, 1), blk>>>(sa, sa);
    }

    // ---- Phase 7: xf = xs @ W_freq^T + b_freq + x_freq ----
    {
        GArgs a{bhi, blo, wFH, wFL, b_freq, x_freq, dout + (size_t)NT * Dd};
        gemm_bf3<<<dim3(Dd / 128, NT / 128, 1), blk, GEMM_SMEM>>>(a, a, Dd, Dd, Dd);
    }
}

// round 13
// speedup vs baseline: 1.3803x; 1.0276x over previous
#include <cuda_runtime.h>
#include <cuda_bf16.h>
#include <cstdint>

// ---------------------------------------------------------------------------
// Problem constants
// ---------------------------------------------------------------------------
constexpr int Bb = 2, Tt = 256, Mm = 80, Dd = 512;
constexpr int NT = Bb * Tt * Mm;   // 40960 tokens
constexpr int G3 = 3 * Dd;         // 1536
constexpr int NSEQ_T = Bb * Mm;    // 160
constexpr int NSEQ_F = Bb * Tt;    // 512

constexpr int TGROUPS = 8;
constexpr int TSQ = NSEQ_T / TGROUPS;  // 20
constexpr int TCOLB = 16;

// ---------------------------------------------------------------------------
// Static device scratch
// ---------------------------------------------------------------------------
__device__ float g_gi_t[(size_t)NT * G3];
__device__ float g_gi_f[(size_t)NT * G3];
__device__ float g_gi_b[(size_t)NT * G3];
__device__ float g_gi_s[(size_t)NT * G3];
__device__ float g_h0[NSEQ_F * Dd];
__device__ float g_h1[NSEQ_F * Dd];
__device__ float g_h2[NSEQ_F * Dd];
__device__ float g_h3[NSEQ_F * Dd];
__device__ float g_ht0[NSEQ_T * Dd];              // time-scan private h ping/pong
__device__ float g_ht1[NSEQ_T * Dd];
__device__ float g_gh[2 * (size_t)NSEQ_F * G3];   // per-step gh (2 dirs / 2 K-halves)
__device__ unsigned g_tbar[TGROUPS];

// bf16 split buffers
__device__ __nv_bfloat16 g_ahi[(size_t)NT * G3];   // xcat split ONLY (scan outputs)
__device__ __nv_bfloat16 g_alo[(size_t)NT * G3];
__device__ __nv_bfloat16 g_bhi[(size_t)NT * Dd];   // x_time split -> later (xt+x_freq)/xs
__device__ __nv_bfloat16 g_blo[(size_t)NT * Dd];
// bf16 hidden-state ping-pong: [dir(2)*pp(2)][NSEQ_F*Dd]
__device__ __nv_bfloat16 g_hbhi[4 * NSEQ_F * Dd];
__device__ __nv_bfloat16 g_hblo[4 * NSEQ_F * Dd];
// weights: 9 slots of 1536*512
constexpr size_t WSLOT = 786432;
__device__ __nv_bfloat16 g_whi[9 * WSLOT];
__device__ __nv_bfloat16 g_wlo[9 * WSLOT];

// ---------------------------------------------------------------------------
// PTX helpers (portable: cp.async / ldmatrix / mma.sync)
// ---------------------------------------------------------------------------
__device__ __forceinline__ uint32_t smem_to_u32(const void* p) {
    uint32_t a;
    asm("{ .reg .u64 t; cvta.to.shared.u64 t, %1; cvt.u32.u64 %0, t; }"
        : "=r"(a) : "l"(p));
    return a;
}
#define CP_ASYNC16(dst, src) \
    asm volatile("cp.async.cg.shared.global [%0], [%1], 16;" \
        :: "r"((uint32_t)(dst)), "l"(src) : "memory")
#define CP_COMMIT() asm volatile("cp.async.commit_group;" ::: "memory")
#define CP_WAIT(n)  asm volatile("cp.async.wait_group %0;" :: "n"(n) : "memory")

__device__ __forceinline__ void ldsm4(uint32_t* r, uint32_t addr) {
    asm volatile("ldmatrix.sync.aligned.m8n8.x4.shared.b16 {%0,%1,%2,%3}, [%4];"
        : "=r"(r[0]), "=r"(r[1]), "=r"(r[2]), "=r"(r[3]) : "r"(addr));
}
__device__ __forceinline__ void mma16816(float* c, const uint32_t* a, const uint32_t* b) {
    asm volatile(
        "mma.sync.aligned.m16n8k16.row.col.f32.bf16.bf16.f32 "
        "{%0,%1,%2,%3}, {%4,%5,%6,%7}, {%8,%9}, {%0,%1,%2,%3};"
        : "+f"(c[0]), "+f"(c[1]), "+f"(c[2]), "+f"(c[3])
        : "r"(a[0]), "r"(a[1]), "r"(a[2]), "r"(a[3]), "r"(b[0]), "r"(b[1]));
}
__device__ __forceinline__ unsigned ld_cg_u32(const unsigned* p) {
    unsigned v;
    asm volatile("ld.global.cg.u32 %0, [%1];" : "=r"(v) : "l"(p));
    return v;
}

// ---------------------------------------------------------------------------
// fp32 -> (hi,lo) bf16 split (optionally X+Y first)
// ---------------------------------------------------------------------------
__global__ void split_bf16_kernel(
    const float* __restrict__ X, const float* __restrict__ Y,
    __nv_bfloat16* __restrict__ hi, __nv_bfloat16* __restrict__ lo, int n4)
{
    int i = blockIdx.x * blockDim.x + threadIdx.x;
    if (i >= n4) return;
    float4 v = reinterpret_cast<const float4*>(X)[i];
    if (Y) {
        float4 y = reinterpret_cast<const float4*>(Y)[i];
        v.x += y.x; v.y += y.y; v.z += y.z; v.w += y.w;
    }
    __nv_bfloat16 h0 = __float2bfloat16_rn(v.x);
    __nv_bfloat16 h1 = __float2bfloat16_rn(v.y);
    __nv_bfloat16 h2 = __float2bfloat16_rn(v.z);
    __nv_bfloat16 h3 = __float2bfloat16_rn(v.w);
    __nv_bfloat16 l0 = __float2bfloat16_rn(v.x - __bfloat162float(h0));
    __nv_bfloat16 l1 = __float2bfloat16_rn(v.y - __bfloat162float(h1));
    __nv_bfloat16 l2 = __float2bfloat16_rn(v.z - __bfloat162float(h2));
    __nv_bfloat16 l3 = __float2bfloat16_rn(v.w - __bfloat162float(h3));
    reinterpret_cast<__nv_bfloat162*>(hi)[2*i]   = __nv_bfloat162(h0, h1);
    reinterpret_cast<__nv_bfloat162*>(hi)[2*i+1] = __nv_bfloat162(h2, h3);
    reinterpret_cast<__nv_bfloat162*>(lo)[2*i]   = __nv_bfloat162(l0, l1);
    reinterpret_cast<__nv_bfloat162*>(lo)[2*i+1] = __nv_bfloat162(l2, l3);
}

// ---------------------------------------------------------------------------
// mma.sync 128x128 tile core (3-product bf16 split), BK=32, 3-stage cp.async.
// ---------------------------------------------------------------------------
constexpr int GSTRIDE = 40;
constexpr int TILE_B  = 128 * GSTRIDE * 2;     // 10240 B
constexpr int STAGE_B = 4 * TILE_B;            // 40960 B
constexpr int NSTAGE  = 3;
constexpr int GEMM_SMEM = NSTAGE * STAGE_B;    // 122880 B

__device__ __forceinline__ void gemm128_core(
    const __nv_bfloat16* __restrict__ Ahi, const __nv_bfloat16* __restrict__ Alo,
    const __nv_bfloat16* __restrict__ Bhi, const __nv_bfloat16* __restrict__ Blo,
    int ld, int K, char* smem, float acc[2][8][4])
{
    const uint32_t sb = smem_to_u32(smem);
    const int tid  = threadIdx.x;
    const int lane = tid & 31;
    const int wid  = tid >> 5;
    const int wm   = wid & 3;
    const int wn   = wid >> 2;

    const __nv_bfloat16* srcs[4] = {Ahi, Alo, Bhi, Blo};

    auto stage_load = [&](int c, int buf) {
        const int k0 = c * 32;
        const uint32_t base = sb + buf * STAGE_B;
#pragma unroll
        for (int t4 = 0; t4 < 4; t4++) {
#pragma unroll
            for (int i = 0; i < 2; i++) {
                int idx = tid + i * 256;
                int r = idx >> 2;
                int seg = idx & 3;
                uint32_t dst = base + t4 * TILE_B + r * (GSTRIDE * 2) + seg * 16;
                const void* gp = srcs[t4] + (size_t)r * ld + k0 + seg * 8;
                CP_ASYNC16(dst, gp);
            }
        }
        CP_COMMIT();
    };

#pragma unroll
    for (int mf = 0; mf < 2; mf++)
#pragma unroll
        for (int nf = 0; nf < 8; nf++)
#pragma unroll
            for (int q = 0; q < 4; q++) acc[mf][nf][q] = 0.f;

    const int NC = K / 32;
    stage_load(0, 0);
    stage_load(1, 1);

    const uint32_t a_off =
        ((wm * 32 + (lane & 15)) * GSTRIDE + ((lane >> 4) * 8)) * 2;
    const uint32_t b_row = wn * 64 + (lane & 7) + ((lane >> 4) & 1) * 8;
    const uint32_t b_off = (b_row * GSTRIDE + (((lane >> 3) & 1) * 8)) * 2;

    int nb = 2 % NSTAGE;
    for (int c = 0; c < NC; c++) {
        if (c + 2 < NC) {
            stage_load(c + 2, nb);
            nb = (nb + 1) % NSTAGE;
            CP_WAIT(2);
        } else if (c + 1 < NC) {
            CP_WAIT(1);
        } else {
            CP_WAIT(0);
        }
        __syncthreads();

        const uint32_t st = sb + (c % NSTAGE) * STAGE_B;

#pragma unroll
        for (int kk = 0; kk < 2; kk++) {
            const uint32_t kb = kk * 32;
            uint32_t ahi[2][4], alo[2][4];
#pragma unroll
            for (int mf = 0; mf < 2; mf++) {
                ldsm4(ahi[mf], st + 0 * TILE_B + a_off + mf * 16 * (GSTRIDE * 2) + kb);
                ldsm4(alo[mf], st + 1 * TILE_B + a_off + mf * 16 * (GSTRIDE * 2) + kb);
            }
            uint32_t bhi[8][2], blo[8][2];
#pragma unroll
            for (int p = 0; p < 4; p++) {
                uint32_t r4[4];
                ldsm4(r4, st + 2 * TILE_B + b_off + p * 16 * (GSTRIDE * 2) + kb);
                bhi[2*p][0] = r4[0]; bhi[2*p][1] = r4[1];
                bhi[2*p+1][0] = r4[2]; bhi[2*p+1][1] = r4[3];
                ldsm4(r4, st + 3 * TILE_B + b_off + p * 16 * (GSTRIDE * 2) + kb);
                blo[2*p][0] = r4[0]; blo[2*p][1] = r4[1];
                blo[2*p+1][0] = r4[2]; blo[2*p+1][1] = r4[3];
            }
#pragma unroll
            for (int mf = 0; mf < 2; mf++)
#pragma unroll
                for (int nf = 0; nf < 8; nf++) {
                    mma16816(acc[mf][nf], ahi[mf], bhi[nf]);
                    mma16816(acc[mf][nf], alo[mf], bhi[nf]);
                    mma16816(acc[mf][nf], ahi[mf], blo[nf]);
                }
        }
        __syncthreads();
    }
}

__device__ __forceinline__ void epi_store(
    float acc[2][8][4], float* __restrict__ C, const float* __restrict__ bias,
    const float* __restrict__ res, int row0, int col0, int N)
{
    const int lane = threadIdx.x & 31;
    const int wid  = threadIdx.x >> 5;
    const int wm   = wid & 3;
    const int wn   = wid >> 2;
#pragma unroll
    for (int mf = 0; mf < 2; mf++) {
        const int rA = row0 + wm * 32 + mf * 16 + (lane >> 2);
        const int rB = rA + 8;
#pragma unroll
        for (int nf = 0; nf < 8; nf++) {
            const int cc = col0 + wn * 64 + nf * 8 + (lane & 3) * 2;
            float b0 = bias ? bias[cc] : 0.f;
            float b1 = bias ? bias[cc + 1] : 0.f;
            float2 v0, v1;
            v0.x = acc[mf][nf][0] + b0;
            v0.y = acc[mf][nf][1] + b1;
            v1.x = acc[mf][nf][2] + b0;
            v1.y = acc[mf][nf][3] + b1;
            if (res) {
                float2 r0 = *reinterpret_cast<const float2*>(res + (size_t)rA * N + cc);
                float2 r1 = *reinterpret_cast<const float2*>(res + (size_t)rB * N + cc);
                v0.x += r0.x; v0.y += r0.y; v1.x += r1.x; v1.y += r1.y;
            }
            *reinterpret_cast<float2*>(C + (size_t)rA * N + cc) = v0;
            *reinterpret_cast<float2*>(C + (size_t)rB * N + cc) = v1;
        }
    }
}

// ---------------------------------------------------------------------------
// Standalone dual-arg GEMM
// ---------------------------------------------------------------------------
struct GArgs {
    const __nv_bfloat16 *Ahi, *Alo, *Bhi, *Blo;
    const float *bias, *res;
    float *C;
};

__global__ __launch_bounds__(256, 1) void gemm_bf3(GArgs g0, GArgs g1,
                                                    int K, int ld, int N)
{
    const GArgs g = blockIdx.z ? g1 : g0;
    extern __shared__ char smem[];
    const int row0 = blockIdx.y * 128;
    const int col0 = blockIdx.x * 128;
    float acc[2][8][4];
    gemm128_core(g.Ahi + (size_t)row0 * ld, g.Alo + (size_t)row0 * ld,
                 g.Bhi + (size_t)col0 * ld, g.Blo + (size_t)col0 * ld,
                 ld, K, smem, acc);
    epi_store(acc, g.C, g.bias, g.res, row0, col0, N);
}

// ---------------------------------------------------------------------------
// Phase-4 fused GEMM: xt -> dout, split(xt + x_freq) -> shi/slo
// ---------------------------------------------------------------------------
__global__ __launch_bounds__(256, 1) void gemm_p4(
    const __nv_bfloat16* __restrict__ Ahi, const __nv_bfloat16* __restrict__ Alo,
    const __nv_bfloat16* __restrict__ Bhi, const __nv_bfloat16* __restrict__ Blo,
    const float* __restrict__ bias, const float* __restrict__ xtime,
    const float* __restrict__ xfreq, float* __restrict__ C,
    __nv_bfloat16* __restrict__ shi, __nv_bfloat16* __restrict__ slo)
{
    extern __shared__ char smem[];
    const int row0 = blockIdx.y * 128;
    const int col0 = blockIdx.x * 128;
    float acc[2][8][4];
    gemm128_core(Ahi + (size_t)row0 * G3, Alo + (size_t)row0 * G3,
                 Bhi + (size_t)col0 * G3, Blo + (size_t)col0 * G3,
                 G3, G3, smem, acc);

    const int lane = threadIdx.x & 31;
    const int wid  = threadIdx.x >> 5;
    const int wm   = wid & 3;
    const int wn   = wid >> 2;
#pragma unroll
    for (int mf = 0; mf < 2; mf++) {
        const int rA = row0 + wm * 32 + mf * 16 + (lane >> 2);
#pragma unroll
        for (int half = 0; half < 2; half++) {
            const int r = rA + half * 8;
#pragma unroll
            for (int nf = 0; nf < 8; nf++) {
                const int cc = col0 + wn * 64 + nf * 8 + (lane & 3) * 2;
                const size_t o = (size_t)r * Dd + cc;
                float2 v;
                v.x = acc[mf][nf][half * 2 + 0] + bias[cc];
                v.y = acc[mf][nf][half * 2 + 1] + bias[cc + 1];
                float2 rt = *reinterpret_cast<const float2*>(xtime + o);
                v.x += rt.x; v.y += rt.y;
                *reinterpret_cast<float2*>(C + o) = v;
                float2 rf = *reinterpret_cast<const float2*>(xfreq + o);
                float t0 = v.x + rf.x;
                float t1 = v.y + rf.y;
                __nv_bfloat16 h0 = __float2bfloat16_rn(t0);
                __nv_bfloat16 h1 = __float2bfloat16_rn(t1);
                *reinterpret_cast<__nv_bfloat162*>(shi + o) = __nv_bfloat162(h0, h1);
                *reinterpret_cast<__nv_bfloat162*>(slo + o) = __nv_bfloat162(
                    __float2bfloat16_rn(t0 - __bfloat162float(h0)),
                    __float2bfloat16_rn(t1 - __bfloat162float(h1)));
            }
        }
    }
}

// ---------------------------------------------------------------------------
// Activation helpers
// ---------------------------------------------------------------------------
__device__ __forceinline__ float sigf(float x) {
    return 1.f / (1.f + __expf(-x));
}
__device__ __forceinline__ float tanhfast(float x) {
    float e2x = __expf(2.f * x);
    return 1.f - 2.f / (e2x + 1.f);
}

// ---------------------------------------------------------------------------
// Gate kernel for tensor-core recurrent steps.
// ---------------------------------------------------------------------------
struct SArgs {
    const float *gh, *gh2;
    const float* gi;
    const float* hprev;
    float* hnext;
    __nv_bfloat16 *hhi, *hlo;
    __nv_bfloat16 *ohi, *olo;
    int outStride, outOff, mtok;
};

__global__ __launch_bounds__(256) void gate_step(SArgs a0, SArgs a1)
{
    const SArgs a = blockIdx.z ? a1 : a0;
    const int idx = blockIdx.x * 256 + threadIdx.x;
    const int s = idx >> 9;
    const int j = idx & 511;

    const float* g0 = a.gh + (size_t)s * G3;
    float ghr = g0[j], ghz = g0[Dd + j], ghn = g0[2*Dd + j];
    if (a.gh2) {
        const float* g1 = a.gh2 + (size_t)s * G3;
        ghr += g1[j]; ghz += g1[Dd + j]; ghn += g1[2*Dd + j];
    }
    const int token = s * Mm + a.mtok;
    const float* gir = a.gi + (size_t)token * G3;

    float r = sigf(gir[j]        + ghr);
    float z = sigf(gir[Dd + j]   + ghz);
    float n = tanhfast(gir[2*Dd + j] + r * ghn);
    float hp = a.hprev[idx];
    float hv = (1.f - z) * n + z * hp;

    a.hnext[idx] = hv;
    __nv_bfloat16 hi = __float2bfloat16_rn(hv);
    __nv_bfloat16 lo = __float2bfloat16_rn(hv - __bfloat162float(hi));
    a.hhi[idx] = hi;
    a.hlo[idx] = lo;
    size_t o = (size_t)token * a.outStride + a.outOff + j;
    a.ohi[o] = hi;
    a.olo[o] = lo;
}

// ---------------------------------------------------------------------------
// Persistent time-GRU scan (fp32 SIMT), 512 threads = 16 warps x 32-k slices.
// ---------------------------------------------------------------------------
constexpr int TPART = 17;   // padded partial stride (bank-conflict-free)
constexpr int TIME_SMEM = (TSQ * 512 + TSQ * 3 * 32 * TPART) * 4; // 171520 B

__global__ __launch_bounds__(512, 1) void gru_time_persist(
    const float* __restrict__ gi, const float* __restrict__ Whh,
    const float* __restrict__ bhh,
    __nv_bfloat16* __restrict__ ohi, __nv_bfloat16* __restrict__ olo,
    float* __restrict__ hb0, float* __restrict__ hb1)
{
    const int grp  = blockIdx.x;
    const int cb   = blockIdx.y;
    const int j0   = cb * 32;
    const int tid  = threadIdx.x;
    const int lane = tid & 31;
    const int w    = tid >> 5;     // 0..15
    const int k0   = w * 32;

    extern __shared__ float sm[];
    float* hs   = sm;                       // [TSQ][512]
    float* part = sm + TSQ * 512;           // [TSQ*3*32][TPART]

    float wr[32], wz[32], wn[32];
    {
        const float* Wr = Whh + (size_t)(0 * Dd + j0 + lane) * Dd + k0;
        const float* Wz = Whh + (size_t)(1 * Dd + j0 + lane) * Dd + k0;
        const float* Wn = Whh + (size_t)(2 * Dd + j0 + lane) * Dd + k0;
#pragma unroll
        for (int i = 0; i < 32; i += 4) {
            float4 a = *reinterpret_cast<const float4*>(Wr + i);
            float4 b = *reinterpret_cast<const float4*>(Wz + i);
            float4 c = *reinterpret_cast<const float4*>(Wn + i);
            wr[i] = a.x; wr[i+1] = a.y; wr[i+2] = a.z; wr[i+3] = a.w;
            wz[i] = b.x; wz[i+1] = b.y; wz[i+2] = b.z; wz[i+3] = b.w;
            wn[i] = c.x; wn[i+1] = c.y; wn[i+2] = c.z; wn[i+3] = c.w;
        }
    }

    for (int t = 0; t < Tt; t++) {
        const float* hc = (t & 1) ? hb1 : hb0;
        float*       hn = (t & 1) ? hb0 : hb1;

        for (int i = tid; i < TSQ * 128; i += 512) {
            int s  = i >> 7;
            int k4 = i & 127;
            float4 v = __ldcg(reinterpret_cast<const float4*>(
                hc + (size_t)(grp * TSQ + s) * Dd) + k4);
            *reinterpret_cast<float4*>(hs + s * Dd + k4 * 4) = v;
        }
        __syncthreads();

        for (int s = 0; s < TSQ; s++) {
            float ar = 0.f, az = 0.f, an = 0.f;
            const float* hrow = hs + s * Dd + k0;
#pragma unroll
            for (int i = 0; i < 32; i += 4) {
                float4 h4 = *reinterpret_cast<const float4*>(hrow + i);
                ar = fmaf(h4.x, wr[i],   ar); az = fmaf(h4.x, wz[i],   az); an = fmaf(h4.x, wn[i],   an);
                ar = fmaf(h4.y, wr[i+1], ar); az = fmaf(h4.y, wz[i+1], az); an = fmaf(h4.y, wn[i+1], an);
                ar = fmaf(h4.z, wr[i+2], ar); az = fmaf(h4.z, wz[i+2], az); an = fmaf(h4.z, wn[i+2], an);
                ar = fmaf(h4.w, wr[i+3], ar); az = fmaf(h4.w, wz[i+3], az); an = fmaf(h4.w, wn[i+3], an);
            }
            part[((s * 3 + 0) * 32 + lane) * TPART + w] = ar;
            part[((s * 3 + 1) * 32 + lane) * TPART + w] = az;
            part[((s * 3 + 2) * 32 + lane) * TPART + w] = an;
        }
        __syncthreads();

        for (int idx = tid; idx < TSQ * 32; idx += 512) {
            int s = idx >> 5, j = idx & 31;
            float r = 0.f, z = 0.f, n = 0.f;
            const float* pr = part + ((s * 3 + 0) * 32 + j) * TPART;
            const float* pz = part + ((s * 3 + 1) * 32 + j) * TPART;
            const float* pn = part + ((s * 3 + 2) * 32 + j) * TPART;
#pragma unroll
            for (int ww = 0; ww < 16; ww++) { r += pr[ww]; z += pz[ww]; n += pn[ww]; }

            int sg = grp * TSQ + s;
            int b  = sg / Mm;
            int m  = sg - b * Mm;
            size_t token = ((size_t)(b * Tt + t)) * Mm + m;
            const float* gir = gi + token * G3;
            int jc = j0 + j;
            float rr = sigf(gir[jc]        + r + bhh[jc]);
            float zz = sigf(gir[Dd + jc]   + z + bhh[Dd + jc]);
            float nn = tanhfast(gir[2*Dd + jc] + rr * (n + bhh[2*Dd + jc]));
            float hp = hs[s * Dd + jc];
            float hv = (1.f - zz) * nn + zz * hp;
            __stcg(hn + (size_t)sg * Dd + jc, hv);
            __nv_bfloat16 hib = __float2bfloat16_rn(hv);
            ohi[token * G3 + jc] = hib;
            olo[token * G3 + jc] = __float2bfloat16_rn(hv - __bfloat162float(hib));
        }

        __threadfence();
        __syncthreads();
        if (tid == 0) {
            atomicAdd(&g_tbar[grp], 1u);
            unsigned target = (unsigned)(t + 1) * TCOLB;
            while (ld_cg_u32(&g_tbar[grp]) < target) __nanosleep(64);
        }
        __syncthreads();
    }
}

// ---------------------------------------------------------------------------
// Launch
// ---------------------------------------------------------------------------
static void split_launch_s(cudaStream_t st, const float* X, const float* Y,
                           __nv_bfloat16* hi, __nv_bfloat16* lo, size_t n)
{
    int n4 = (int)(n / 4);
    split_bf16_kernel<<<(n4 + 255) / 256, 256, 0, st>>>(X, Y, hi, lo, n4);
}

extern "C" void kernel_launch(void* const* d_in, const int* in_sizes, int n_in,
                              void* d_out_v, int out_size)
{
    const float* x_time = (const float*)d_in[0];
    const float* x_freq = (const float*)d_in[1];
    const float* wt_ih  = (const float*)d_in[2];
    const float* wt_hh  = (const float*)d_in[3];
    const float* bt_ih  = (const float*)d_in[4];
    const float* bt_hh  = (const float*)d_in[5];
    const float* wf_ih  = (const float*)d_in[6];
    const float* wf_hh  = (const float*)d_in[7];
    const float* bf_ih  = (const float*)d_in[8];
    const float* bf_hh  = (const float*)d_in[9];
    const float* wb_ih  = (const float*)d_in[10];
    const float* wb_hh  = (const float*)d_in[11];
    const float* bb_ih  = (const float*)d_in[12];
    const float* bb_hh  = (const float*)d_in[13];
    const float* ws_ih  = (const float*)d_in[14];
    const float* ws_hh  = (const float*)d_in[15];
    const float* bs_ih  = (const float*)d_in[16];
    const float* bs_hh  = (const float*)d_in[17];
    const float* W_time = (const float*)d_in[18];
    const float* b_time = (const float*)d_in[19];
    const float* W_freq = (const float*)d_in[20];
    const float* b_freq = (const float*)d_in[21];
    float* dout = (float*)d_out_v;

    float *gi_t, *gi_f, *gi_b, *gi_s, *h0, *h1, *h2, *h3, *ht0, *ht1, *gh;
    unsigned* tbar;
    __nv_bfloat16 *ahi, *alo, *bhi, *blo, *whi, *wlo, *hbhi, *hblo;
    cudaGetSymbolAddress((void**)&gi_t, g_gi_t);
    cudaGetSymbolAddress((void**)&gi_f, g_gi_f);
    cudaGetSymbolAddress((void**)&gi_b, g_gi_b);
    cudaGetSymbolAddress((void**)&gi_s, g_gi_s);
    cudaGetSymbolAddress((void**)&h0,   g_h0);
    cudaGetSymbolAddress((void**)&h1,   g_h1);
    cudaGetSymbolAddress((void**)&h2,   g_h2);
    cudaGetSymbolAddress((void**)&h3,   g_h3);
    cudaGetSymbolAddress((void**)&ht0,  g_ht0);
    cudaGetSymbolAddress((void**)&ht1,  g_ht1);
    cudaGetSymbolAddress((void**)&gh,   g_gh);
    cudaGetSymbolAddress((void**)&tbar, g_tbar);
    cudaGetSymbolAddress((void**)&ahi,  g_ahi);
    cudaGetSymbolAddress((void**)&alo,  g_alo);
    cudaGetSymbolAddress((void**)&bhi,  g_bhi);
    cudaGetSymbolAddress((void**)&blo,  g_blo);
    cudaGetSymbolAddress((void**)&whi,  g_whi);
    cudaGetSymbolAddress((void**)&wlo,  g_wlo);
    cudaGetSymbolAddress((void**)&hbhi, g_hbhi);
    cudaGetSymbolAddress((void**)&hblo, g_hblo);

    // one-time side stream + fork/join events (host resources; same work/call)
    static cudaStream_t sSide = nullptr;
    static cudaEvent_t evFork = nullptr, evJoin = nullptr;
    if (!sSide) {
        cudaStreamCreateWithFlags(&sSide, cudaStreamNonBlocking);
        cudaEventCreateWithFlags(&evFork, cudaEventDisableTiming);
        cudaEventCreateWithFlags(&evJoin, cudaEventDisableTiming);
    }
    cudaStream_t s0 = 0;

    const dim3 blk(256);
    cudaFuncSetAttribute(gru_time_persist,
                         cudaFuncAttributeMaxDynamicSharedMemorySize, TIME_SMEM);
    cudaFuncSetAttribute(gemm_bf3,
                         cudaFuncAttributeMaxDynamicSharedMemorySize, GEMM_SMEM);
    cudaFuncSetAttribute(gemm_p4,
                         cudaFuncAttributeMaxDynamicSharedMemorySize, GEMM_SMEM);

    __nv_bfloat16 *wtH = whi + 0*WSLOT, *wtL = wlo + 0*WSLOT;   // wt_ih
    __nv_bfloat16 *wfH = whi + 1*WSLOT, *wfL = wlo + 1*WSLOT;   // wf_ih
    __nv_bfloat16 *wbH = whi + 2*WSLOT, *wbL = wlo + 2*WSLOT;   // wb_ih
    __nv_bfloat16 *wsH = whi + 3*WSLOT, *wsL = wlo + 3*WSLOT;   // ws_ih
    __nv_bfloat16 *wTH = whi + 4*WSLOT, *wTL = wlo + 4*WSLOT;   // W_time
    __nv_bfloat16 *wFH = whi + 5*WSLOT, *wFL = wlo + 5*WSLOT;   // W_freq
    __nv_bfloat16 *wfhH = whi + 6*WSLOT, *wfhL = wlo + 6*WSLOT; // wf_hh
    __nv_bfloat16 *wbhH = whi + 7*WSLOT, *wbhL = wlo + 7*WSLOT; // wb_hh
    __nv_bfloat16 *wshH = whi + 8*WSLOT, *wshL = wlo + 8*WSLOT; // ws_hh

    const size_t HB = (size_t)NSEQ_F * Dd;

    // ---- Phase 0: splits (main stream). x_time split -> bhi/blo (NOT ahi!) --
    split_launch_s(s0, wt_ih,  nullptr, wtH, wtL, (size_t)G3 * Dd);
    split_launch_s(s0, wf_ih,  nullptr, wfH, wfL, (size_t)G3 * Dd);
    split_launch_s(s0, wb_ih,  nullptr, wbH, wbL, (size_t)G3 * Dd);
    split_launch_s(s0, ws_ih,  nullptr, wsH, wsL, (size_t)G3 * Dd);
    split_launch_s(s0, W_time, nullptr, wTH, wTL, (size_t)Dd * G3);
    split_launch_s(s0, W_freq, nullptr, wFH, wFL, (size_t)Dd * Dd);
    split_launch_s(s0, wf_hh,  nullptr, wfhH, wfhL, (size_t)G3 * Dd);
    split_launch_s(s0, wb_hh,  nullptr, wbhH, wbhL, (size_t)G3 * Dd);
    split_launch_s(s0, ws_hh,  nullptr, wshH, wshL, (size_t)G3 * Dd);
    split_launch_s(s0, x_time, nullptr, bhi, blo, (size_t)NT * Dd);

    // ---- Phase 1a: gi_t GEMM (reads bhi/blo) + time-scan memsets (main) ----
    {
        GArgs a{bhi, blo, wtH, wtL, bt_ih, nullptr, gi_t};
        gemm_bf3<<<dim3(G3 / 128, NT / 128, 1), blk, GEMM_SMEM>>>(a, a, Dd, Dd, G3);
    }
    cudaMemsetAsync(ht0, 0, (size_t)NSEQ_T * Dd * sizeof(float));
    cudaMemsetAsync(ht1, 0, (size_t)NSEQ_T * Dd * sizeof(float));
    cudaMemsetAsync(tbar, 0, TGROUPS * sizeof(unsigned));

    // ---- FORK: time scan on side stream writes ahi/alo cols [0,512) only ----
    cudaEventRecord(evFork, s0);
    cudaStreamWaitEvent(sSide, evFork, 0);
    gru_time_persist<<<dim3(TGROUPS, TCOLB), dim3(512), TIME_SMEM, sSide>>>(
        gi_t, wt_hh, bt_hh, ahi, alo, ht0, ht1);
    cudaEventRecord(evJoin, sSide);

    // ---- Phase 1b: gi_f / gi_b GEMMs (main; read bhi/blo — no alias) ----
    {
        dim3 grid(G3 / 128, NT / 128, 1);
        GArgs b{bhi, blo, wfH, wfL, bf_ih, nullptr, gi_f};
        gemm_bf3<<<grid, blk, GEMM_SMEM>>>(b, b, Dd, Dd, G3);
        GArgs c{bhi, blo, wbH, wbL, bb_ih, nullptr, gi_b};
        gemm_bf3<<<grid, blk, GEMM_SMEM>>>(c, c, Dd, Dd, G3);
    }

    // ---- Phase 3: bidirectional freq GRU scan (main; writes ahi cols [512,1536))
    cudaMemsetAsync(h0, 0, HB * sizeof(float));
    cudaMemsetAsync(h2, 0, HB * sizeof(float));
    cudaMemsetAsync(hbhi + 0 * HB, 0, HB * sizeof(__nv_bfloat16));
    cudaMemsetAsync(hblo + 0 * HB, 0, HB * sizeof(__nv_bfloat16));
    cudaMemsetAsync(hbhi + 2 * HB, 0, HB * sizeof(__nv_bfloat16));
    cudaMemsetAsync(hblo + 2 * HB, 0, HB * sizeof(__nv_bfloat16));
    for (int s = 0; s < Mm; s++) {
        const int pp = s & 1;
        GArgs gf{hbhi + (0 + pp) * HB, hblo + (0 + pp) * HB,
                 wfhH, wfhL, bf_hh, nullptr, gh};
        GArgs gb{hbhi + (2 + pp) * HB, hblo + (2 + pp) * HB,
                 wbhH, wbhL, bb_hh, nullptr, gh + (size_t)NSEQ_F * G3};
        gemm_bf3<<<dim3(G3 / 128, NSEQ_F / 128, 2), blk, GEMM_SMEM>>>(
            gf, gb, Dd, Dd, G3);

        float* hpF = pp ? h1 : h0;  float* hnF = pp ? h0 : h1;
        float* hpB = pp ? h3 : h2;  float* hnB = pp ? h2 : h3;
        SArgs sf{gh, nullptr, gi_f, hpF, hnF,
                 hbhi + (0 + (pp ^ 1)) * HB, hblo + (0 + (pp ^ 1)) * HB,
                 ahi, alo, G3, Dd, s};
        SArgs sb{gh + (size_t)NSEQ_F * G3, nullptr, gi_b, hpB, hnB,
                 hbhi + (2 + (pp ^ 1)) * HB, hblo + (2 + (pp ^ 1)) * HB,
                 ahi, alo, G3, 2 * Dd, Mm - 1 - s};
        gate_step<<<dim3((int)(HB / 256), 1, 2), blk>>>(sf, sb);
    }

    // ---- JOIN: wait for the time scan before phase 4 ----
    cudaStreamWaitEvent(s0, evJoin, 0);

    // ---- Phase 4: fused xt GEMM + split(xt + x_freq) -> bhi/blo (x_time
    //      split is dead past this point) ----
    gemm_p4<<<dim3(Dd / 128, NT / 128), blk, GEMM_SMEM>>>(
        ahi, alo, wTH, wTL, b_time, x_time, x_freq, dout, bhi, blo);

    // ---- Phase 5: gi_s = (xt + x_freq) @ ws_ih^T + bs_ih ----
    {
        GArgs a{bhi, blo, wsH, wsL, bs_ih, nullptr, gi_s};
        gemm_bf3<<<dim3(G3 / 128, NT / 128, 1), blk, GEMM_SMEM>>>(a, a, Dd, Dd, G3);
    }

    // ---- Phase 6: stack GRU scan (per-step tensor cores, split-K=2) ----
    cudaMemsetAsync(h0, 0, HB * sizeof(float));
    cudaMemsetAsync(hbhi + 0 * HB, 0, HB * sizeof(__nv_bfloat16));
    cudaMemsetAsync(hblo + 0 * HB, 0, HB * sizeof(__nv_bfloat16));
    for (int s = 0; s < Mm; s++) {
        const int pp = s & 1;
        GArgs k0{hbhi + pp * HB, hblo + pp * HB,
                 wshH, wshL, bs_hh, nullptr, gh};
        GArgs k1{hbhi + pp * HB + 256, hblo + pp * HB + 256,
                 wshH + 256, wshL + 256, nullptr, nullptr,
                 gh + (size_t)NSEQ_F * G3};
        gemm_bf3<<<dim3(G3 / 128, NSEQ_F / 128, 2), blk, GEMM_SMEM>>>(
            k0, k1, 256, Dd, G3);

        float* hp = pp ? h1 : h0;  float* hn = pp ? h0 : h1;
        SArgs sa{gh, gh + (size_t)NSEQ_F * G3, gi_s, hp, hn,
                 hbhi + (pp ^ 1) * HB, hblo + (pp ^ 1) * HB,
                 bhi, blo, Dd, 0, s};
        gate_step<<<dim3((int)(HB / 256), 1, 1), blk>>>(sa, sa);
    }

    // ---- Phase 7: xf = xs @ W_freq^T + b_freq + x_freq ----
    {
        GArgs a{bhi, blo, wFH, wFL, b_freq, x_freq, dout + (size_t)NT * Dd};
        gemm_bf3<<<dim3(Dd / 128, NT / 128, 1), blk, GEMM_SMEM>>>(a, a, Dd, Dd, Dd);
    }
}

// round 15
// speedup vs baseline: 1.4066x; 1.0190x over previous
#include <cuda_runtime.h>
#include <cuda_bf16.h>
#include <cstdint>

// ---------------------------------------------------------------------------
// Problem constants
// ---------------------------------------------------------------------------
constexpr int Bb = 2, Tt = 256, Mm = 80, Dd = 512;
constexpr int NT = Bb * Tt * Mm;   // 40960 tokens
constexpr int G3 = 3 * Dd;         // 1536
constexpr int NSEQ_T = Bb * Mm;    // 160
constexpr int NSEQ_F = Bb * Tt;    // 512

constexpr int TGROUPS = 4;             // fewer, fatter groups -> 64-block grid
constexpr int TSQ = NSEQ_T / TGROUPS;  // 40 seqs per group
constexpr int TCHUNK = 20;             // partial-array chunk (smem limit)
constexpr int TCOLB = 16;

// ---------------------------------------------------------------------------
// Static device scratch
// ---------------------------------------------------------------------------
__device__ float g_gi_t[(size_t)NT * G3];
__device__ float g_gi_f[(size_t)NT * G3];
__device__ float g_gi_b[(size_t)NT * G3];
__device__ float g_gi_s[(size_t)NT * G3];
__device__ float g_h0[NSEQ_F * Dd];
__device__ float g_h1[NSEQ_F * Dd];
__device__ float g_h2[NSEQ_F * Dd];
__device__ float g_h3[NSEQ_F * Dd];
__device__ float g_ht0[NSEQ_T * Dd];              // time-scan private h ping/pong
__device__ float g_ht1[NSEQ_T * Dd];
__device__ float g_gh[2 * (size_t)NSEQ_F * G3];   // per-step gh (2 dirs / 2 K-halves)
__device__ unsigned g_tbar[TGROUPS];

// bf16 split buffers
__device__ __nv_bfloat16 g_ahi[(size_t)NT * G3];   // xcat split ONLY (scan outputs)
__device__ __nv_bfloat16 g_alo[(size_t)NT * G3];
__device__ __nv_bfloat16 g_bhi[(size_t)NT * Dd];   // x_time split -> later (xt+x_freq)/xs
__device__ __nv_bfloat16 g_blo[(size_t)NT * Dd];
// bf16 hidden-state ping-pong: [dir(2)*pp(2)][NSEQ_F*Dd]
__device__ __nv_bfloat16 g_hbhi[4 * NSEQ_F * Dd];
__device__ __nv_bfloat16 g_hblo[4 * NSEQ_F * Dd];
// weights: 9 slots of 1536*512
constexpr size_t WSLOT = 786432;
__device__ __nv_bfloat16 g_whi[9 * WSLOT];
__device__ __nv_bfloat16 g_wlo[9 * WSLOT];

// ---------------------------------------------------------------------------
// PTX helpers (portable: cp.async / ldmatrix / mma.sync)
// ---------------------------------------------------------------------------
__device__ __forceinline__ uint32_t smem_to_u32(const void* p) {
    uint32_t a;
    asm("{ .reg .u64 t; cvta.to.shared.u64 t, %1; cvt.u32.u64 %0, t; }"
        : "=r"(a) : "l"(p));
    return a;
}
#define CP_ASYNC16(dst, src) \
    asm volatile("cp.async.cg.shared.global [%0], [%1], 16;" \
        :: "r"((uint32_t)(dst)), "l"(src) : "memory")
#define CP_COMMIT() asm volatile("cp.async.commit_group;" ::: "memory")
#define CP_WAIT(n)  asm volatile("cp.async.wait_group %0;" :: "n"(n) : "memory")

__device__ __forceinline__ void ldsm4(uint32_t* r, uint32_t addr) {
    asm volatile("ldmatrix.sync.aligned.m8n8.x4.shared.b16 {%0,%1,%2,%3}, [%4];"
        : "=r"(r[0]), "=r"(r[1]), "=r"(r[2]), "=r"(r[3]) : "r"(addr));
}
__device__ __forceinline__ void mma16816(float* c, const uint32_t* a, const uint32_t* b) {
    asm volatile(
        "mma.sync.aligned.m16n8k16.row.col.f32.bf16.bf16.f32 "
        "{%0,%1,%2,%3}, {%4,%5,%6,%7}, {%8,%9}, {%0,%1,%2,%3};"
        : "+f"(c[0]), "+f"(c[1]), "+f"(c[2]), "+f"(c[3])
        : "r"(a[0]), "r"(a[1]), "r"(a[2]), "r"(a[3]), "r"(b[0]), "r"(b[1]));
}
__device__ __forceinline__ unsigned ld_cg_u32(const unsigned* p) {
    unsigned v;
    asm volatile("ld.global.cg.u32 %0, [%1];" : "=r"(v) : "l"(p));
    return v;
}

// ---------------------------------------------------------------------------
// fp32 -> (hi,lo) bf16 split (optionally X+Y first)
// ---------------------------------------------------------------------------
__global__ void split_bf16_kernel(
    const float* __restrict__ X, const float* __restrict__ Y,
    __nv_bfloat16* __restrict__ hi, __nv_bfloat16* __restrict__ lo, int n4)
{
    int i = blockIdx.x * blockDim.x + threadIdx.x;
    if (i >= n4) return;
    float4 v = reinterpret_cast<const float4*>(X)[i];
    if (Y) {
        float4 y = reinterpret_cast<const float4*>(Y)[i];
        v.x += y.x; v.y += y.y; v.z += y.z; v.w += y.w;
    }
    __nv_bfloat16 h0 = __float2bfloat16_rn(v.x);
    __nv_bfloat16 h1 = __float2bfloat16_rn(v.y);
    __nv_bfloat16 h2 = __float2bfloat16_rn(v.z);
    __nv_bfloat16 h3 = __float2bfloat16_rn(v.w);
    __nv_bfloat16 l0 = __float2bfloat16_rn(v.x - __bfloat162float(h0));
    __nv_bfloat16 l1 = __float2bfloat16_rn(v.y - __bfloat162float(h1));
    __nv_bfloat16 l2 = __float2bfloat16_rn(v.z - __bfloat162float(h2));
    __nv_bfloat16 l3 = __float2bfloat16_rn(v.w - __bfloat162float(h3));
    reinterpret_cast<__nv_bfloat162*>(hi)[2*i]   = __nv_bfloat162(h0, h1);
    reinterpret_cast<__nv_bfloat162*>(hi)[2*i+1] = __nv_bfloat162(h2, h3);
    reinterpret_cast<__nv_bfloat162*>(lo)[2*i]   = __nv_bfloat162(l0, l1);
    reinterpret_cast<__nv_bfloat162*>(lo)[2*i+1] = __nv_bfloat162(l2, l3);
}

// ---------------------------------------------------------------------------
// mma.sync 128x128 tile core (3-product bf16 split), BK=32, 3-stage cp.async.
// ---------------------------------------------------------------------------
constexpr int GSTRIDE = 40;
constexpr int TILE_B  = 128 * GSTRIDE * 2;     // 10240 B
constexpr int STAGE_B = 4 * TILE_B;            // 40960 B
constexpr int NSTAGE  = 3;
constexpr int GEMM_SMEM = NSTAGE * STAGE_B;    // 122880 B

__device__ __forceinline__ void gemm128_core(
    const __nv_bfloat16* __restrict__ Ahi, const __nv_bfloat16* __restrict__ Alo,
    const __nv_bfloat16* __restrict__ Bhi, const __nv_bfloat16* __restrict__ Blo,
    int ld, int K, char* smem, float acc[2][8][4])
{
    const uint32_t sb = smem_to_u32(smem);
    const int tid  = threadIdx.x;
    const int lane = tid & 31;
    const int wid  = tid >> 5;
    const int wm   = wid & 3;
    const int wn   = wid >> 2;

    const __nv_bfloat16* srcs[4] = {Ahi, Alo, Bhi, Blo};

    auto stage_load = [&](int c, int buf) {
        const int k0 = c * 32;
        const uint32_t base = sb + buf * STAGE_B;
#pragma unroll
        for (int t4 = 0; t4 < 4; t4++) {
#pragma unroll
            for (int i = 0; i < 2; i++) {
                int idx = tid + i * 256;
                int r = idx >> 2;
                int seg = idx & 3;
                uint32_t dst = base + t4 * TILE_B + r * (GSTRIDE * 2) + seg * 16;
                const void* gp = srcs[t4] + (size_t)r * ld + k0 + seg * 8;
                CP_ASYNC16(dst, gp);
            }
        }
        CP_COMMIT();
    };

#pragma unroll
    for (int mf = 0; mf < 2; mf++)
#pragma unroll
        for (int nf = 0; nf < 8; nf++)
#pragma unroll
            for (int q = 0; q < 4; q++) acc[mf][nf][q] = 0.f;

    const int NC = K / 32;
    stage_load(0, 0);
    stage_load(1, 1);

    const uint32_t a_off =
        ((wm * 32 + (lane & 15)) * GSTRIDE + ((lane >> 4) * 8)) * 2;
    const uint32_t b_row = wn * 64 + (lane & 7) + ((lane >> 4) & 1) * 8;
    const uint32_t b_off = (b_row * GSTRIDE + (((lane >> 3) & 1) * 8)) * 2;

    int nb = 2 % NSTAGE;
    for (int c = 0; c < NC; c++) {
        if (c + 2 < NC) {
            stage_load(c + 2, nb);
            nb = (nb + 1) % NSTAGE;
            CP_WAIT(2);
        } else if (c + 1 < NC) {
            CP_WAIT(1);
        } else {
            CP_WAIT(0);
        }
        __syncthreads();

        const uint32_t st = sb + (c % NSTAGE) * STAGE_B;

#pragma unroll
        for (int kk = 0; kk < 2; kk++) {
            const uint32_t kb = kk * 32;
            uint32_t ahi[2][4], alo[2][4];
#pragma unroll
            for (int mf = 0; mf < 2; mf++) {
                ldsm4(ahi[mf], st + 0 * TILE_B + a_off + mf * 16 * (GSTRIDE * 2) + kb);
                ldsm4(alo[mf], st + 1 * TILE_B + a_off + mf * 16 * (GSTRIDE * 2) + kb);
            }
            uint32_t bhi[8][2], blo[8][2];
#pragma unroll
            for (int p = 0; p < 4; p++) {
                uint32_t r4[4];
                ldsm4(r4, st + 2 * TILE_B + b_off + p * 16 * (GSTRIDE * 2) + kb);
                bhi[2*p][0] = r4[0]; bhi[2*p][1] = r4[1];
                bhi[2*p+1][0] = r4[2]; bhi[2*p+1][1] = r4[3];
                ldsm4(r4, st + 3 * TILE_B + b_off + p * 16 * (GSTRIDE * 2) + kb);
                blo[2*p][0] = r4[0]; blo[2*p][1] = r4[1];
                blo[2*p+1][0] = r4[2]; blo[2*p+1][1] = r4[3];
            }
#pragma unroll
            for (int mf = 0; mf < 2; mf++)
#pragma unroll
                for (int nf = 0; nf < 8; nf++) {
                    mma16816(acc[mf][nf], ahi[mf], bhi[nf]);
                    mma16816(acc[mf][nf], alo[mf], bhi[nf]);
                    mma16816(acc[mf][nf], ahi[mf], blo[nf]);
                }
        }
        __syncthreads();
    }
}

__device__ __forceinline__ void epi_store(
    float acc[2][8][4], float* __restrict__ C, const float* __restrict__ bias,
    const float* __restrict__ res, int row0, int col0, int N)
{
    const int lane = threadIdx.x & 31;
    const int wid  = threadIdx.x >> 5;
    const int wm   = wid & 3;
    const int wn   = wid >> 2;
#pragma unroll
    for (int mf = 0; mf < 2; mf++) {
        const int rA = row0 + wm * 32 + mf * 16 + (lane >> 2);
        const int rB = rA + 8;
#pragma unroll
        for (int nf = 0; nf < 8; nf++) {
            const int cc = col0 + wn * 64 + nf * 8 + (lane & 3) * 2;
            float b0 = bias ? bias[cc] : 0.f;
            float b1 = bias ? bias[cc + 1] : 0.f;
            float2 v0, v1;
            v0.x = acc[mf][nf][0] + b0;
            v0.y = acc[mf][nf][1] + b1;
            v1.x = acc[mf][nf][2] + b0;
            v1.y = acc[mf][nf][3] + b1;
            if (res) {
                float2 r0 = *reinterpret_cast<const float2*>(res + (size_t)rA * N + cc);
                float2 r1 = *reinterpret_cast<const float2*>(res + (size_t)rB * N + cc);
                v0.x += r0.x; v0.y += r0.y; v1.x += r1.x; v1.y += r1.y;
            }
            *reinterpret_cast<float2*>(C + (size_t)rA * N + cc) = v0;
            *reinterpret_cast<float2*>(C + (size_t)rB * N + cc) = v1;
        }
    }
}

// ---------------------------------------------------------------------------
// Standalone dual-arg GEMM
// ---------------------------------------------------------------------------
struct GArgs {
    const __nv_bfloat16 *Ahi, *Alo, *Bhi, *Blo;
    const float *bias, *res;
    float *C;
};

__global__ __launch_bounds__(256, 1) void gemm_bf3(GArgs g0, GArgs g1,
                                                    int K, int ld, int N)
{
    const GArgs g = blockIdx.z ? g1 : g0;
    extern __shared__ char smem[];
    const int row0 = blockIdx.y * 128;
    const int col0 = blockIdx.x * 128;
    float acc[2][8][4];
    gemm128_core(g.Ahi + (size_t)row0 * ld, g.Alo + (size_t)row0 * ld,
                 g.Bhi + (size_t)col0 * ld, g.Blo + (size_t)col0 * ld,
                 ld, K, smem, acc);
    epi_store(acc, g.C, g.bias, g.res, row0, col0, N);
}

// ---------------------------------------------------------------------------
// Phase-4 fused GEMM: xt -> dout, split(xt + x_freq) -> shi/slo
// ---------------------------------------------------------------------------
__global__ __launch_bounds__(256, 1) void gemm_p4(
    const __nv_bfloat16* __restrict__ Ahi, const __nv_bfloat16* __restrict__ Alo,
    const __nv_bfloat16* __restrict__ Bhi, const __nv_bfloat16* __restrict__ Blo,
    const float* __restrict__ bias, const float* __restrict__ xtime,
    const float* __restrict__ xfreq, float* __restrict__ C,
    __nv_bfloat16* __restrict__ shi, __nv_bfloat16* __restrict__ slo)
{
    extern __shared__ char smem[];
    const int row0 = blockIdx.y * 128;
    const int col0 = blockIdx.x * 128;
    float acc[2][8][4];
    gemm128_core(Ahi + (size_t)row0 * G3, Alo + (size_t)row0 * G3,
                 Bhi + (size_t)col0 * G3, Blo + (size_t)col0 * G3,
                 G3, G3, smem, acc);

    const int lane = threadIdx.x & 31;
    const int wid  = threadIdx.x >> 5;
    const int wm   = wid & 3;
    const int wn   = wid >> 2;
#pragma unroll
    for (int mf = 0; mf < 2; mf++) {
        const int rA = row0 + wm * 32 + mf * 16 + (lane >> 2);
#pragma unroll
        for (int half = 0; half < 2; half++) {
            const int r = rA + half * 8;
#pragma unroll
            for (int nf = 0; nf < 8; nf++) {
                const int cc = col0 + wn * 64 + nf * 8 + (lane & 3) * 2;
                const size_t o = (size_t)r * Dd + cc;
                float2 v;
                v.x = acc[mf][nf][half * 2 + 0] + bias[cc];
                v.y = acc[mf][nf][half * 2 + 1] + bias[cc + 1];
                float2 rt = *reinterpret_cast<const float2*>(xtime + o);
                v.x += rt.x; v.y += rt.y;
                *reinterpret_cast<float2*>(C + o) = v;
                float2 rf = *reinterpret_cast<const float2*>(xfreq + o);
                float t0 = v.x + rf.x;
                float t1 = v.y + rf.y;
                __nv_bfloat16 h0 = __float2bfloat16_rn(t0);
                __nv_bfloat16 h1 = __float2bfloat16_rn(t1);
                *reinterpret_cast<__nv_bfloat162*>(shi + o) = __nv_bfloat162(h0, h1);
                *reinterpret_cast<__nv_bfloat162*>(slo + o) = __nv_bfloat162(
                    __float2bfloat16_rn(t0 - __bfloat162float(h0)),
                    __float2bfloat16_rn(t1 - __bfloat162float(h1)));
            }
        }
    }
}

// ---------------------------------------------------------------------------
// Activation helpers
// ---------------------------------------------------------------------------
__device__ __forceinline__ float sigf(float x) {
    return 1.f / (1.f + __expf(-x));
}
__device__ __forceinline__ float tanhfast(float x) {
    float e2x = __expf(2.f * x);
    return 1.f - 2.f / (e2x + 1.f);
}

// ---------------------------------------------------------------------------
// Gate kernel for tensor-core recurrent steps.
// ---------------------------------------------------------------------------
struct SArgs {
    const float *gh, *gh2;
    const float* gi;
    const float* hprev;
    float* hnext;
    __nv_bfloat16 *hhi, *hlo;
    __nv_bfloat16 *ohi, *olo;
    int outStride, outOff, mtok;
};

__global__ __launch_bounds__(256) void gate_step(SArgs a0, SArgs a1)
{
    const SArgs a = blockIdx.z ? a1 : a0;
    const int idx = blockIdx.x * 256 + threadIdx.x;
    const int s = idx >> 9;
    const int j = idx & 511;

    const float* g0 = a.gh + (size_t)s * G3;
    float ghr = g0[j], ghz = g0[Dd + j], ghn = g0[2*Dd + j];
    if (a.gh2) {
        const float* g1 = a.gh2 + (size_t)s * G3;
        ghr += g1[j]; ghz += g1[Dd + j]; ghn += g1[2*Dd + j];
    }
    const int token = s * Mm + a.mtok;
    const float* gir = a.gi + (size_t)token * G3;

    float r = sigf(gir[j]        + ghr);
    float z = sigf(gir[Dd + j]   + ghz);
    float n = tanhfast(gir[2*Dd + j] + r * ghn);
    float hp = a.hprev[idx];
    float hv = (1.f - z) * n + z * hp;

    a.hnext[idx] = hv;
    __nv_bfloat16 hi = __float2bfloat16_rn(hv);
    __nv_bfloat16 lo = __float2bfloat16_rn(hv - __bfloat162float(hi));
    a.hhi[idx] = hi;
    a.hlo[idx] = lo;
    size_t o = (size_t)token * a.outStride + a.outOff + j;
    a.ohi[o] = hi;
    a.olo[o] = lo;
}

// ---------------------------------------------------------------------------
// Persistent time-GRU scan (fp32 SIMT), 512 threads = 16 warps x 32-k slices.
// Grid (TGROUPS=4, TCOLB=16) = 64 blocks -> leaves ~84 SMs for the freq stream.
// Partials processed in 2 chunks of 20 seqs (smem cap).
// ---------------------------------------------------------------------------
constexpr int TPART = 17;   // padded partial stride (bank-conflict-free)
constexpr int TIME_SMEM = (TSQ * 512 + TCHUNK * 3 * 32 * TPART) * 4; // 212480 B

__global__ __launch_bounds__(512, 1) void gru_time_persist(
    const float* __restrict__ gi, const float* __restrict__ Whh,
    const float* __restrict__ bhh,
    __nv_bfloat16* __restrict__ ohi, __nv_bfloat16* __restrict__ olo,
    float* __restrict__ hb0, float* __restrict__ hb1)
{
    const int grp  = blockIdx.x;   // 0..3
    const int cb   = blockIdx.y;   // 0..15
    const int j0   = cb * 32;
    const int tid  = threadIdx.x;
    const int lane = tid & 31;
    const int w    = tid >> 5;     // 0..15
    const int k0   = w * 32;

    extern __shared__ float sm[];
    float* hs   = sm;                       // [TSQ][512]
    float* part = sm + TSQ * 512;           // [TCHUNK*3*32][TPART]

    float wr[32], wz[32], wn[32];
    {
        const float* Wr = Whh + (size_t)(0 * Dd + j0 + lane) * Dd + k0;
        const float* Wz = Whh + (size_t)(1 * Dd + j0 + lane) * Dd + k0;
        const float* Wn = Whh + (size_t)(2 * Dd + j0 + lane) * Dd + k0;
#pragma unroll
        for (int i = 0; i < 32; i += 4) {
            float4 a = *reinterpret_cast<const float4*>(Wr + i);
            float4 b = *reinterpret_cast<const float4*>(Wz + i);
            float4 c = *reinterpret_cast<const float4*>(Wn + i);
            wr[i] = a.x; wr[i+1] = a.y; wr[i+2] = a.z; wr[i+3] = a.w;
            wz[i] = b.x; wz[i+1] = b.y; wz[i+2] = b.z; wz[i+3] = b.w;
            wn[i] = c.x; wn[i+1] = c.y; wn[i+2] = c.z; wn[i+3] = c.w;
        }
    }

    for (int t = 0; t < Tt; t++) {
        const float* hc = (t & 1) ? hb1 : hb0;
        float*       hn = (t & 1) ? hb0 : hb1;

        for (int i = tid; i < TSQ * 128; i += 512) {
            int s  = i >> 7;
            int k4 = i & 127;
            float4 v = __ldcg(reinterpret_cast<const float4*>(
                hc + (size_t)(grp * TSQ + s) * Dd) + k4);
            *reinterpret_cast<float4*>(hs + s * Dd + k4 * 4) = v;
        }
        __syncthreads();

        for (int c0 = 0; c0 < TSQ; c0 += TCHUNK) {
            for (int ls = 0; ls < TCHUNK; ls++) {
                const int s = c0 + ls;
                float ar = 0.f, az = 0.f, an = 0.f;
                const float* hrow = hs + s * Dd + k0;
#pragma unroll
                for (int i = 0; i < 32; i += 4) {
                    float4 h4 = *reinterpret_cast<const float4*>(hrow + i);
                    ar = fmaf(h4.x, wr[i],   ar); az = fmaf(h4.x, wz[i],   az); an = fmaf(h4.x, wn[i],   an);
                    ar = fmaf(h4.y, wr[i+1], ar); az = fmaf(h4.y, wz[i+1], az); an = fmaf(h4.y, wn[i+1], an);
                    ar = fmaf(h4.z, wr[i+2], ar); az = fmaf(h4.z, wz[i+2], az); an = fmaf(h4.z, wn[i+2], an);
                    ar = fmaf(h4.w, wr[i+3], ar); az = fmaf(h4.w, wz[i+3], az); an = fmaf(h4.w, wn[i+3], an);
                }
                part[((ls * 3 + 0) * 32 + lane) * TPART + w] = ar;
                part[((ls * 3 + 1) * 32 + lane) * TPART + w] = az;
                part[((ls * 3 + 2) * 32 + lane) * TPART + w] = an;
            }
            __syncthreads();

            for (int idx = tid; idx < TCHUNK * 32; idx += 512) {
                int ls = idx >> 5, j = idx & 31;
                int s = c0 + ls;
                float r = 0.f, z = 0.f, n = 0.f;
                const float* pr = part + ((ls * 3 + 0) * 32 + j) * TPART;
                const float* pz = part + ((ls * 3 + 1) * 32 + j) * TPART;
                const float* pn = part + ((ls * 3 + 2) * 32 + j) * TPART;
#pragma unroll
                for (int ww = 0; ww < 16; ww++) { r += pr[ww]; z += pz[ww]; n += pn[ww]; }

                int sg = grp * TSQ + s;
                int b  = sg / Mm;
                int m  = sg - b * Mm;
                size_t token = ((size_t)(b * Tt + t)) * Mm + m;
                const float* gir = gi + token * G3;
                int jc = j0 + j;
                float rr = sigf(gir[jc]        + r + bhh[jc]);
                float zz = sigf(gir[Dd + jc]   + z + bhh[Dd + jc]);
                float nn = tanhfast(gir[2*Dd + jc] + rr * (n + bhh[2*Dd + jc]));
                float hp = hs[s * Dd + jc];
                float hv = (1.f - zz) * nn + zz * hp;
                __stcg(hn + (size_t)sg * Dd + jc, hv);
                __nv_bfloat16 hib = __float2bfloat16_rn(hv);
                ohi[token * G3 + jc] = hib;
                olo[token * G3 + jc] = __float2bfloat16_rn(hv - __bfloat162float(hib));
            }
            __syncthreads();
        }

        __threadfence();
        __syncthreads();
        if (tid == 0) {
            atomicAdd(&g_tbar[grp], 1u);
            unsigned target = (unsigned)(t + 1) * TCOLB;
            while (ld_cg_u32(&g_tbar[grp]) < target) __nanosleep(64);
        }
        __syncthreads();
    }
}

// ---------------------------------------------------------------------------
// Launch
// ---------------------------------------------------------------------------
static void split_launch_s(cudaStream_t st, const float* X, const float* Y,
                           __nv_bfloat16* hi, __nv_bfloat16* lo, size_t n)
{
    int n4 = (int)(n / 4);
    split_bf16_kernel<<<(n4 + 255) / 256, 256, 0, st>>>(X, Y, hi, lo, n4);
}

extern "C" void kernel_launch(void* const* d_in, const int* in_sizes, int n_in,
                              void* d_out_v, int out_size)
{
    const float* x_time = (const float*)d_in[0];
    const float* x_freq = (const float*)d_in[1];
    const float* wt_ih  = (const float*)d_in[2];
    const float* wt_hh  = (const float*)d_in[3];
    const float* bt_ih  = (const float*)d_in[4];
    const float* bt_hh  = (const float*)d_in[5];
    const float* wf_ih  = (const float*)d_in[6];
    const float* wf_hh  = (const float*)d_in[7];
    const float* bf_ih  = (const float*)d_in[8];
    const float* bf_hh  = (const float*)d_in[9];
    const float* wb_ih  = (const float*)d_in[10];
    const float* wb_hh  = (const float*)d_in[11];
    const float* bb_ih  = (const float*)d_in[12];
    const float* bb_hh  = (const float*)d_in[13];
    const float* ws_ih  = (const float*)d_in[14];
    const float* ws_hh  = (const float*)d_in[15];
    const float* bs_ih  = (const float*)d_in[16];
    const float* bs_hh  = (const float*)d_in[17];
    const float* W_time = (const float*)d_in[18];
    const float* b_time = (const float*)d_in[19];
    const float* W_freq = (const float*)d_in[20];
    const float* b_freq = (const float*)d_in[21];
    float* dout = (float*)d_out_v;

    float *gi_t, *gi_f, *gi_b, *gi_s, *h0, *h1, *h2, *h3, *ht0, *ht1, *gh;
    unsigned* tbar;
    __nv_bfloat16 *ahi, *alo, *bhi, *blo, *whi, *wlo, *hbhi, *hblo;
    cudaGetSymbolAddress((void**)&gi_t, g_gi_t);
    cudaGetSymbolAddress((void**)&gi_f, g_gi_f);
    cudaGetSymbolAddress((void**)&gi_b, g_gi_b);
    cudaGetSymbolAddress((void**)&gi_s, g_gi_s);
    cudaGetSymbolAddress((void**)&h0,   g_h0);
    cudaGetSymbolAddress((void**)&h1,   g_h1);
    cudaGetSymbolAddress((void**)&h2,   g_h2);
    cudaGetSymbolAddress((void**)&h3,   g_h3);
    cudaGetSymbolAddress((void**)&ht0,  g_ht0);
    cudaGetSymbolAddress((void**)&ht1,  g_ht1);
    cudaGetSymbolAddress((void**)&gh,   g_gh);
    cudaGetSymbolAddress((void**)&tbar, g_tbar);
    cudaGetSymbolAddress((void**)&ahi,  g_ahi);
    cudaGetSymbolAddress((void**)&alo,  g_alo);
    cudaGetSymbolAddress((void**)&bhi,  g_bhi);
    cudaGetSymbolAddress((void**)&blo,  g_blo);
    cudaGetSymbolAddress((void**)&whi,  g_whi);
    cudaGetSymbolAddress((void**)&wlo,  g_wlo);
    cudaGetSymbolAddress((void**)&hbhi, g_hbhi);
    cudaGetSymbolAddress((void**)&hblo, g_hblo);

    // one-time side stream + fork/join events (host resources; same work/call)
    static cudaStream_t sSide = nullptr;
    static cudaEvent_t evFork = nullptr, evJoin = nullptr;
    if (!sSide) {
        cudaStreamCreateWithFlags(&sSide, cudaStreamNonBlocking);
        cudaEventCreateWithFlags(&evFork, cudaEventDisableTiming);
        cudaEventCreateWithFlags(&evJoin, cudaEventDisableTiming);
    }
    cudaStream_t s0 = 0;

    const dim3 blk(256);
    cudaFuncSetAttribute(gru_time_persist,
                         cudaFuncAttributeMaxDynamicSharedMemorySize, TIME_SMEM);
    cudaFuncSetAttribute(gemm_bf3,
                         cudaFuncAttributeMaxDynamicSharedMemorySize, GEMM_SMEM);
    cudaFuncSetAttribute(gemm_p4,
                         cudaFuncAttributeMaxDynamicSharedMemorySize, GEMM_SMEM);

    __nv_bfloat16 *wtH = whi + 0*WSLOT, *wtL = wlo + 0*WSLOT;   // wt_ih
    __nv_bfloat16 *wfH = whi + 1*WSLOT, *wfL = wlo + 1*WSLOT;   // wf_ih
    __nv_bfloat16 *wbH = whi + 2*WSLOT, *wbL = wlo + 2*WSLOT;   // wb_ih
    __nv_bfloat16 *wsH = whi + 3*WSLOT, *wsL = wlo + 3*WSLOT;   // ws_ih
    __nv_bfloat16 *wTH = whi + 4*WSLOT, *wTL = wlo + 4*WSLOT;   // W_time
    __nv_bfloat16 *wFH = whi + 5*WSLOT, *wFL = wlo + 5*WSLOT;   // W_freq
    __nv_bfloat16 *wfhH = whi + 6*WSLOT, *wfhL = wlo + 6*WSLOT; // wf_hh
    __nv_bfloat16 *wbhH = whi + 7*WSLOT, *wbhL = wlo + 7*WSLOT; // wb_hh
    __nv_bfloat16 *wshH = whi + 8*WSLOT, *wshL = wlo + 8*WSLOT; // ws_hh

    const size_t HB = (size_t)NSEQ_F * Dd;

    // ---- Phase 0: splits (main stream). x_time split -> bhi/blo ----
    split_launch_s(s0, wt_ih,  nullptr, wtH, wtL, (size_t)G3 * Dd);
    split_launch_s(s0, wf_ih,  nullptr, wfH, wfL, (size_t)G3 * Dd);
    split_launch_s(s0, wb_ih,  nullptr, wbH, wbL, (size_t)G3 * Dd);
    split_launch_s(s0, ws_ih,  nullptr, wsH, wsL, (size_t)G3 * Dd);
    split_launch_s(s0, W_time, nullptr, wTH, wTL, (size_t)Dd * G3);
    split_launch_s(s0, W_freq, nullptr, wFH, wFL, (size_t)Dd * Dd);
    split_launch_s(s0, wf_hh,  nullptr, wfhH, wfhL, (size_t)G3 * Dd);
    split_launch_s(s0, wb_hh,  nullptr, wbhH, wbhL, (size_t)G3 * Dd);
    split_launch_s(s0, ws_hh,  nullptr, wshH, wshL, (size_t)G3 * Dd);
    split_launch_s(s0, x_time, nullptr, bhi, blo, (size_t)NT * Dd);

    // ---- Phase 1a: gi_t GEMM (reads bhi/blo) + time-scan memsets (main) ----
    {
        GArgs a{bhi, blo, wtH, wtL, bt_ih, nullptr, gi_t};
        gemm_bf3<<<dim3(G3 / 128, NT / 128, 1), blk, GEMM_SMEM>>>(a, a, Dd, Dd, G3);
    }
    cudaMemsetAsync(ht0, 0, (size_t)NSEQ_T * Dd * sizeof(float));
    cudaMemsetAsync(ht1, 0, (size_t)NSEQ_T * Dd * sizeof(float));
    cudaMemsetAsync(tbar, 0, TGROUPS * sizeof(unsigned));

    // ---- FORK: time scan on side stream (64 blocks -> ~84 SMs left free) ----
    cudaEventRecord(evFork, s0);
    cudaStreamWaitEvent(sSide, evFork, 0);
    gru_time_persist<<<dim3(TGROUPS, TCOLB), dim3(512), TIME_SMEM, sSide>>>(
        gi_t, wt_hh, bt_hh, ahi, alo, ht0, ht1);
    cudaEventRecord(evJoin, sSide);

    // ---- Phase 1b: gi_f / gi_b GEMMs (main; read bhi/blo) ----
    {
        dim3 grid(G3 / 128, NT / 128, 1);
        GArgs b{bhi, blo, wfH, wfL, bf_ih, nullptr, gi_f};
        gemm_bf3<<<grid, blk, GEMM_SMEM>>>(b, b, Dd, Dd, G3);
        GArgs c{bhi, blo, wbH, wbL, bb_ih, nullptr, gi_b};
        gemm_bf3<<<grid, blk, GEMM_SMEM>>>(c, c, Dd, Dd, G3);
    }

    // ---- Phase 3: bidirectional freq GRU scan (main) ----
    cudaMemsetAsync(h0, 0, HB * sizeof(float));
    cudaMemsetAsync(h2, 0, HB * sizeof(float));
    cudaMemsetAsync(hbhi + 0 * HB, 0, HB * sizeof(__nv_bfloat16));
    cudaMemsetAsync(hblo + 0 * HB, 0, HB * sizeof(__nv_bfloat16));
    cudaMemsetAsync(hbhi + 2 * HB, 0, HB * sizeof(__nv_bfloat16));
    cudaMemsetAsync(hblo + 2 * HB, 0, HB * sizeof(__nv_bfloat16));
    for (int s = 0; s < Mm; s++) {
        const int pp = s & 1;
        GArgs gf{hbhi + (0 + pp) * HB, hblo + (0 + pp) * HB,
                 wfhH, wfhL, bf_hh, nullptr, gh};
        GArgs gb{hbhi + (2 + pp) * HB, hblo + (2 + pp) * HB,
                 wbhH, wbhL, bb_hh, nullptr, gh + (size_t)NSEQ_F * G3};
        gemm_bf3<<<dim3(G3 / 128, NSEQ_F / 128, 2), blk, GEMM_SMEM>>>(
            gf, gb, Dd, Dd, G3);

        float* hpF = pp ? h1 : h0;  float* hnF = pp ? h0 : h1;
        float* hpB = pp ? h3 : h2;  float* hnB = pp ? h2 : h3;
        SArgs sf{gh, nullptr, gi_f, hpF, hnF,
                 hbhi + (0 + (pp ^ 1)) * HB, hblo + (0 + (pp ^ 1)) * HB,
                 ahi, alo, G3, Dd, s};
        SArgs sb{gh + (size_t)NSEQ_F * G3, nullptr, gi_b, hpB, hnB,
                 hbhi + (2 + (pp ^ 1)) * HB, hblo + (2 + (pp ^ 1)) * HB,
                 ahi, alo, G3, 2 * Dd, Mm - 1 - s};
        gate_step<<<dim3((int)(HB / 256), 1, 2), blk>>>(sf, sb);
    }

    // ---- JOIN: wait for the time scan before phase 4 ----
    cudaStreamWaitEvent(s0, evJoin, 0);

    // ---- Phase 4: fused xt GEMM + split(xt + x_freq) -> bhi/blo ----
    gemm_p4<<<dim3(Dd / 128, NT / 128), blk, GEMM_SMEM>>>(
        ahi, alo, wTH, wTL, b_time, x_time, x_freq, dout, bhi, blo);

    // ---- Phase 5: gi_s = (xt + x_freq) @ ws_ih^T + bs_ih ----
    {
        GArgs a{bhi, blo, wsH, wsL, bs_ih, nullptr, gi_s};
        gemm_bf3<<<dim3(G3 / 128, NT / 128, 1), blk, GEMM_SMEM>>>(a, a, Dd, Dd, G3);
    }

    // ---- Phase 6: stack GRU scan (per-step tensor cores, split-K=2) ----
    cudaMemsetAsync(h0, 0, HB * sizeof(float));
    cudaMemsetAsync(hbhi + 0 * HB, 0, HB * sizeof(__nv_bfloat16));
    cudaMemsetAsync(hblo + 0 * HB, 0, HB * sizeof(__nv_bfloat16));
    for (int s = 0; s < Mm; s++) {
        const int pp = s & 1;
        GArgs k0{hbhi + pp * HB, hblo + pp * HB,
                 wshH, wshL, bs_hh, nullptr, gh};
        GArgs k1{hbhi + pp * HB + 256, hblo + pp * HB + 256,
                 wshH + 256, wshL + 256, nullptr, nullptr,
                 gh + (size_t)NSEQ_F * G3};
        gemm_bf3<<<dim3(G3 / 128, NSEQ_F / 128, 2), blk, GEMM_SMEM>>>(
            k0, k1, 256, Dd, G3);

        float* hp = pp ? h1 : h0;  float* hn = pp ? h0 : h1;
        SArgs sa{gh, gh + (size_t)NSEQ_F * G3, gi_s, hp, hn,
                 hbhi + (pp ^ 1) * HB, hblo + (pp ^ 1) * HB,
                 bhi, blo, Dd, 0, s};
        gate_step<<<dim3((int)(HB / 256), 1, 1), blk>>>(sa, sa);
    }

    // ---- Phase 7: xf = xs @ W_freq^T + b_freq + x_freq ----
    {
        GArgs a{bhi, blo, wFH, wFL, b_freq, x_freq, dout + (size_t)NT * Dd};
        gemm_bf3<<<dim3(Dd / 128, NT / 128, 1), blk, GEMM_SMEM>>>(a, a, Dd, Dd, Dd);
    }
}

// round 16
// speedup vs baseline: 1.7289x; 1.2292x over previous
#include <cuda_runtime.h>
#include <cuda_fp16.h>
#include <cstdint>

// ---------------------------------------------------------------------------
// Problem constants
// ---------------------------------------------------------------------------
constexpr int Bb = 2, Tt = 256, Mm = 80, Dd = 512;
constexpr int NT = Bb * Tt * Mm;   // 40960 tokens
constexpr int G3 = 3 * Dd;         // 1536
constexpr int NSEQ_T = Bb * Mm;    // 160
constexpr int NSEQ_F = Bb * Tt;    // 512

constexpr int TGROUPS = 4;
constexpr int TSQ = NSEQ_T / TGROUPS;  // 40
constexpr int TCHUNK = 20;
constexpr int TCOLB = 16;

// ---------------------------------------------------------------------------
// Static device scratch
// ---------------------------------------------------------------------------
__device__ float g_gi_t[(size_t)NT * G3];
__device__ float g_gi_f[(size_t)NT * G3];
__device__ float g_gi_b[(size_t)NT * G3];
__device__ float g_gi_s[(size_t)NT * G3];
__device__ float g_h0[NSEQ_F * Dd];
__device__ float g_h1[NSEQ_F * Dd];
__device__ float g_h2[NSEQ_F * Dd];
__device__ float g_h3[NSEQ_F * Dd];
__device__ float g_ht0[NSEQ_T * Dd];
__device__ float g_ht1[NSEQ_T * Dd];
__device__ float g_gh[2 * (size_t)NSEQ_F * G3];
__device__ unsigned g_tbar[TGROUPS];

// fp16 split buffers (activations: hi + lo)
__device__ __half g_ahi[(size_t)NT * G3];   // xcat split ONLY (scan outputs)
__device__ __half g_alo[(size_t)NT * G3];
__device__ __half g_bhi[(size_t)NT * Dd];   // x_time split -> later (xt+x_freq)/xs
__device__ __half g_blo[(size_t)NT * Dd];
// fp16 hidden-state ping-pong: [dir(2)*pp(2)][NSEQ_F*Dd]
__device__ __half g_hbhi[4 * NSEQ_F * Dd];
__device__ __half g_hblo[4 * NSEQ_F * Dd];
// weights: fp16 hi only (2-product scheme), 9 slots of 1536*512
constexpr size_t WSLOT = 786432;
__device__ __half g_whi[9 * WSLOT];

// ---------------------------------------------------------------------------
// PTX helpers
// ---------------------------------------------------------------------------
__device__ __forceinline__ uint32_t smem_to_u32(const void* p) {
    uint32_t a;
    asm("{ .reg .u64 t; cvta.to.shared.u64 t, %1; cvt.u32.u64 %0, t; }"
        : "=r"(a) : "l"(p));
    return a;
}
#define CP_ASYNC16(dst, src) \
    asm volatile("cp.async.cg.shared.global [%0], [%1], 16;" \
        :: "r"((uint32_t)(dst)), "l"(src) : "memory")
#define CP_COMMIT() asm volatile("cp.async.commit_group;" ::: "memory")
#define CP_WAIT(n)  asm volatile("cp.async.wait_group %0;" :: "n"(n) : "memory")

__device__ __forceinline__ void ldsm4(uint32_t* r, uint32_t addr) {
    asm volatile("ldmatrix.sync.aligned.m8n8.x4.shared.b16 {%0,%1,%2,%3}, [%4];"
        : "=r"(r[0]), "=r"(r[1]), "=r"(r[2]), "=r"(r[3]) : "r"(addr));
}
__device__ __forceinline__ void mma16816(float* c, const uint32_t* a, const uint32_t* b) {
    asm volatile(
        "mma.sync.aligned.m16n8k16.row.col.f32.f16.f16.f32 "
        "{%0,%1,%2,%3}, {%4,%5,%6,%7}, {%8,%9}, {%0,%1,%2,%3};"
        : "+f"(c[0]), "+f"(c[1]), "+f"(c[2]), "+f"(c[3])
        : "r"(a[0]), "r"(a[1]), "r"(a[2]), "r"(a[3]), "r"(b[0]), "r"(b[1]));
}
__device__ __forceinline__ unsigned ld_cg_u32(const unsigned* p) {
    unsigned v;
    asm volatile("ld.global.cg.u32 %0, [%1];" : "=r"(v) : "l"(p));
    return v;
}

// ---------------------------------------------------------------------------
// fp32 -> fp16 (hi, optional lo) split; optionally X+Y first
// ---------------------------------------------------------------------------
__global__ void split_fp16_kernel(
    const float* __restrict__ X, const float* __restrict__ Y,
    __half* __restrict__ hi, __half* __restrict__ lo, int n4)
{
    int i = blockIdx.x * blockDim.x + threadIdx.x;
    if (i >= n4) return;
    float4 v = reinterpret_cast<const float4*>(X)[i];
    if (Y) {
        float4 y = reinterpret_cast<const float4*>(Y)[i];
        v.x += y.x; v.y += y.y; v.z += y.z; v.w += y.w;
    }
    __half h0 = __float2half_rn(v.x);
    __half h1 = __float2half_rn(v.y);
    __half h2 = __float2half_rn(v.z);
    __half h3 = __float2half_rn(v.w);
    reinterpret_cast<__half2*>(hi)[2*i]   = __half2(h0, h1);
    reinterpret_cast<__half2*>(hi)[2*i+1] = __half2(h2, h3);
    if (lo) {
        __half l0 = __float2half_rn(v.x - __half2float(h0));
        __half l1 = __float2half_rn(v.y - __half2float(h1));
        __half l2 = __float2half_rn(v.z - __half2float(h2));
        __half l3 = __float2half_rn(v.w - __half2float(h3));
        reinterpret_cast<__half2*>(lo)[2*i]   = __half2(l0, l1);
        reinterpret_cast<__half2*>(lo)[2*i+1] = __half2(l2, l3);
    }
}

// ---------------------------------------------------------------------------
// mma.sync 128x128 tile core (2-product fp16 split: Ahi*B + Alo*B),
// BK=32, 3-stage cp.async, 3 smem tiles per stage.
// ---------------------------------------------------------------------------
constexpr int GSTRIDE = 40;
constexpr int TILE_B  = 128 * GSTRIDE * 2;     // 10240 B
constexpr int STAGE_B = 3 * TILE_B;            // 30720 B
constexpr int NSTAGE  = 3;
constexpr int GEMM_SMEM = NSTAGE * STAGE_B;    // 92160 B -> 2 blocks/SM

__device__ __forceinline__ void gemm128_core(
    const __half* __restrict__ Ahi, const __half* __restrict__ Alo,
    const __half* __restrict__ Bh,
    int ld, int K, char* smem, float acc[2][8][4])
{
    const uint32_t sb = smem_to_u32(smem);
    const int tid  = threadIdx.x;
    const int lane = tid & 31;
    const int wid  = tid >> 5;
    const int wm   = wid & 3;
    const int wn   = wid >> 2;

    const __half* srcs[3] = {Ahi, Alo, Bh};

    auto stage_load = [&](int c, int buf) {
        const int k0 = c * 32;
        const uint32_t base = sb + buf * STAGE_B;
#pragma unroll
        for (int t4 = 0; t4 < 3; t4++) {
#pragma unroll
            for (int i = 0; i < 2; i++) {
                int idx = tid + i * 256;
                int r = idx >> 2;
                int seg = idx & 3;
                uint32_t dst = base + t4 * TILE_B + r * (GSTRIDE * 2) + seg * 16;
                const void* gp = srcs[t4] + (size_t)r * ld + k0 + seg * 8;
                CP_ASYNC16(dst, gp);
            }
        }
        CP_COMMIT();
    };

#pragma unroll
    for (int mf = 0; mf < 2; mf++)
#pragma unroll
        for (int nf = 0; nf < 8; nf++)
#pragma unroll
            for (int q = 0; q < 4; q++) acc[mf][nf][q] = 0.f;

    const int NC = K / 32;
    stage_load(0, 0);
    stage_load(1, 1);

    const uint32_t a_off =
        ((wm * 32 + (lane & 15)) * GSTRIDE + ((lane >> 4) * 8)) * 2;
    const uint32_t b_row = wn * 64 + (lane & 7) + ((lane >> 4) & 1) * 8;
    const uint32_t b_off = (b_row * GSTRIDE + (((lane >> 3) & 1) * 8)) * 2;

    int nb = 2 % NSTAGE;
    for (int c = 0; c < NC; c++) {
        if (c + 2 < NC) {
            stage_load(c + 2, nb);
            nb = (nb + 1) % NSTAGE;
            CP_WAIT(2);
        } else if (c + 1 < NC) {
            CP_WAIT(1);
        } else {
            CP_WAIT(0);
        }
        __syncthreads();

        const uint32_t st = sb + (c % NSTAGE) * STAGE_B;

#pragma unroll
        for (int kk = 0; kk < 2; kk++) {
            const uint32_t kb = kk * 32;
            uint32_t ahi[2][4], alo[2][4];
#pragma unroll
            for (int mf = 0; mf < 2; mf++) {
                ldsm4(ahi[mf], st + 0 * TILE_B + a_off + mf * 16 * (GSTRIDE * 2) + kb);
                ldsm4(alo[mf], st + 1 * TILE_B + a_off + mf * 16 * (GSTRIDE * 2) + kb);
            }
            uint32_t bh[8][2];
#pragma unroll
            for (int p = 0; p < 4; p++) {
                uint32_t r4[4];
                ldsm4(r4, st + 2 * TILE_B + b_off + p * 16 * (GSTRIDE * 2) + kb);
                bh[2*p][0] = r4[0]; bh[2*p][1] = r4[1];
                bh[2*p+1][0] = r4[2]; bh[2*p+1][1] = r4[3];
            }
#pragma unroll
            for (int mf = 0; mf < 2; mf++)
#pragma unroll
                for (int nf = 0; nf < 8; nf++) {
                    mma16816(acc[mf][nf], ahi[mf], bh[nf]);
                    mma16816(acc[mf][nf], alo[mf], bh[nf]);
                }
        }
        __syncthreads();
    }
}

__device__ __forceinline__ void epi_store(
    float acc[2][8][4], float* __restrict__ C, const float* __restrict__ bias,
    const float* __restrict__ res, int row0, int col0, int N)
{
    const int lane = threadIdx.x & 31;
    const int wid  = threadIdx.x >> 5;
    const int wm   = wid & 3;
    const int wn   = wid >> 2;
#pragma unroll
    for (int mf = 0; mf < 2; mf++) {
        const int rA = row0 + wm * 32 + mf * 16 + (lane >> 2);
        const int rB = rA + 8;
#pragma unroll
        for (int nf = 0; nf < 8; nf++) {
            const int cc = col0 + wn * 64 + nf * 8 + (lane & 3) * 2;
            float b0 = bias ? bias[cc] : 0.f;
            float b1 = bias ? bias[cc + 1] : 0.f;
            float2 v0, v1;
            v0.x = acc[mf][nf][0] + b0;
            v0.y = acc[mf][nf][1] + b1;
            v1.x = acc[mf][nf][2] + b0;
            v1.y = acc[mf][nf][3] + b1;
            if (res) {
                float2 r0 = *reinterpret_cast<const float2*>(res + (size_t)rA * N + cc);
                float2 r1 = *reinterpret_cast<const float2*>(res + (size_t)rB * N + cc);
                v0.x += r0.x; v0.y += r0.y; v1.x += r1.x; v1.y += r1.y;
            }
            *reinterpret_cast<float2*>(C + (size_t)rA * N + cc) = v0;
            *reinterpret_cast<float2*>(C + (size_t)rB * N + cc) = v1;
        }
    }
}

// ---------------------------------------------------------------------------
// Standalone dual-arg GEMM (A split hi/lo, B fp16)
// ---------------------------------------------------------------------------
struct GArgs {
    const __half *Ahi, *Alo, *Bh;
    const float *bias, *res;
    float *C;
};

__global__ __launch_bounds__(256) void gemm_f16(GArgs g0, GArgs g1,
                                                 int K, int ld, int N)
{
    const GArgs g = blockIdx.z ? g1 : g0;
    extern __shared__ char smem[];
    const int row0 = blockIdx.y * 128;
    const int col0 = blockIdx.x * 128;
    float acc[2][8][4];
    gemm128_core(g.Ahi + (size_t)row0 * ld, g.Alo + (size_t)row0 * ld,
                 g.Bh + (size_t)col0 * ld, ld, K, smem, acc);
    epi_store(acc, g.C, g.bias, g.res, row0, col0, N);
}

// ---------------------------------------------------------------------------
// Phase-4 fused GEMM: xt -> dout, split(xt + x_freq) -> shi/slo
// ---------------------------------------------------------------------------
__global__ __launch_bounds__(256) void gemm_p4(
    const __half* __restrict__ Ahi, const __half* __restrict__ Alo,
    const __half* __restrict__ Bh,
    const float* __restrict__ bias, const float* __restrict__ xtime,
    const float* __restrict__ xfreq, float* __restrict__ C,
    __half* __restrict__ shi, __half* __restrict__ slo)
{
    extern __shared__ char smem[];
    const int row0 = blockIdx.y * 128;
    const int col0 = blockIdx.x * 128;
    float acc[2][8][4];
    gemm128_core(Ahi + (size_t)row0 * G3, Alo + (size_t)row0 * G3,
                 Bh + (size_t)col0 * G3, G3, G3, smem, acc);

    const int lane = threadIdx.x & 31;
    const int wid  = threadIdx.x >> 5;
    const int wm   = wid & 3;
    const int wn   = wid >> 2;
#pragma unroll
    for (int mf = 0; mf < 2; mf++) {
        const int rA = row0 + wm * 32 + mf * 16 + (lane >> 2);
#pragma unroll
        for (int half = 0; half < 2; half++) {
            const int r = rA + half * 8;
#pragma unroll
            for (int nf = 0; nf < 8; nf++) {
                const int cc = col0 + wn * 64 + nf * 8 + (lane & 3) * 2;
                const size_t o = (size_t)r * Dd + cc;
                float2 v;
                v.x = acc[mf][nf][half * 2 + 0] + bias[cc];
                v.y = acc[mf][nf][half * 2 + 1] + bias[cc + 1];
                float2 rt = *reinterpret_cast<const float2*>(xtime + o);
                v.x += rt.x; v.y += rt.y;
                *reinterpret_cast<float2*>(C + o) = v;
                float2 rf = *reinterpret_cast<const float2*>(xfreq + o);
                float t0 = v.x + rf.x;
                float t1 = v.y + rf.y;
                __half h0 = __float2half_rn(t0);
                __half h1 = __float2half_rn(t1);
                *reinterpret_cast<__half2*>(shi + o) = __half2(h0, h1);
                *reinterpret_cast<__half2*>(slo + o) = __half2(
                    __float2half_rn(t0 - __half2float(h0)),
                    __float2half_rn(t1 - __half2float(h1)));
            }
        }
    }
}

// ---------------------------------------------------------------------------
// Activation helpers
// ---------------------------------------------------------------------------
__device__ __forceinline__ float sigf(float x) {
    return 1.f / (1.f + __expf(-x));
}
__device__ __forceinline__ float tanhfast(float x) {
    float e2x = __expf(2.f * x);
    return 1.f - 2.f / (e2x + 1.f);
}

// ---------------------------------------------------------------------------
// Gate kernel for tensor-core recurrent steps.
// ---------------------------------------------------------------------------
struct SArgs {
    const float *gh, *gh2;
    const float* gi;
    const float* hprev;
    float* hnext;
    __half *hhi, *hlo;
    __half *ohi, *olo;
    int outStride, outOff, mtok;
};

__global__ __launch_bounds__(256) void gate_step(SArgs a0, SArgs a1)
{
    const SArgs a = blockIdx.z ? a1 : a0;
    const int idx = blockIdx.x * 256 + threadIdx.x;
    const int s = idx >> 9;
    const int j = idx & 511;

    const float* g0 = a.gh + (size_t)s * G3;
    float ghr = g0[j], ghz = g0[Dd + j], ghn = g0[2*Dd + j];
    if (a.gh2) {
        const float* g1 = a.gh2 + (size_t)s * G3;
        ghr += g1[j]; ghz += g1[Dd + j]; ghn += g1[2*Dd + j];
    }
    const int token = s * Mm + a.mtok;
    const float* gir = a.gi + (size_t)token * G3;

    float r = sigf(gir[j]        + ghr);
    float z = sigf(gir[Dd + j]   + ghz);
    float n = tanhfast(gir[2*Dd + j] + r * ghn);
    float hp = a.hprev[idx];
    float hv = (1.f - z) * n + z * hp;

    a.hnext[idx] = hv;
    __half hi = __float2half_rn(hv);
    __half lo = __float2half_rn(hv - __half2float(hi));
    a.hhi[idx] = hi;
    a.hlo[idx] = lo;
    size_t o = (size_t)token * a.outStride + a.outOff + j;
    a.ohi[o] = hi;
    a.olo[o] = lo;
}

// ---------------------------------------------------------------------------
// Persistent time-GRU scan (fp32 SIMT), 512 threads, grid (4, 16).
// ---------------------------------------------------------------------------
constexpr int TPART = 17;
constexpr int TIME_SMEM = (TSQ * 512 + TCHUNK * 3 * 32 * TPART) * 4; // 212480 B

__global__ __launch_bounds__(512, 1) void gru_time_persist(
    const float* __restrict__ gi, const float* __restrict__ Whh,
    const float* __restrict__ bhh,
    __half* __restrict__ ohi, __half* __restrict__ olo,
    float* __restrict__ hb0, float* __restrict__ hb1)
{
    const int grp  = blockIdx.x;
    const int cb   = blockIdx.y;
    const int j0   = cb * 32;
    const int tid  = threadIdx.x;
    const int lane = tid & 31;
    const int w    = tid >> 5;
    const int k0   = w * 32;

    extern __shared__ float sm[];
    float* hs   = sm;
    float* part = sm + TSQ * 512;

    float wr[32], wz[32], wn[32];
    {
        const float* Wr = Whh + (size_t)(0 * Dd + j0 + lane) * Dd + k0;
        const float* Wz = Whh + (size_t)(1 * Dd + j0 + lane) * Dd + k0;
        const float* Wn = Whh + (size_t)(2 * Dd + j0 + lane) * Dd + k0;
#pragma unroll
        for (int i = 0; i < 32; i += 4) {
            float4 a = *reinterpret_cast<const float4*>(Wr + i);
            float4 b = *reinterpret_cast<const float4*>(Wz + i);
            float4 c = *reinterpret_cast<const float4*>(Wn + i);
            wr[i] = a.x; wr[i+1] = a.y; wr[i+2] = a.z; wr[i+3] = a.w;
            wz[i] = b.x; wz[i+1] = b.y; wz[i+2] = b.z; wz[i+3] = b.w;
            wn[i] = c.x; wn[i+1] = c.y; wn[i+2] = c.z; wn[i+3] = c.w;
        }
    }

    for (int t = 0; t < Tt; t++) {
        const float* hc = (t & 1) ? hb1 : hb0;
        float*       hn = (t & 1) ? hb0 : hb1;

        for (int i = tid; i < TSQ * 128; i += 512) {
            int s  = i >> 7;
            int k4 = i & 127;
            float4 v = __ldcg(reinterpret_cast<const float4*>(
                hc + (size_t)(grp * TSQ + s) * Dd) + k4);
            *reinterpret_cast<float4*>(hs + s * Dd + k4 * 4) = v;
        }
        __syncthreads();

        for (int c0 = 0; c0 < TSQ; c0 += TCHUNK) {
            for (int ls = 0; ls < TCHUNK; ls++) {
                const int s = c0 + ls;
                float ar = 0.f, az = 0.f, an = 0.f;
                const float* hrow = hs + s * Dd + k0;
#pragma unroll
                for (int i = 0; i < 32; i += 4) {
                    float4 h4 = *reinterpret_cast<const float4*>(hrow + i);
                    ar = fmaf(h4.x, wr[i],   ar); az = fmaf(h4.x, wz[i],   az); an = fmaf(h4.x, wn[i],   an);
                    ar = fmaf(h4.y, wr[i+1], ar); az = fmaf(h4.y, wz[i+1], az); an = fmaf(h4.y, wn[i+1], an);
                    ar = fmaf(h4.z, wr[i+2], ar); az = fmaf(h4.z, wz[i+2], az); an = fmaf(h4.z, wn[i+2], an);
                    ar = fmaf(h4.w, wr[i+3], ar); az = fmaf(h4.w, wz[i+3], az); an = fmaf(h4.w, wn[i+3], an);
                }
                part[((ls * 3 + 0) * 32 + lane) * TPART + w] = ar;
                part[((ls * 3 + 1) * 32 + lane) * TPART + w] = az;
                part[((ls * 3 + 2) * 32 + lane) * TPART + w] = an;
            }
            __syncthreads();

            for (int idx = tid; idx < TCHUNK * 32; idx += 512) {
                int ls = idx >> 5, j = idx & 31;
                int s = c0 + ls;
                float r = 0.f, z = 0.f, n = 0.f;
                const float* pr = part + ((ls * 3 + 0) * 32 + j) * TPART;
                const float* pz = part + ((ls * 3 + 1) * 32 + j) * TPART;
                const float* pn = part + ((ls * 3 + 2) * 32 + j) * TPART;
#pragma unroll
                for (int ww = 0; ww < 16; ww++) { r += pr[ww]; z += pz[ww]; n += pn[ww]; }

                int sg = grp * TSQ + s;
                int b  = sg / Mm;
                int m  = sg - b * Mm;
                size_t token = ((size_t)(b * Tt + t)) * Mm + m;
                const float* gir = gi + token * G3;
                int jc = j0 + j;
                float rr = sigf(gir[jc]        + r + bhh[jc]);
                float zz = sigf(gir[Dd + jc]   + z + bhh[Dd + jc]);
                float nn = tanhfast(gir[2*Dd + jc] + rr * (n + bhh[2*Dd + jc]));
                float hp = hs[s * Dd + jc];
                float hv = (1.f - zz) * nn + zz * hp;
                __stcg(hn + (size_t)sg * Dd + jc, hv);
                __half hib = __float2half_rn(hv);
                ohi[token * G3 + jc] = hib;
                olo[token * G3 + jc] = __float2half_rn(hv - __half2float(hib));
            }
            __syncthreads();
        }

        __threadfence();
        __syncthreads();
        if (tid == 0) {
            atomicAdd(&g_tbar[grp], 1u);
            unsigned target = (unsigned)(t + 1) * TCOLB;
            while (ld_cg_u32(&g_tbar[grp]) < target) __nanosleep(64);
        }
        __syncthreads();
    }
}

// ---------------------------------------------------------------------------
// Launch
// ---------------------------------------------------------------------------
static void split_launch_s(cudaStream_t st, const float* X, const float* Y,
                           __half* hi, __half* lo, size_t n)
{
    int n4 = (int)(n / 4);
    split_fp16_kernel<<<(n4 + 255) / 256, 256, 0, st>>>(X, Y, hi, lo, n4);
}

extern "C" void kernel_launch(void* const* d_in, const int* in_sizes, int n_in,
                              void* d_out_v, int out_size)
{
    const float* x_time = (const float*)d_in[0];
    const float* x_freq = (const float*)d_in[1];
    const float* wt_ih  = (const float*)d_in[2];
    const float* wt_hh  = (const float*)d_in[3];
    const float* bt_ih  = (const float*)d_in[4];
    const float* bt_hh  = (const float*)d_in[5];
    const float* wf_ih  = (const float*)d_in[6];
    const float* wf_hh  = (const float*)d_in[7];
    const float* bf_ih  = (const float*)d_in[8];
    const float* bf_hh  = (const float*)d_in[9];
    const float* wb_ih  = (const float*)d_in[10];
    const float* wb_hh  = (const float*)d_in[11];
    const float* bb_ih  = (const float*)d_in[12];
    const float* bb_hh  = (const float*)d_in[13];
    const float* ws_ih  = (const float*)d_in[14];
    const float* ws_hh  = (const float*)d_in[15];
    const float* bs_ih  = (const float*)d_in[16];
    const float* bs_hh  = (const float*)d_in[17];
    const float* W_time = (const float*)d_in[18];
    const float* b_time = (const float*)d_in[19];
    const float* W_freq = (const float*)d_in[20];
    const float* b_freq = (const float*)d_in[21];
    float* dout = (float*)d_out_v;

    float *gi_t, *gi_f, *gi_b, *gi_s, *h0, *h1, *h2, *h3, *ht0, *ht1, *gh;
    unsigned* tbar;
    __half *ahi, *alo, *bhi, *blo, *whi, *hbhi, *hblo;
    cudaGetSymbolAddress((void**)&gi_t, g_gi_t);
    cudaGetSymbolAddress((void**)&gi_f, g_gi_f);
    cudaGetSymbolAddress((void**)&gi_b, g_gi_b);
    cudaGetSymbolAddress((void**)&gi_s, g_gi_s);
    cudaGetSymbolAddress((void**)&h0,   g_h0);
    cudaGetSymbolAddress((void**)&h1,   g_h1);
    cudaGetSymbolAddress((void**)&h2,   g_h2);
    cudaGetSymbolAddress((void**)&h3,   g_h3);
    cudaGetSymbolAddress((void**)&ht0,  g_ht0);
    cudaGetSymbolAddress((void**)&ht1,  g_ht1);
    cudaGetSymbolAddress((void**)&gh,   g_gh);
    cudaGetSymbolAddress((void**)&tbar, g_tbar);
    cudaGetSymbolAddress((void**)&ahi,  g_ahi);
    cudaGetSymbolAddress((void**)&alo,  g_alo);
    cudaGetSymbolAddress((void**)&bhi,  g_bhi);
    cudaGetSymbolAddress((void**)&blo,  g_blo);
    cudaGetSymbolAddress((void**)&whi,  g_whi);
    cudaGetSymbolAddress((void**)&hbhi, g_hbhi);
    cudaGetSymbolAddress((void**)&hblo, g_hblo);

    static cudaStream_t sSide = nullptr;
    static cudaEvent_t evFork = nullptr, evJoin = nullptr;
    if (!sSide) {
        cudaStreamCreateWithFlags(&sSide, cudaStreamNonBlocking);
        cudaEventCreateWithFlags(&evFork, cudaEventDisableTiming);
        cudaEventCreateWithFlags(&evJoin, cudaEventDisableTiming);
    }
    cudaStream_t s0 = 0;

    const dim3 blk(256);
    cudaFuncSetAttribute(gru_time_persist,
                         cudaFuncAttributeMaxDynamicSharedMemorySize, TIME_SMEM);
    cudaFuncSetAttribute(gemm_f16,
                         cudaFuncAttributeMaxDynamicSharedMemorySize, GEMM_SMEM);
    cudaFuncSetAttribute(gemm_p4,
                         cudaFuncAttributeMaxDynamicSharedMemorySize, GEMM_SMEM);

    __half *wtH = whi + 0*WSLOT;   // wt_ih
    __half *wfH = whi + 1*WSLOT;   // wf_ih
    __half *wbH = whi + 2*WSLOT;   // wb_ih
    __half *wsH = whi + 3*WSLOT;   // ws_ih
    __half *wTH = whi + 4*WSLOT;   // W_time
    __half *wFH = whi + 5*WSLOT;   // W_freq
    __half *wfhH = whi + 6*WSLOT;  // wf_hh
    __half *wbhH = whi + 7*WSLOT;  // wb_hh
    __half *wshH = whi + 8*WSLOT;  // ws_hh

    const size_t HB = (size_t)NSEQ_F * Dd;

    // ---- Phase 0: splits (weights hi-only; x_time hi/lo -> bhi/blo) ----
    split_launch_s(s0, wt_ih,  nullptr, wtH, nullptr, (size_t)G3 * Dd);
    split_launch_s(s0, wf_ih,  nullptr, wfH, nullptr, (size_t)G3 * Dd);
    split_launch_s(s0, wb_ih,  nullptr, wbH, nullptr, (size_t)G3 * Dd);
    split_launch_s(s0, ws_ih,  nullptr, wsH, nullptr, (size_t)G3 * Dd);
    split_launch_s(s0, W_time, nullptr, wTH, nullptr, (size_t)Dd * G3);
    split_launch_s(s0, W_freq, nullptr, wFH, nullptr, (size_t)Dd * Dd);
    split_launch_s(s0, wf_hh,  nullptr, wfhH, nullptr, (size_t)G3 * Dd);
    split_launch_s(s0, wb_hh,  nullptr, wbhH, nullptr, (size_t)G3 * Dd);
    split_launch_s(s0, ws_hh,  nullptr, wshH, nullptr, (size_t)G3 * Dd);
    split_launch_s(s0, x_time, nullptr, bhi, blo, (size_t)NT * Dd);

    // ---- Phase 1a: gi_t GEMM + time-scan memsets (main) ----
    {
        GArgs a{bhi, blo, wtH, bt_ih, nullptr, gi_t};
        gemm_f16<<<dim3(G3 / 128, NT / 128, 1), blk, GEMM_SMEM>>>(a, a, Dd, Dd, G3);
    }
    cudaMemsetAsync(ht0, 0, (size_t)NSEQ_T * Dd * sizeof(float));
    cudaMemsetAsync(ht1, 0, (size_t)NSEQ_T * Dd * sizeof(float));
    cudaMemsetAsync(tbar, 0, TGROUPS * sizeof(unsigned));

    // ---- FORK: time scan on side stream ----
    cudaEventRecord(evFork, s0);
    cudaStreamWaitEvent(sSide, evFork, 0);
    gru_time_persist<<<dim3(TGROUPS, TCOLB), dim3(512), TIME_SMEM, sSide>>>(
        gi_t, wt_hh, bt_hh, ahi, alo, ht0, ht1);
    cudaEventRecord(evJoin, sSide);

    // ---- Phase 1b: gi_f / gi_b GEMMs (main) ----
    {
        dim3 grid(G3 / 128, NT / 128, 1);
        GArgs b{bhi, blo, wfH, bf_ih, nullptr, gi_f};
        gemm_f16<<<grid, blk, GEMM_SMEM>>>(b, b, Dd, Dd, G3);
        GArgs c{bhi, blo, wbH, bb_ih, nullptr, gi_b};
        gemm_f16<<<grid, blk, GEMM_SMEM>>>(c, c, Dd, Dd, G3);
    }

    // ---- Phase 3: bidirectional freq GRU scan (main) ----
    cudaMemsetAsync(h0, 0, HB * sizeof(float));
    cudaMemsetAsync(h2, 0, HB * sizeof(float));
    cudaMemsetAsync(hbhi + 0 * HB, 0, HB * sizeof(__half));
    cudaMemsetAsync(hblo + 0 * HB, 0, HB * sizeof(__half));
    cudaMemsetAsync(hbhi + 2 * HB, 0, HB * sizeof(__half));
    cudaMemsetAsync(hblo + 2 * HB, 0, HB * sizeof(__half));
    for (int s = 0; s < Mm; s++) {
        const int pp = s & 1;
        GArgs gf{hbhi + (0 + pp) * HB, hblo + (0 + pp) * HB,
                 wfhH, bf_hh, nullptr, gh};
        GArgs gb{hbhi + (2 + pp) * HB, hblo + (2 + pp) * HB,
                 wbhH, bb_hh, nullptr, gh + (size_t)NSEQ_F * G3};
        gemm_f16<<<dim3(G3 / 128, NSEQ_F / 128, 2), blk, GEMM_SMEM>>>(
            gf, gb, Dd, Dd, G3);

        float* hpF = pp ? h1 : h0;  float* hnF = pp ? h0 : h1;
        float* hpB = pp ? h3 : h2;  float* hnB = pp ? h2 : h3;
        SArgs sf{gh, nullptr, gi_f, hpF, hnF,
                 hbhi + (0 + (pp ^ 1)) * HB, hblo + (0 + (pp ^ 1)) * HB,
                 ahi, alo, G3, Dd, s};
        SArgs sb{gh + (size_t)NSEQ_F * G3, nullptr, gi_b, hpB, hnB,
                 hbhi + (2 + (pp ^ 1)) * HB, hblo + (2 + (pp ^ 1)) * HB,
                 ahi, alo, G3, 2 * Dd, Mm - 1 - s};
        gate_step<<<dim3((int)(HB / 256), 1, 2), blk>>>(sf, sb);
    }

    // ---- JOIN ----
    cudaStreamWaitEvent(s0, evJoin, 0);

    // ---- Phase 4: fused xt GEMM + split(xt + x_freq) -> bhi/blo ----
    gemm_p4<<<dim3(Dd / 128, NT / 128), blk, GEMM_SMEM>>>(
        ahi, alo, wTH, b_time, x_time, x_freq, dout, bhi, blo);

    // ---- Phase 5: gi_s = (xt + x_freq) @ ws_ih^T + bs_ih ----
    {
        GArgs a{bhi, blo, wsH, bs_ih, nullptr, gi_s};
        gemm_f16<<<dim3(G3 / 128, NT / 128, 1), blk, GEMM_SMEM>>>(a, a, Dd, Dd, G3);
    }

    // ---- Phase 6: stack GRU scan (split-K=2) ----
    cudaMemsetAsync(h0, 0, HB * sizeof(float));
    cudaMemsetAsync(hbhi + 0 * HB, 0, HB * sizeof(__half));
    cudaMemsetAsync(hblo + 0 * HB, 0, HB * sizeof(__half));
    for (int s = 0; s < Mm; s++) {
        const int pp = s & 1;
        GArgs k0{hbhi + pp * HB, hblo + pp * HB,
                 wshH, bs_hh, nullptr, gh};
        GArgs k1{hbhi + pp * HB + 256, hblo + pp * HB + 256,
                 wshH + 256, nullptr, nullptr,
                 gh + (size_t)NSEQ_F * G3};
        gemm_f16<<<dim3(G3 / 128, NSEQ_F / 128, 2), blk, GEMM_SMEM>>>(
            k0, k1, 256, Dd, G3);

        float* hp = pp ? h1 : h0;  float* hn = pp ? h0 : h1;
        SArgs sa{gh, gh + (size_t)NSEQ_F * G3, gi_s, hp, hn,
                 hbhi + (pp ^ 1) * HB, hblo + (pp ^ 1) * HB,
                 bhi, blo, Dd, 0, s};
        gate_step<<<dim3((int)(HB / 256), 1, 1), blk>>>(sa, sa);
    }

    // ---- Phase 7: xf = xs @ W_freq^T + b_freq + x_freq ----
    {
        GArgs a{bhi, blo, wFH, b_freq, x_freq, dout + (size_t)NT * Dd};
        gemm_f16<<<dim3(Dd / 128, NT / 128, 1), blk, GEMM_SMEM>>>(a, a, Dd, Dd, Dd);
    }
}

// round 17
// speedup vs baseline: 1.9842x; 1.1477x over previous
#include <cuda_runtime.h>
#include <cuda_fp16.h>
#include <cstdint>

// ---------------------------------------------------------------------------
// Problem constants
// ---------------------------------------------------------------------------
constexpr int Bb = 2, Tt = 256, Mm = 80, Dd = 512;
constexpr int NT = Bb * Tt * Mm;   // 40960 tokens
constexpr int G3 = 3 * Dd;         // 1536
constexpr int NSEQ_T = Bb * Mm;    // 160
constexpr int NSEQ_F = Bb * Tt;    // 512

constexpr int TGROUPS = 5;             // 80-block grid (~balance point)
constexpr int TSQ = NSEQ_T / TGROUPS;  // 32 seqs per group
constexpr int TCHUNK = 16;             // partial-array chunk
constexpr int TCOLB = 16;

// ---------------------------------------------------------------------------
// Static device scratch
// ---------------------------------------------------------------------------
__device__ float g_gi_t[(size_t)NT * G3];
__device__ float g_gi_f[(size_t)NT * G3];
__device__ float g_gi_b[(size_t)NT * G3];
__device__ float g_gi_s[(size_t)NT * G3];
__device__ float g_h0[NSEQ_F * Dd];
__device__ float g_h1[NSEQ_F * Dd];
__device__ float g_h2[NSEQ_F * Dd];
__device__ float g_h3[NSEQ_F * Dd];
__device__ float g_ht0[NSEQ_T * Dd];
__device__ float g_ht1[NSEQ_T * Dd];
__device__ float g_gh[2 * (size_t)NSEQ_F * G3];
__device__ unsigned g_tbar[TGROUPS];

// fp16 split buffers (activations: hi + lo)
__device__ __half g_ahi[(size_t)NT * G3];   // xcat split ONLY (scan outputs)
__device__ __half g_alo[(size_t)NT * G3];
__device__ __half g_bhi[(size_t)NT * Dd];   // x_time split -> later (xt+x_freq)/xs
__device__ __half g_blo[(size_t)NT * Dd];
// fp16 hidden-state ping-pong: [dir(2)*pp(2)][NSEQ_F*Dd]
__device__ __half g_hbhi[4 * NSEQ_F * Dd];
__device__ __half g_hblo[4 * NSEQ_F * Dd];
// weights: fp16 hi only, 9 slots of 1536*512
constexpr size_t WSLOT = 786432;
__device__ __half g_whi[9 * WSLOT];

// ---------------------------------------------------------------------------
// PTX helpers
// ---------------------------------------------------------------------------
__device__ __forceinline__ uint32_t smem_to_u32(const void* p) {
    uint32_t a;
    asm("{ .reg .u64 t; cvta.to.shared.u64 t, %1; cvt.u32.u64 %0, t; }"
        : "=r"(a) : "l"(p));
    return a;
}
#define CP_ASYNC16(dst, src) \
    asm volatile("cp.async.cg.shared.global [%0], [%1], 16;" \
        :: "r"((uint32_t)(dst)), "l"(src) : "memory")
#define CP_COMMIT() asm volatile("cp.async.commit_group;" ::: "memory")
#define CP_WAIT(n)  asm volatile("cp.async.wait_group %0;" :: "n"(n) : "memory")

__device__ __forceinline__ void ldsm4(uint32_t* r, uint32_t addr) {
    asm volatile("ldmatrix.sync.aligned.m8n8.x4.shared.b16 {%0,%1,%2,%3}, [%4];"
        : "=r"(r[0]), "=r"(r[1]), "=r"(r[2]), "=r"(r[3]) : "r"(addr));
}
__device__ __forceinline__ void mma16816(float* c, const uint32_t* a, const uint32_t* b) {
    asm volatile(
        "mma.sync.aligned.m16n8k16.row.col.f32.f16.f16.f32 "
        "{%0,%1,%2,%3}, {%4,%5,%6,%7}, {%8,%9}, {%0,%1,%2,%3};"
        : "+f"(c[0]), "+f"(c[1]), "+f"(c[2]), "+f"(c[3])
        : "r"(a[0]), "r"(a[1]), "r"(a[2]), "r"(a[3]), "r"(b[0]), "r"(b[1]));
}
__device__ __forceinline__ unsigned ld_cg_u32(const unsigned* p) {
    unsigned v;
    asm volatile("ld.global.cg.u32 %0, [%1];" : "=r"(v) : "l"(p));
    return v;
}

// ---------------------------------------------------------------------------
// fp32 -> fp16 (hi, optional lo) split; optionally X+Y first
// ---------------------------------------------------------------------------
__global__ void split_fp16_kernel(
    const float* __restrict__ X, const float* __restrict__ Y,
    __half* __restrict__ hi, __half* __restrict__ lo, int n4)
{
    int i = blockIdx.x * blockDim.x + threadIdx.x;
    if (i >= n4) return;
    float4 v = reinterpret_cast<const float4*>(X)[i];
    if (Y) {
        float4 y = reinterpret_cast<const float4*>(Y)[i];
        v.x += y.x; v.y += y.y; v.z += y.z; v.w += y.w;
    }
    __half h0 = __float2half_rn(v.x);
    __half h1 = __float2half_rn(v.y);
    __half h2 = __float2half_rn(v.z);
    __half h3 = __float2half_rn(v.w);
    reinterpret_cast<__half2*>(hi)[2*i]   = __half2(h0, h1);
    reinterpret_cast<__half2*>(hi)[2*i+1] = __half2(h2, h3);
    if (lo) {
        __half l0 = __float2half_rn(v.x - __half2float(h0));
        __half l1 = __float2half_rn(v.y - __half2float(h1));
        __half l2 = __float2half_rn(v.z - __half2float(h2));
        __half l3 = __float2half_rn(v.w - __half2float(h3));
        reinterpret_cast<__half2*>(lo)[2*i]   = __half2(l0, l1);
        reinterpret_cast<__half2*>(lo)[2*i+1] = __half2(l2, l3);
    }
}

// ---------------------------------------------------------------------------
// mma.sync 128x128 tile core (2-product fp16 split: Ahi*B + Alo*B),
// BK=32, 3-stage cp.async, 3 smem tiles per stage.
// ---------------------------------------------------------------------------
constexpr int GSTRIDE = 40;
constexpr int TILE_B  = 128 * GSTRIDE * 2;     // 10240 B
constexpr int STAGE_B = 3 * TILE_B;            // 30720 B
constexpr int NSTAGE  = 3;
constexpr int GEMM_SMEM = NSTAGE * STAGE_B;    // 92160 B -> 2 blocks/SM

__device__ __forceinline__ void gemm128_core(
    const __half* __restrict__ Ahi, const __half* __restrict__ Alo,
    const __half* __restrict__ Bh,
    int ld, int K, char* smem, float acc[2][8][4])
{
    const uint32_t sb = smem_to_u32(smem);
    const int tid  = threadIdx.x;
    const int lane = tid & 31;
    const int wid  = tid >> 5;
    const int wm   = wid & 3;
    const int wn   = wid >> 2;

    const __half* srcs[3] = {Ahi, Alo, Bh};

    auto stage_load = [&](int c, int buf) {
        const int k0 = c * 32;
        const uint32_t base = sb + buf * STAGE_B;
#pragma unroll
        for (int t4 = 0; t4 < 3; t4++) {
#pragma unroll
            for (int i = 0; i < 2; i++) {
                int idx = tid + i * 256;
                int r = idx >> 2;
                int seg = idx & 3;
                uint32_t dst = base + t4 * TILE_B + r * (GSTRIDE * 2) + seg * 16;
                const void* gp = srcs[t4] + (size_t)r * ld + k0 + seg * 8;
                CP_ASYNC16(dst, gp);
            }
        }
        CP_COMMIT();
    };

#pragma unroll
    for (int mf = 0; mf < 2; mf++)
#pragma unroll
        for (int nf = 0; nf < 8; nf++)
#pragma unroll
            for (int q = 0; q < 4; q++) acc[mf][nf][q] = 0.f;

    const int NC = K / 32;
    stage_load(0, 0);
    stage_load(1, 1);

    const uint32_t a_off =
        ((wm * 32 + (lane & 15)) * GSTRIDE + ((lane >> 4) * 8)) * 2;
    const uint32_t b_row = wn * 64 + (lane & 7) + ((lane >> 4) & 1) * 8;
    const uint32_t b_off = (b_row * GSTRIDE + (((lane >> 3) & 1) * 8)) * 2;

    int nb = 2 % NSTAGE;
    for (int c = 0; c < NC; c++) {
        if (c + 2 < NC) {
            stage_load(c + 2, nb);
            nb = (nb + 1) % NSTAGE;
            CP_WAIT(2);
        } else if (c + 1 < NC) {
            CP_WAIT(1);
        } else {
            CP_WAIT(0);
        }
        __syncthreads();

        const uint32_t st = sb + (c % NSTAGE) * STAGE_B;

#pragma unroll
        for (int kk = 0; kk < 2; kk++) {
            const uint32_t kb = kk * 32;
            uint32_t ahi[2][4], alo[2][4];
#pragma unroll
            for (int mf = 0; mf < 2; mf++) {
                ldsm4(ahi[mf], st + 0 * TILE_B + a_off + mf * 16 * (GSTRIDE * 2) + kb);
                ldsm4(alo[mf], st + 1 * TILE_B + a_off + mf * 16 * (GSTRIDE * 2) + kb);
            }
            uint32_t bh[8][2];
#pragma unroll
            for (int p = 0; p < 4; p++) {
                uint32_t r4[4];
                ldsm4(r4, st + 2 * TILE_B + b_off + p * 16 * (GSTRIDE * 2) + kb);
                bh[2*p][0] = r4[0]; bh[2*p][1] = r4[1];
                bh[2*p+1][0] = r4[2]; bh[2*p+1][1] = r4[3];
            }
#pragma unroll
            for (int mf = 0; mf < 2; mf++)
#pragma unroll
                for (int nf = 0; nf < 8; nf++) {
                    mma16816(acc[mf][nf], ahi[mf], bh[nf]);
                    mma16816(acc[mf][nf], alo[mf], bh[nf]);
                }
        }
        __syncthreads();
    }
}

__device__ __forceinline__ void epi_store(
    float acc[2][8][4], float* __restrict__ C, const float* __restrict__ bias,
    const float* __restrict__ res, int row0, int col0, int N)
{
    const int lane = threadIdx.x & 31;
    const int wid  = threadIdx.x >> 5;
    const int wm   = wid & 3;
    const int wn   = wid >> 2;
#pragma unroll
    for (int mf = 0; mf < 2; mf++) {
        const int rA = row0 + wm * 32 + mf * 16 + (lane >> 2);
        const int rB = rA + 8;
#pragma unroll
        for (int nf = 0; nf < 8; nf++) {
            const int cc = col0 + wn * 64 + nf * 8 + (lane & 3) * 2;
            float b0 = bias ? bias[cc] : 0.f;
            float b1 = bias ? bias[cc + 1] : 0.f;
            float2 v0, v1;
            v0.x = acc[mf][nf][0] + b0;
            v0.y = acc[mf][nf][1] + b1;
            v1.x = acc[mf][nf][2] + b0;
            v1.y = acc[mf][nf][3] + b1;
            if (res) {
                float2 r0 = *reinterpret_cast<const float2*>(res + (size_t)rA * N + cc);
                float2 r1 = *reinterpret_cast<const float2*>(res + (size_t)rB * N + cc);
                v0.x += r0.x; v0.y += r0.y; v1.x += r1.x; v1.y += r1.y;
            }
            *reinterpret_cast<float2*>(C + (size_t)rA * N + cc) = v0;
            *reinterpret_cast<float2*>(C + (size_t)rB * N + cc) = v1;
        }
    }
}

// ---------------------------------------------------------------------------
// Standalone dual-arg GEMM (A split hi/lo, B fp16)
// ---------------------------------------------------------------------------
struct GArgs {
    const __half *Ahi, *Alo, *Bh;
    const float *bias, *res;
    float *C;
};

__global__ __launch_bounds__(256) void gemm_f16(GArgs g0, GArgs g1,
                                                 int K, int ld, int N)
{
    const GArgs g = blockIdx.z ? g1 : g0;
    extern __shared__ char smem[];
    const int row0 = blockIdx.y * 128;
    const int col0 = blockIdx.x * 128;
    float acc[2][8][4];
    gemm128_core(g.Ahi + (size_t)row0 * ld, g.Alo + (size_t)row0 * ld,
                 g.Bh + (size_t)col0 * ld, ld, K, smem, acc);
    epi_store(acc, g.C, g.bias, g.res, row0, col0, N);
}

// ---------------------------------------------------------------------------
// Phase-4 fused GEMM: xt -> dout, split(xt + x_freq) -> shi/slo
// ---------------------------------------------------------------------------
__global__ __launch_bounds__(256) void gemm_p4(
    const __half* __restrict__ Ahi, const __half* __restrict__ Alo,
    const __half* __restrict__ Bh,
    const float* __restrict__ bias, const float* __restrict__ xtime,
    const float* __restrict__ xfreq, float* __restrict__ C,
    __half* __restrict__ shi, __half* __restrict__ slo)
{
    extern __shared__ char smem[];
    const int row0 = blockIdx.y * 128;
    const int col0 = blockIdx.x * 128;
    float acc[2][8][4];
    gemm128_core(Ahi + (size_t)row0 * G3, Alo + (size_t)row0 * G3,
                 Bh + (size_t)col0 * G3, G3, G3, smem, acc);

    const int lane = threadIdx.x & 31;
    const int wid  = threadIdx.x >> 5;
    const int wm   = wid & 3;
    const int wn   = wid >> 2;
#pragma unroll
    for (int mf = 0; mf < 2; mf++) {
        const int rA = row0 + wm * 32 + mf * 16 + (lane >> 2);
#pragma unroll
        for (int half = 0; half < 2; half++) {
            const int r = rA + half * 8;
#pragma unroll
            for (int nf = 0; nf < 8; nf++) {
                const int cc = col0 + wn * 64 + nf * 8 + (lane & 3) * 2;
                const size_t o = (size_t)r * Dd + cc;
                float2 v;
                v.x = acc[mf][nf][half * 2 + 0] + bias[cc];
                v.y = acc[mf][nf][half * 2 + 1] + bias[cc + 1];
                float2 rt = *reinterpret_cast<const float2*>(xtime + o);
                v.x += rt.x; v.y += rt.y;
                *reinterpret_cast<float2*>(C + o) = v;
                float2 rf = *reinterpret_cast<const float2*>(xfreq + o);
                float t0 = v.x + rf.x;
                float t1 = v.y + rf.y;
                __half h0 = __float2half_rn(t0);
                __half h1 = __float2half_rn(t1);
                *reinterpret_cast<__half2*>(shi + o) = __half2(h0, h1);
                *reinterpret_cast<__half2*>(slo + o) = __half2(
                    __float2half_rn(t0 - __half2float(h0)),
                    __float2half_rn(t1 - __half2float(h1)));
            }
        }
    }
}

// ---------------------------------------------------------------------------
// Activation helpers
// ---------------------------------------------------------------------------
__device__ __forceinline__ float sigf(float x) {
    return 1.f / (1.f + __expf(-x));
}
__device__ __forceinline__ float tanhfast(float x) {
    float e2x = __expf(2.f * x);
    return 1.f - 2.f / (e2x + 1.f);
}

// ---------------------------------------------------------------------------
// Gate kernel for tensor-core recurrent steps.
// ---------------------------------------------------------------------------
struct SArgs {
    const float *gh, *gh2;
    const float* gi;
    const float* hprev;
    float* hnext;
    __half *hhi, *hlo;
    __half *ohi, *olo;
    int outStride, outOff, mtok;
};

__global__ __launch_bounds__(256) void gate_step(SArgs a0, SArgs a1)
{
    const SArgs a = blockIdx.z ? a1 : a0;
    const int idx = blockIdx.x * 256 + threadIdx.x;
    const int s = idx >> 9;
    const int j = idx & 511;

    const float* g0 = a.gh + (size_t)s * G3;
    float ghr = g0[j], ghz = g0[Dd + j], ghn = g0[2*Dd + j];
    if (a.gh2) {
        const float* g1 = a.gh2 + (size_t)s * G3;
        ghr += g1[j]; ghz += g1[Dd + j]; ghn += g1[2*Dd + j];
    }
    const int token = s * Mm + a.mtok;
    const float* gir = a.gi + (size_t)token * G3;

    float r = sigf(gir[j]        + ghr);
    float z = sigf(gir[Dd + j]   + ghz);
    float n = tanhfast(gir[2*Dd + j] + r * ghn);
    float hp = a.hprev[idx];
    float hv = (1.f - z) * n + z * hp;

    a.hnext[idx] = hv;
    __half hi = __float2half_rn(hv);
    __half lo = __float2half_rn(hv - __half2float(hi));
    a.hhi[idx] = hi;
    a.hlo[idx] = lo;
    size_t o = (size_t)token * a.outStride + a.outOff + j;
    a.ohi[o] = hi;
    a.olo[o] = lo;
}

// ---------------------------------------------------------------------------
// Persistent time-GRU scan (fp32 SIMT), 512 threads, grid (5, 16) = 80 blocks.
// ---------------------------------------------------------------------------
constexpr int TPART = 17;
constexpr int TIME_SMEM = (TSQ * 512 + TCHUNK * 3 * 32 * TPART) * 4; // 169984 B

__global__ __launch_bounds__(512, 1) void gru_time_persist(
    const float* __restrict__ gi, const float* __restrict__ Whh,
    const float* __restrict__ bhh,
    __half* __restrict__ ohi, __half* __restrict__ olo,
    float* __restrict__ hb0, float* __restrict__ hb1)
{
    const int grp  = blockIdx.x;   // 0..4
    const int cb   = blockIdx.y;   // 0..15
    const int j0   = cb * 32;
    const int tid  = threadIdx.x;
    const int lane = tid & 31;
    const int w    = tid >> 5;
    const int k0   = w * 32;

    extern __shared__ float sm[];
    float* hs   = sm;                       // [TSQ][512]
    float* part = sm + TSQ * 512;           // [TCHUNK*3*32][TPART]

    float wr[32], wz[32], wn[32];
    {
        const float* Wr = Whh + (size_t)(0 * Dd + j0 + lane) * Dd + k0;
        const float* Wz = Whh + (size_t)(1 * Dd + j0 + lane) * Dd + k0;
        const float* Wn = Whh + (size_t)(2 * Dd + j0 + lane) * Dd + k0;
#pragma unroll
        for (int i = 0; i < 32; i += 4) {
            float4 a = *reinterpret_cast<const float4*>(Wr + i);
            float4 b = *reinterpret_cast<const float4*>(Wz + i);
            float4 c = *reinterpret_cast<const float4*>(Wn + i);
            wr[i] = a.x; wr[i+1] = a.y; wr[i+2] = a.z; wr[i+3] = a.w;
            wz[i] = b.x; wz[i+1] = b.y; wz[i+2] = b.z; wz[i+3] = b.w;
            wn[i] = c.x; wn[i+1] = c.y; wn[i+2] = c.z; wn[i+3] = c.w;
        }
    }

    for (int t = 0; t < Tt; t++) {
        const float* hc = (t & 1) ? hb1 : hb0;
        float*       hn = (t & 1) ? hb0 : hb1;

        for (int i = tid; i < TSQ * 128; i += 512) {
            int s  = i >> 7;
            int k4 = i & 127;
            float4 v = __ldcg(reinterpret_cast<const float4*>(
                hc + (size_t)(grp * TSQ + s) * Dd) + k4);
            *reinterpret_cast<float4*>(hs + s * Dd + k4 * 4) = v;
        }
        __syncthreads();

        for (int c0 = 0; c0 < TSQ; c0 += TCHUNK) {
            for (int ls = 0; ls < TCHUNK; ls++) {
                const int s = c0 + ls;
                float ar = 0.f, az = 0.f, an = 0.f;
                const float* hrow = hs + s * Dd + k0;
#pragma unroll
                for (int i = 0; i < 32; i += 4) {
                    float4 h4 = *reinterpret_cast<const float4*>(hrow + i);
                    ar = fmaf(h4.x, wr[i],   ar); az = fmaf(h4.x, wz[i],   az); an = fmaf(h4.x, wn[i],   an);
                    ar = fmaf(h4.y, wr[i+1], ar); az = fmaf(h4.y, wz[i+1], az); an = fmaf(h4.y, wn[i+1], an);
                    ar = fmaf(h4.z, wr[i+2], ar); az = fmaf(h4.z, wz[i+2], az); an = fmaf(h4.z, wn[i+2], an);
                    ar = fmaf(h4.w, wr[i+3], ar); az = fmaf(h4.w, wz[i+3], az); an = fmaf(h4.w, wn[i+3], an);
                }
                part[((ls * 3 + 0) * 32 + lane) * TPART + w] = ar;
                part[((ls * 3 + 1) * 32 + lane) * TPART + w] = az;
                part[((ls * 3 + 2) * 32 + lane) * TPART + w] = an;
            }
            __syncthreads();

            for (int idx = tid; idx < TCHUNK * 32; idx += 512) {
                int ls = idx >> 5, j = idx & 31;
                int s = c0 + ls;
                float r = 0.f, z = 0.f, n = 0.f;
                const float* pr = part + ((ls * 3 + 0) * 32 + j) * TPART;
                const float* pz = part + ((ls * 3 + 1) * 32 + j) * TPART;
                const float* pn = part + ((ls * 3 + 2) * 32 + j) * TPART;
#pragma unroll
                for (int ww = 0; ww < 16; ww++) { r += pr[ww]; z += pz[ww]; n += pn[ww]; }

                int sg = grp * TSQ + s;
                int b  = sg / Mm;
                int m  = sg - b * Mm;
                size_t token = ((size_t)(b * Tt + t)) * Mm + m;
                const float* gir = gi + token * G3;
                int jc = j0 + j;
                float rr = sigf(gir[jc]        + r + bhh[jc]);
                float zz = sigf(gir[Dd + jc]   + z + bhh[Dd + jc]);
                float nn = tanhfast(gir[2*Dd + jc] + rr * (n + bhh[2*Dd + jc]));
                float hp = hs[s * Dd + jc];
                float hv = (1.f - zz) * nn + zz * hp;
                __stcg(hn + (size_t)sg * Dd + jc, hv);
                __half hib = __float2half_rn(hv);
                ohi[token * G3 + jc] = hib;
                olo[token * G3 + jc] = __float2half_rn(hv - __half2float(hib));
            }
            __syncthreads();
        }

        __threadfence();
        __syncthreads();
        if (tid == 0) {
            atomicAdd(&g_tbar[grp], 1u);
            unsigned target = (unsigned)(t + 1) * TCOLB;
            while (ld_cg_u32(&g_tbar[grp]) < target) __nanosleep(64);
        }
        __syncthreads();
    }
}

// ---------------------------------------------------------------------------
// Launch
// ---------------------------------------------------------------------------
static void split_launch_s(cudaStream_t st, const float* X, const float* Y,
                           __half* hi, __half* lo, size_t n)
{
    int n4 = (int)(n / 4);
    split_fp16_kernel<<<(n4 + 255) / 256, 256, 0, st>>>(X, Y, hi, lo, n4);
}

extern "C" void kernel_launch(void* const* d_in, const int* in_sizes, int n_in,
                              void* d_out_v, int out_size)
{
    const float* x_time = (const float*)d_in[0];
    const float* x_freq = (const float*)d_in[1];
    const float* wt_ih  = (const float*)d_in[2];
    const float* wt_hh  = (const float*)d_in[3];
    const float* bt_ih  = (const float*)d_in[4];
    const float* bt_hh  = (const float*)d_in[5];
    const float* wf_ih  = (const float*)d_in[6];
    const float* wf_hh  = (const float*)d_in[7];
    const float* bf_ih  = (const float*)d_in[8];
    const float* bf_hh  = (const float*)d_in[9];
    const float* wb_ih  = (const float*)d_in[10];
    const float* wb_hh  = (const float*)d_in[11];
    const float* bb_ih  = (const float*)d_in[12];
    const float* bb_hh  = (const float*)d_in[13];
    const float* ws_ih  = (const float*)d_in[14];
    const float* ws_hh  = (const float*)d_in[15];
    const float* bs_ih  = (const float*)d_in[16];
    const float* bs_hh  = (const float*)d_in[17];
    const float* W_time = (const float*)d_in[18];
    const float* b_time = (const float*)d_in[19];
    const float* W_freq = (const float*)d_in[20];
    const float* b_freq = (const float*)d_in[21];
    float* dout = (float*)d_out_v;

    float *gi_t, *gi_f, *gi_b, *gi_s, *h0, *h1, *h2, *h3, *ht0, *ht1, *gh;
    unsigned* tbar;
    __half *ahi, *alo, *bhi, *blo, *whi, *hbhi, *hblo;
    cudaGetSymbolAddress((void**)&gi_t, g_gi_t);
    cudaGetSymbolAddress((void**)&gi_f, g_gi_f);
    cudaGetSymbolAddress((void**)&gi_b, g_gi_b);
    cudaGetSymbolAddress((void**)&gi_s, g_gi_s);
    cudaGetSymbolAddress((void**)&h0,   g_h0);
    cudaGetSymbolAddress((void**)&h1,   g_h1);
    cudaGetSymbolAddress((void**)&h2,   g_h2);
    cudaGetSymbolAddress((void**)&h3,   g_h3);
    cudaGetSymbolAddress((void**)&ht0,  g_ht0);
    cudaGetSymbolAddress((void**)&ht1,  g_ht1);
    cudaGetSymbolAddress((void**)&gh,   g_gh);
    cudaGetSymbolAddress((void**)&tbar, g_tbar);
    cudaGetSymbolAddress((void**)&ahi,  g_ahi);
    cudaGetSymbolAddress((void**)&alo,  g_alo);
    cudaGetSymbolAddress((void**)&bhi,  g_bhi);
    cudaGetSymbolAddress((void**)&blo,  g_blo);
    cudaGetSymbolAddress((void**)&whi,  g_whi);
    cudaGetSymbolAddress((void**)&hbhi, g_hbhi);
    cudaGetSymbolAddress((void**)&hblo, g_hblo);

    static cudaStream_t sSide = nullptr;
    static cudaEvent_t evFork = nullptr, evJoin = nullptr;
    if (!sSide) {
        cudaStreamCreateWithFlags(&sSide, cudaStreamNonBlocking);
        cudaEventCreateWithFlags(&evFork, cudaEventDisableTiming);
        cudaEventCreateWithFlags(&evJoin, cudaEventDisableTiming);
    }
    cudaStream_t s0 = 0;

    const dim3 blk(256);
    cudaFuncSetAttribute(gru_time_persist,
                         cudaFuncAttributeMaxDynamicSharedMemorySize, TIME_SMEM);
    cudaFuncSetAttribute(gemm_f16,
                         cudaFuncAttributeMaxDynamicSharedMemorySize, GEMM_SMEM);
    cudaFuncSetAttribute(gemm_p4,
                         cudaFuncAttributeMaxDynamicSharedMemorySize, GEMM_SMEM);

    __half *wtH = whi + 0*WSLOT;   // wt_ih
    __half *wfH = whi + 1*WSLOT;   // wf_ih
    __half *wbH = whi + 2*WSLOT;   // wb_ih
    __half *wsH = whi + 3*WSLOT;   // ws_ih
    __half *wTH = whi + 4*WSLOT;   // W_time
    __half *wFH = whi + 5*WSLOT;   // W_freq
    __half *wfhH = whi + 6*WSLOT;  // wf_hh
    __half *wbhH = whi + 7*WSLOT;  // wb_hh
    __half *wshH = whi + 8*WSLOT;  // ws_hh

    const size_t HB = (size_t)NSEQ_F * Dd;

    // ---- Phase 0: splits (weights hi-only; x_time hi/lo -> bhi/blo) ----
    split_launch_s(s0, wt_ih,  nullptr, wtH, nullptr, (size_t)G3 * Dd);
    split_launch_s(s0, wf_ih,  nullptr, wfH, nullptr, (size_t)G3 * Dd);
    split_launch_s(s0, wb_ih,  nullptr, wbH, nullptr, (size_t)G3 * Dd);
    split_launch_s(s0, ws_ih,  nullptr, wsH, nullptr, (size_t)G3 * Dd);
    split_launch_s(s0, W_time, nullptr, wTH, nullptr, (size_t)Dd * G3);
    split_launch_s(s0, W_freq, nullptr, wFH, nullptr, (size_t)Dd * Dd);
    split_launch_s(s0, wf_hh,  nullptr, wfhH, nullptr, (size_t)G3 * Dd);
    split_launch_s(s0, wb_hh,  nullptr, wbhH, nullptr, (size_t)G3 * Dd);
    split_launch_s(s0, ws_hh,  nullptr, wshH, nullptr, (size_t)G3 * Dd);
    split_launch_s(s0, x_time, nullptr, bhi, blo, (size_t)NT * Dd);

    // ---- Phase 1a: gi_t GEMM + time-scan memsets (main) ----
    {
        GArgs a{bhi, blo, wtH, bt_ih, nullptr, gi_t};
        gemm_f16<<<dim3(G3 / 128, NT / 128, 1), blk, GEMM_SMEM>>>(a, a, Dd, Dd, G3);
    }
    cudaMemsetAsync(ht0, 0, (size_t)NSEQ_T * Dd * sizeof(float));
    cudaMemsetAsync(ht1, 0, (size_t)NSEQ_T * Dd * sizeof(float));
    cudaMemsetAsync(tbar, 0, TGROUPS * sizeof(unsigned));

    // ---- FORK: time scan on side stream (80 blocks) ----
    cudaEventRecord(evFork, s0);
    cudaStreamWaitEvent(sSide, evFork, 0);
    gru_time_persist<<<dim3(TGROUPS, TCOLB), dim3(512), TIME_SMEM, sSide>>>(
        gi_t, wt_hh, bt_hh, ahi, alo, ht0, ht1);
    cudaEventRecord(evJoin, sSide);

    // ---- Phase 1b: gi_f / gi_b GEMMs (main) ----
    {
        dim3 grid(G3 / 128, NT / 128, 1);
        GArgs b{bhi, blo, wfH, bf_ih, nullptr, gi_f};
        gemm_f16<<<grid, blk, GEMM_SMEM>>>(b, b, Dd, Dd, G3);
        GArgs c{bhi, blo, wbH, bb_ih, nullptr, gi_b};
        gemm_f16<<<grid, blk, GEMM_SMEM>>>(c, c, Dd, Dd, G3);
    }

    // ---- Phase 3: bidirectional freq GRU scan (main) ----
    cudaMemsetAsync(h0, 0, HB * sizeof(float));
    cudaMemsetAsync(h2, 0, HB * sizeof(float));
    cudaMemsetAsync(hbhi + 0 * HB, 0, HB * sizeof(__half));
    cudaMemsetAsync(hblo + 0 * HB, 0, HB * sizeof(__half));
    cudaMemsetAsync(hbhi + 2 * HB, 0, HB * sizeof(__half));
    cudaMemsetAsync(hblo + 2 * HB, 0, HB * sizeof(__half));
    for (int s = 0; s < Mm; s++) {
        const int pp = s & 1;
        GArgs gf{hbhi + (0 + pp) * HB, hblo + (0 + pp) * HB,
                 wfhH, bf_hh, nullptr, gh};
        GArgs gb{hbhi + (2 + pp) * HB, hblo + (2 + pp) * HB,
                 wbhH, bb_hh, nullptr, gh + (size_t)NSEQ_F * G3};
        gemm_f16<<<dim3(G3 / 128, NSEQ_F / 128, 2), blk, GEMM_SMEM>>>(
            gf, gb, Dd, Dd, G3);

        float* hpF = pp ? h1 : h0;  float* hnF = pp ? h0 : h1;
        float* hpB = pp ? h3 : h2;  float* hnB = pp ? h2 : h3;
        SArgs sf{gh, nullptr, gi_f, hpF, hnF,
                 hbhi + (0 + (pp ^ 1)) * HB, hblo + (0 + (pp ^ 1)) * HB,
                 ahi, alo, G3, Dd, s};
        SArgs sb{gh + (size_t)NSEQ_F * G3, nullptr, gi_b, hpB, hnB,
                 hbhi + (2 + (pp ^ 1)) * HB, hblo + (2 + (pp ^ 1)) * HB,
                 ahi, alo, G3, 2 * Dd, Mm - 1 - s};
        gate_step<<<dim3((int)(HB / 256), 1, 2), blk>>>(sf, sb);
    }

    // ---- JOIN ----
    cudaStreamWaitEvent(s0, evJoin, 0);

    // ---- Phase 4: fused xt GEMM + split(xt + x_freq) -> bhi/blo ----
    gemm_p4<<<dim3(Dd / 128, NT / 128), blk, GEMM_SMEM>>>(
        ahi, alo, wTH, b_time, x_time, x_freq, dout, bhi, blo);

    // ---- Phase 5: gi_s = (xt + x_freq) @ ws_ih^T + bs_ih ----
    {
        GArgs a{bhi, blo, wsH, bs_ih, nullptr, gi_s};
        gemm_f16<<<dim3(G3 / 128, NT / 128, 1), blk, GEMM_SMEM>>>(a, a, Dd, Dd, G3);
    }

    // ---- Phase 6: stack GRU scan (split-K=2) ----
    cudaMemsetAsync(h0, 0, HB * sizeof(float));
    cudaMemsetAsync(hbhi + 0 * HB, 0, HB * sizeof(__half));
    cudaMemsetAsync(hblo + 0 * HB, 0, HB * sizeof(__half));
    for (int s = 0; s < Mm; s++) {
        const int pp = s & 1;
        GArgs k0{hbhi + pp * HB, hblo + pp * HB,
                 wshH, bs_hh, nullptr, gh};
        GArgs k1{hbhi + pp * HB + 256, hblo + pp * HB + 256,
                 wshH + 256, nullptr, nullptr,
                 gh + (size_t)NSEQ_F * G3};
        gemm_f16<<<dim3(G3 / 128, NSEQ_F / 128, 2), blk, GEMM_SMEM>>>(
            k0, k1, 256, Dd, G3);

        float* hp = pp ? h1 : h0;  float* hn = pp ? h0 : h1;
        SArgs sa{gh, gh + (size_t)NSEQ_F * G3, gi_s, hp, hn,
                 hbhi + (pp ^ 1) * HB, hblo + (pp ^ 1) * HB,
                 bhi, blo, Dd, 0, s};
        gate_step<<<dim3((int)(HB / 256), 1, 1), blk>>>(sa, sa);
    }

    // ---- Phase 7: xf = xs @ W_freq^T + b_freq + x_freq ----
    {
        GArgs a{bhi, blo, wFH, b_freq, x_freq, dout + (size_t)NT * Dd};
        gemm_f16<<<dim3(Dd / 128, NT / 128, 1), blk, GEMM_SMEM>>>(a, a, Dd, Dd, Dd);
    }
}